// round 1
// baseline (speedup 1.0000x reference)
#include <cuda_runtime.h>
#include <math.h>
#include <stdint.h>
#include <stddef.h>

// ---------------- problem dims ----------------
#define B_   256
#define T_   96
#define D_   768
#define H_   384
#define G_   1536          // 4*H
#define BT_  (B_*T_)       // 24576
#define NE_  128
#define NC_  256
#define NK_  64
#define CK_  4
#define POS_ 50
#define K2_  2355          // 3D+1+POS
#define K3_  2356          // 3D+2+POS

// ---------------- scratch (static device globals; no allocation) ----------------
__device__ float g_xrev[BT_*D_];            // reversed input
__device__ float g_xbf[BT_*G_];             // x@Wih_f^T + bias
__device__ float g_xbb[BT_*G_];
__device__ float g_hsf[BT_*H_];             // forward hidden states
__device__ float g_hsrev[BT_*H_];           // backward (in reversed time)
__device__ float g_hbuf[2][2][B_*H_];       // [dir][parity]
__device__ float g_cbuf[2][B_*H_];
__device__ float g_Hs[BT_*D_];
__device__ float g_t1[BT_*D_];
__device__ float g_e[BT_];
__device__ float g_U[B_*D_];
__device__ float g_R[NC_*D_];               // lrelu(U@rep_W+rep_b)
__device__ float g_cE[NE_*NK_*D_];          // chunkEmb
__device__ float g_d2[NE_*NK_*K2_];
__device__ float g_z2[NE_*NK_*D_];
__device__ float g_of[NE_*NK_];             // out_feat
__device__ float g_d3[(size_t)NE_*NC_*K3_];
__device__ float g_z3[NE_*NC_*D_];
__device__ float g_bf[G_];
__device__ float g_bb[G_];
__device__ int   g_rev[BT_];

__device__ __forceinline__ float lrelu(float x){ return x >= 0.f ? x : 0.01f*x; }
__device__ __forceinline__ float sigm(float x){ return 1.f/(1.f+expf(-x)); }

// ---------------- small prep kernels ----------------
__global__ void k_prep(const int* __restrict__ slen){
    int b = blockIdx.x, t = threadIdx.x;     // block = 96 threads
    int len = slen[b];
    g_rev[b*T_ + t] = (t < len) ? (len - 1 - t) : t;
}

__global__ void k_gather(const float4* __restrict__ word){
    int i = blockIdx.x*256 + threadIdx.x;    // over BT_*192 float4s
    if (i >= BT_*192) return;
    int bt = i / 192, q = i - bt*192;
    int b  = bt / T_;
    int rid = g_rev[bt];
    ((float4*)g_xrev)[i] = word[(b*T_ + rid)*192 + q];
}

__global__ void k_bias(const float* bihf, const float* bhhf,
                       const float* bihb, const float* bhhb){
    int i = blockIdx.x*256 + threadIdx.x;
    if (i < G_){ g_bf[i] = bihf[i] + bhhf[i]; g_bb[i] = bihb[i] + bhhb[i]; }
}

__global__ void k_zero(){
    int i = blockIdx.x*256 + threadIdx.x;
    if (i < 2*2*B_*H_) (&g_hbuf[0][0][0])[i] = 0.f;
    if (i < 2*B_*H_)   (&g_cbuf[0][0])[i]    = 0.f;
}

// ---------------- SGEMM: C[M,N] = A[M,K] * B (+bias, opt lrelu) ----------------
// TB=false: B is [K,N] row-major (NN).  TB=true: B is [N,K] row-major (NT).
template<bool TB, bool RELU>
__global__ void sgemm(const float* __restrict__ A, const float* __restrict__ Bm,
                      const float* __restrict__ bias, float* __restrict__ Cm,
                      int M, int N, int K){
    __shared__ float As[16][65];
    __shared__ float Bs[16][65];
    int bm = blockIdx.y << 6, bn = blockIdx.x << 6;
    int tid = threadIdx.x;
    int tx = tid & 15, ty = tid >> 4;
    float acc[4][4];
    #pragma unroll
    for (int i = 0; i < 4; i++)
        #pragma unroll
        for (int j = 0; j < 4; j++) acc[i][j] = 0.f;

    int arow = tid >> 2, ak0 = (tid & 3) << 2;
    for (int k0 = 0; k0 < K; k0 += 16){
        #pragma unroll
        for (int q = 0; q < 4; q++){
            int kk = ak0 + q, gm = bm + arow, gk = k0 + kk;
            As[kk][arow] = (gm < M && gk < K) ? A[(size_t)gm*K + gk] : 0.f;
        }
        if (!TB){
            int kr = tid >> 4, nc0 = (tid & 15) << 2;
            #pragma unroll
            for (int q = 0; q < 4; q++){
                int n = nc0 + q, gk = k0 + kr, gn = bn + n;
                Bs[kr][n] = (gk < K && gn < N) ? Bm[(size_t)gk*N + gn] : 0.f;
            }
        } else {
            int nr = tid >> 2, bk0 = (tid & 3) << 2;
            #pragma unroll
            for (int q = 0; q < 4; q++){
                int kk = bk0 + q, gn = bn + nr, gk = k0 + kk;
                Bs[kk][nr] = (gn < N && gk < K) ? Bm[(size_t)gn*K + gk] : 0.f;
            }
        }
        __syncthreads();
        #pragma unroll
        for (int kk = 0; kk < 16; kk++){
            float a[4], b[4];
            #pragma unroll
            for (int i = 0; i < 4; i++) a[i] = As[kk][ty + (i<<4)];
            #pragma unroll
            for (int j = 0; j < 4; j++) b[j] = Bs[kk][tx + (j<<4)];
            #pragma unroll
            for (int i = 0; i < 4; i++)
                #pragma unroll
                for (int j = 0; j < 4; j++) acc[i][j] += a[i]*b[j];
        }
        __syncthreads();
    }
    #pragma unroll
    for (int i = 0; i < 4; i++){
        int gm = bm + ty + (i<<4); if (gm >= M) continue;
        #pragma unroll
        for (int j = 0; j < 4; j++){
            int gn = bn + tx + (j<<4); if (gn >= N) continue;
            float v = acc[i][j] + bias[gn];
            if (RELU) v = lrelu(v);
            Cm[(size_t)gm*N + gn] = v;
        }
    }
}

// ---------------- fused LSTM step (both directions) ----------------
// block: 128 thr, tile 32(b) x 32(j); thread: 4b x 2j x 4 gates
__global__ void k_lstm(const float* __restrict__ WhhF,
                       const float* __restrict__ WhhB, int t){
    int dir = blockIdx.z;
    const float* Whh = dir ? WhhB : WhhF;
    const float* xb  = dir ? g_xbb : g_xbf;
    const float* hp  = g_hbuf[dir][t & 1];
    float* hn        = g_hbuf[dir][(t & 1) ^ 1];
    float* cc        = g_cbuf[dir];
    float* hs        = dir ? g_hsrev : g_hsf;

    int bBase = blockIdx.x << 5, jBase = blockIdx.y << 5;
    int tid = threadIdx.x, tx = tid & 15, ty = tid >> 4;

    __shared__ float shh[32][17];
    __shared__ float shw[4][16][33];

    float acc[4][4][2];   // [bb][gate][jj]
    #pragma unroll
    for (int a = 0; a < 4; a++)
        #pragma unroll
        for (int g = 0; g < 4; g++){ acc[a][g][0]=0.f; acc[a][g][1]=0.f; }

    for (int kc = 0; kc < H_; kc += 16){
        #pragma unroll
        for (int q = 0; q < 4; q++){
            int e = tid + 128*q;
            int bl = e >> 4, kk = e & 15;
            shh[bl][kk] = hp[(bBase + bl)*H_ + kc + kk];
        }
        #pragma unroll
        for (int q = 0; q < 16; q++){
            int e = tid + 128*q;
            int g = e >> 9, rem = e & 511;
            int jl = rem >> 4, kk = rem & 15;
            shw[g][kk][jl] = Whh[(size_t)(g*H_ + jBase + jl)*H_ + kc + kk];
        }
        __syncthreads();
        #pragma unroll
        for (int kk = 0; kk < 16; kk++){
            float hv[4];
            #pragma unroll
            for (int bb = 0; bb < 4; bb++) hv[bb] = shh[(ty<<2)+bb][kk];
            #pragma unroll
            for (int g = 0; g < 4; g++){
                float w0 = shw[g][kk][(tx<<1)];
                float w1 = shw[g][kk][(tx<<1)+1];
                #pragma unroll
                for (int bb = 0; bb < 4; bb++){
                    acc[bb][g][0] += hv[bb]*w0;
                    acc[bb][g][1] += hv[bb]*w1;
                }
            }
        }
        __syncthreads();
    }
    #pragma unroll
    for (int bb = 0; bb < 4; bb++){
        int b = bBase + (ty<<2) + bb;
        const float* xrow = xb + (size_t)(b*T_ + t)*G_;
        #pragma unroll
        for (int jj = 0; jj < 2; jj++){
            int j = jBase + (tx<<1) + jj;
            float gi = acc[bb][0][jj] + xrow[j];
            float gf = acc[bb][1][jj] + xrow[H_ + j];
            float gg = acc[bb][2][jj] + xrow[2*H_ + j];
            float go = acc[bb][3][jj] + xrow[3*H_ + j];
            float cold = cc[b*H_ + j];
            float cn = sigm(gf)*cold + sigm(gi)*tanhf(gg);
            float hv = sigm(go)*tanhf(cn);
            cc[b*H_ + j] = cn;
            hn[b*H_ + j] = hv;
            hs[(size_t)(b*T_ + t)*H_ + j] = hv;
        }
    }
}

// ---------------- Hs assembly (concat forward + re-gathered backward) ----------
__global__ void k_hs(){
    int i = blockIdx.x*256 + threadIdx.x;
    if (i >= BT_*D_) return;
    int bt = i / D_, d = i - bt*D_;
    if (d < H_) g_Hs[i] = g_hsf[bt*H_ + d];
    else {
        int b = bt / T_;
        int rid = g_rev[bt];
        g_Hs[i] = g_hsrev[(b*T_ + rid)*H_ + d - H_];
    }
}

// ---------------- e = t1 @ s2_W (GEMV; warp per row) ----------------
__global__ void k_e(const float* __restrict__ s2){
    int warp = threadIdx.x >> 5, lane = threadIdx.x & 31;
    int row = blockIdx.x*8 + warp; if (row >= BT_) return;
    const float* h = g_t1 + (size_t)row*D_;
    float a = 0.f;
    for (int k = lane; k < D_; k += 32) a += h[k]*s2[k];
    #pragma unroll
    for (int s = 16; s; s >>= 1) a += __shfl_down_sync(0xffffffffu, a, s);
    if (!lane) g_e[row] = a;
}

// ---------------- masked normalization + pooled U ----------------
__global__ void k_u(const int* __restrict__ slen){
    __shared__ float al[T_];
    __shared__ float red[256];
    int b = blockIdx.x, tid = threadIdx.x;
    int len = slen[b];
    float v = 0.f;
    if (tid < T_){ v = (tid < len) ? g_e[b*T_ + tid] : 0.f; al[tid] = v; }
    red[tid] = v; __syncthreads();
    for (int s = 128; s; s >>= 1){ if (tid < s) red[tid] += red[tid+s]; __syncthreads(); }
    float denom = red[0] + 1e-9f;
    __syncthreads();
    if (tid < T_) al[tid] = al[tid] / denom;
    __syncthreads();
    for (int d = tid; d < D_; d += 256){
        float acc = 0.f;
        for (int t = 0; t < T_; t++) acc += al[t]*g_Hs[(size_t)(b*T_ + t)*D_ + d];
        g_U[b*D_ + d] = acc;
    }
}

// ---------------- per-chunk cross attention ----------------
__global__ void k_chunk(const int* __restrict__ emo, const int* __restrict__ cau){
    __shared__ float Esh[D_];
    __shared__ float red[256];
    __shared__ float scs[4];
    int blk = blockIdx.x, tid = threadIdx.x;
    int e = blk >> 6, k = blk & 63;
    const float* Er = g_R + (size_t)emo[e]*D_;
    for (int d = tid; d < D_; d += 256) Esh[d] = Er[d];
    __syncthreads();
    float dots[4];
    for (int c = 0; c < 4; c++){
        const float* Cr = g_R + (size_t)cau[k*4 + c]*D_;
        float a = 0.f;
        for (int d = tid; d < D_; d += 256) a += Esh[d]*Cr[d];
        red[tid] = a; __syncthreads();
        for (int s = 128; s; s >>= 1){ if (tid < s) red[tid] += red[tid+s]; __syncthreads(); }
        dots[c] = red[0]; __syncthreads();
    }
    if (tid == 0){
        float m = fmaxf(fmaxf(dots[0],dots[1]), fmaxf(dots[2],dots[3]));
        float ex[4], s = 0.f;
        #pragma unroll
        for (int c = 0; c < 4; c++){ ex[c] = expf(dots[c]-m); s += ex[c]; }
        #pragma unroll
        for (int c = 0; c < 4; c++) scs[c] = ex[c]/s;
    }
    __syncthreads();
    const float* C0 = g_R + (size_t)cau[k*4+0]*D_;
    const float* C1 = g_R + (size_t)cau[k*4+1]*D_;
    const float* C2 = g_R + (size_t)cau[k*4+2]*D_;
    const float* C3 = g_R + (size_t)cau[k*4+3]*D_;
    float s0 = scs[0], s1 = scs[1], s2 = scs[2], s3 = scs[3];
    for (int d = tid; d < D_; d += 256)
        g_cE[(size_t)blk*D_ + d] = s0*C0[d] + s1*C1[d] + s2*C2[d] + s3*C3[d];
}

// ---------------- delta (phase 2) ----------------
__global__ void k_d2(const int* __restrict__ emo, const float* __restrict__ pos){
    __shared__ float red[256];
    int blk = blockIdx.x, tid = threadIdx.x;
    int e = blk >> 6;
    const float* Er = g_R + (size_t)emo[e]*D_;
    const float* Y  = g_cE + (size_t)blk*D_;
    float a = 0.f;
    for (int d = tid; d < D_; d += 256){ float df = Er[d]-Y[d]; a += df*df; }
    red[tid] = a; __syncthreads();
    for (int s = 128; s; s >>= 1){ if (tid < s) red[tid] += red[tid+s]; __syncthreads(); }
    float nrm = sqrtf(red[0]);
    float* drow = g_d2 + (size_t)blk*K2_;
    for (int d = tid; d < D_; d += 256){
        float ev = Er[d], yv = Y[d];
        drow[d] = ev; drow[D_ + d] = yv; drow[1537 + d] = ev*yv;
    }
    if (tid == 0) drow[1536] = nrm;
    for (int q = tid; q < POS_; q += 256) drow[2305 + q] = pos[(size_t)blk*POS_ + q];
}

// ---------------- BatchNorm over axis=1 (biased var) + lrelu, in-place -------
__global__ void k_bn(float* __restrict__ z, int rows){
    int e = blockIdx.x;
    int d = blockIdx.y*256 + threadIdx.x;
    size_t base = (size_t)e*rows*D_ + d;
    float s = 0.f;
    for (int r = 0; r < rows; r++) s += z[base + (size_t)r*D_];
    float m = s / (float)rows;
    float v = 0.f;
    for (int r = 0; r < rows; r++){ float t = z[base + (size_t)r*D_] - m; v += t*t; }
    v /= (float)rows;
    float inv = 1.f/sqrtf(v + 1e-5f);
    for (int r = 0; r < rows; r++){
        float t = (z[base + (size_t)r*D_] - m)*inv;
        z[base + (size_t)r*D_] = lrelu(t);
    }
}

// ---------------- 2-class head: logits, log_softmax, optional argmax feat ----
__global__ void k_head(const float* __restrict__ Hx, const float* __restrict__ W,
                       const float* __restrict__ b2, float* __restrict__ out,
                       float* __restrict__ of, int rows){
    int warp = threadIdx.x >> 5, lane = threadIdx.x & 31;
    int row = blockIdx.x*8 + warp; if (row >= rows) return;
    const float* h = Hx + (size_t)row*D_;
    const float2* Wv = (const float2*)W;
    float a0 = 0.f, a1 = 0.f;
    for (int k = lane; k < D_; k += 32){
        float hv = h[k]; float2 w = Wv[k];
        a0 += hv*w.x; a1 += hv*w.y;
    }
    #pragma unroll
    for (int s = 16; s; s >>= 1){
        a0 += __shfl_down_sync(0xffffffffu, a0, s);
        a1 += __shfl_down_sync(0xffffffffu, a1, s);
    }
    if (!lane){
        float l0 = a0 + b2[0], l1 = a1 + b2[1];
        float m = fmaxf(l0, l1);
        float lse = m + logf(expf(l0-m) + expf(l1-m));
        out[row*2]   = l0 - lse;
        out[row*2+1] = l1 - lse;
        if (of) of[row] = (l1 > l0) ? 1.f : 0.f;
    }
}

// ---------------- delta3 (phase 3) ----------------
__global__ void k_d3(const int* __restrict__ emo, const int* __restrict__ cau,
                     const float* __restrict__ dis){
    __shared__ float red[256];
    int blk = blockIdx.x, tid = threadIdx.x;
    int e = blk >> 8, c = blk & 255;
    const float* Er = g_R + (size_t)emo[e]*D_;
    const float* Cr = g_R + (size_t)cau[c]*D_;
    float a = 0.f;
    for (int d = tid; d < D_; d += 256){ float df = Er[d]-Cr[d]; a += df*df; }
    red[tid] = a; __syncthreads();
    for (int s = 128; s; s >>= 1){ if (tid < s) red[tid] += red[tid+s]; __syncthreads(); }
    float nrm = sqrtf(red[0]);
    float* drow = g_d3 + (size_t)blk*K3_;
    for (int d = tid; d < D_; d += 256){
        float ev = Er[d], cv = Cr[d];
        drow[d] = ev; drow[D_ + d] = cv; drow[1537 + d] = ev*cv;
    }
    if (tid == 0){
        drow[1536] = nrm;
        drow[2355] = g_of[e*NK_ + (c >> 2)];
    }
    for (int q = tid; q < POS_; q += 256) drow[2305 + q] = dis[c*POS_ + q];
}

// ---------------- L indicator ----------------
__global__ void k_L(const int* __restrict__ lab, float* __restrict__ out){
    int e = blockIdx.x, c = threadIdx.x;
    int a = lab[e*3], b = lab[e*3+1], d = lab[e*3+2];
    out[e*NC_ + c] = (a == c || b == c || d == c) ? 1.f : 0.f;
}

// ---------------- orchestration ----------------
extern "C" void kernel_launch(void* const* d_in, const int* in_sizes, int n_in,
                              void* d_out, int out_size){
    const float* word = (const float*)d_in[0];
    const float* pos  = (const float*)d_in[1];
    const float* dis  = (const float*)d_in[2];
    const float* WihF = (const float*)d_in[3];
    const float* WhhF = (const float*)d_in[4];
    const float* bihF = (const float*)d_in[5];
    const float* bhhF = (const float*)d_in[6];
    const float* WihB = (const float*)d_in[7];
    const float* WhhB = (const float*)d_in[8];
    const float* bihB = (const float*)d_in[9];
    const float* bhhB = (const float*)d_in[10];
    const float* s1W  = (const float*)d_in[11];
    const float* s1b  = (const float*)d_in[12];
    const float* s2W  = (const float*)d_in[13];
    const float* repW = (const float*)d_in[14];
    const float* repb = (const float*)d_in[15];
    const float* W2W  = (const float*)d_in[16];
    const float* W2b  = (const float*)d_in[17];
    const float* WoW  = (const float*)d_in[18];
    const float* Wob  = (const float*)d_in[19];
    const float* W3W  = (const float*)d_in[20];
    const float* W3b  = (const float*)d_in[21];
    const float* clsW = (const float*)d_in[22];
    const float* clsb = (const float*)d_in[23];
    const int* slen   = (const int*)d_in[24];
    const int* emo    = (const int*)d_in[25];
    const int* cau    = (const int*)d_in[26];
    const int* lab    = (const int*)d_in[27];
    float* out = (float*)d_out;

    void *p_xrev,*p_xbf,*p_xbb,*p_Hs,*p_t1,*p_U,*p_R,*p_d2,*p_z2,*p_d3,*p_z3,*p_bf,*p_bb,*p_of;
    cudaGetSymbolAddress(&p_xrev, g_xrev);
    cudaGetSymbolAddress(&p_xbf,  g_xbf);
    cudaGetSymbolAddress(&p_xbb,  g_xbb);
    cudaGetSymbolAddress(&p_Hs,   g_Hs);
    cudaGetSymbolAddress(&p_t1,   g_t1);
    cudaGetSymbolAddress(&p_U,    g_U);
    cudaGetSymbolAddress(&p_R,    g_R);
    cudaGetSymbolAddress(&p_d2,   g_d2);
    cudaGetSymbolAddress(&p_z2,   g_z2);
    cudaGetSymbolAddress(&p_d3,   g_d3);
    cudaGetSymbolAddress(&p_z3,   g_z3);
    cudaGetSymbolAddress(&p_bf,   g_bf);
    cudaGetSymbolAddress(&p_bb,   g_bb);
    cudaGetSymbolAddress(&p_of,   g_of);

    // prep
    k_prep<<<B_, T_>>>(slen);
    k_gather<<<(BT_*192 + 255)/256, 256>>>((const float4*)word);
    k_bias<<<(G_ + 255)/256, 256>>>(bihF, bhhF, bihB, bhhB);
    k_zero<<<(2*2*B_*H_ + 255)/256, 256>>>();

    // input projections  (x @ Wih^T + bih + bhh)
    sgemm<true,false><<<dim3(G_/64, BT_/64), 256>>>(word, WihF, (const float*)p_bf,
                                                    (float*)p_xbf, BT_, G_, D_);
    sgemm<true,false><<<dim3(G_/64, BT_/64), 256>>>((const float*)p_xrev, WihB,
                                                    (const float*)p_bb,
                                                    (float*)p_xbb, BT_, G_, D_);
    // recurrence (both directions fused per step)
    for (int t = 0; t < T_; t++)
        k_lstm<<<dim3(B_/32, H_/32, 2), 128>>>(WhhF, WhhB, t);

    // Hs = [hs_f ; gather(hs_rev)]
    k_hs<<<(BT_*D_ + 255)/256, 256>>>();

    // attention pooling
    sgemm<false,true><<<dim3(D_/64, BT_/64), 256>>>((const float*)p_Hs, s1W, s1b,
                                                    (float*)p_t1, BT_, D_, D_);
    k_e<<<BT_/8, 256>>>(s2W);
    k_u<<<B_, 256>>>(slen);

    // shared representation
    sgemm<false,true><<<dim3(D_/64, B_/64), 256>>>((const float*)p_U, repW, repb,
                                                   (float*)p_R, B_, D_, D_);

    // phase 2
    k_chunk<<<NE_*NK_, 256>>>(emo, cau);
    k_d2<<<NE_*NK_, 256>>>(emo, pos);
    sgemm<false,false><<<dim3(D_/64, (NE_*NK_)/64), 256>>>((const float*)p_d2, W2W, W2b,
                                                           (float*)p_z2, NE_*NK_, D_, K2_);
    k_bn<<<dim3(NE_, 3), 256>>>((float*)p_z2, NK_);
    k_head<<<(NE_*NK_)/8, 256>>>((const float*)p_z2, WoW, Wob, out, (float*)p_of, NE_*NK_);

    // phase 3
    k_d3<<<NE_*NC_, 256>>>(emo, cau, dis);
    sgemm<false,false><<<dim3(D_/64, (NE_*NC_)/64), 256>>>((const float*)p_d3, W3W, W3b,
                                                           (float*)p_z3, NE_*NC_, D_, K3_);
    k_bn<<<dim3(NE_, 3), 256>>>((float*)p_z3, NC_);
    k_head<<<(NE_*NC_)/8, 256>>>((const float*)p_z3, clsW, clsb,
                                 out + NE_*NK_*2, nullptr, NE_*NC_);

    // L indicator
    k_L<<<NE_, NC_>>>(lab, out + NE_*NK_*2 + NE_*NC_*2);
}

// round 3
// speedup vs baseline: 1.7978x; 1.7978x over previous
#include <cuda_runtime.h>
#include <math.h>
#include <stdint.h>
#include <stddef.h>

// ---------------- problem dims ----------------
#define B_   256
#define T_   96
#define D_   768
#define H_   384
#define G_   1536          // 4*H
#define BT_  (B_*T_)       // 24576
#define NE_  128
#define NC_  256
#define NK_  64
#define CK_  4
#define POS_ 50
#define K2_  2355
#define K3_  2356

// ---------------- scratch ----------------
__device__ float g_xrev[BT_*D_];
__device__ float g_xbf[BT_*G_];
__device__ float g_xbb[BT_*G_];
__device__ float g_hsf[BT_*H_];
__device__ float g_hsrev[BT_*H_];
__device__ float g_hbuf[2][2][B_*H_];
__device__ float g_cbuf[2][B_*H_];
__device__ float g_Hs[BT_*D_];
__device__ float g_t1[BT_*D_];
__device__ float g_e[BT_];
__device__ float g_U[B_*D_];
__device__ float g_R[NC_*D_];
__device__ float g_E[NE_*D_];
__device__ float g_Cu[NC_*D_];
__device__ float g_cE[NE_*NK_*D_];          // chunkEmb  [8192,768]
__device__ float g_EY[NE_*NK_*D_];          // E ⊙ chunkEmb
__device__ float g_EC[NE_*NC_*D_];          // E ⊙ Cu    [32768,768]
__device__ float g_n2[NE_*NK_];
__device__ float g_n3[NE_*NC_];
__device__ float g_z2[NE_*NK_*D_];
__device__ float g_z3[NE_*NC_*D_];
__device__ float g_EW2a[NE_*D_];
__device__ float g_EW3a[NE_*D_];
__device__ float g_CW3b[NC_*D_];
__device__ float g_disW3[NC_*D_];
__device__ float g_of[NE_*NK_];
__device__ float g_bf[G_];
__device__ float g_bb[G_];
__device__ float g_zero[G_];                // stays zero
__device__ float g_WihFT[D_*G_];
__device__ float g_WihBT[D_*G_];
__device__ int   g_rev[BT_];

__device__ __forceinline__ float lrelu(float x){ return x >= 0.f ? x : 0.01f*x; }
__device__ __forceinline__ float sigm(float x){ return 1.f/(1.f+expf(-x)); }

// ---------------- prep ----------------
__global__ void k_prep(const int* __restrict__ slen){
    int b = blockIdx.x, t = threadIdx.x;
    int len = slen[b];
    g_rev[b*T_ + t] = (t < len) ? (len - 1 - t) : t;
}

__global__ void k_gather(const float4* __restrict__ word){
    int i = blockIdx.x*256 + threadIdx.x;
    if (i >= BT_*192) return;
    int bt = i / 192, q = i - bt*192;
    int b  = bt / T_;
    int rid = g_rev[bt];
    ((float4*)g_xrev)[i] = word[(b*T_ + rid)*192 + q];
}

__global__ void k_bias(const float* bihf, const float* bhhf,
                       const float* bihb, const float* bhhb){
    int i = blockIdx.x*256 + threadIdx.x;
    if (i < G_){ g_bf[i] = bihf[i] + bhhf[i]; g_bb[i] = bihb[i] + bhhb[i]; }
}

__global__ void k_zero(){
    int i = blockIdx.x*256 + threadIdx.x;
    if (i < 2*2*B_*H_) (&g_hbuf[0][0][0])[i] = 0.f;
    if (i < 2*B_*H_)   (&g_cbuf[0][0])[i]    = 0.f;
}

// Wih [G,D] -> Wt [D,G]
__global__ void k_transW(const float* __restrict__ Wf, const float* __restrict__ Wb){
    __shared__ float t[32][33];
    const float* W = blockIdx.z ? Wb : Wf;
    float* Wt = blockIdx.z ? g_WihBT : g_WihFT;
    int k0 = blockIdx.x*32, n0 = blockIdx.y*32;
    int tx = threadIdx.x, ty = threadIdx.y;
    #pragma unroll
    for (int q = 0; q < 32; q += 8)
        t[ty+q][tx] = W[(size_t)(n0+ty+q)*D_ + k0+tx];
    __syncthreads();
    #pragma unroll
    for (int q = 0; q < 32; q += 8)
        Wt[(size_t)(k0+ty+q)*G_ + n0+tx] = t[tx][ty+q];
}

// ---------------- fast SGEMM: NN, exact tiles, 128x128x16, 8x8/thread ----------
// requires M%128==0, N%128==0, K%16==0
template<bool RELU, bool ACC>
__global__ __launch_bounds__(256, 2)
void sgemmF(const float* __restrict__ A, const float* __restrict__ Bm,
            const float* __restrict__ bias, float* __restrict__ Cm,
            int M, int N, int K){
    __shared__ float As[2][16][136];   // transposed A tile, padded
    __shared__ float Bs[2][16][128];
    const int tid = threadIdx.x;
    const int bm = blockIdx.y << 7, bn = blockIdx.x << 7;
    const int tx = tid & 15, ty = tid >> 4;

    const int am0 = tid >> 2, ak0 = (tid & 3) << 2;
    const int am1 = am0 + 64;
    const int bk0 = tid >> 5, bn0 = (tid & 31) << 2;
    const int bk1 = bk0 + 8;

    float4 ra0, ra1, rb0, rb1;
    float acc[8][8];
    #pragma unroll
    for (int i = 0; i < 8; i++)
        #pragma unroll
        for (int j = 0; j < 8; j++) acc[i][j] = 0.f;

    auto loadRegs = [&](int k0){
        ra0 = *(const float4*)(A  + (size_t)(bm+am0)*K + k0 + ak0);
        ra1 = *(const float4*)(A  + (size_t)(bm+am1)*K + k0 + ak0);
        rb0 = *(const float4*)(Bm + (size_t)(k0+bk0)*N + bn + bn0);
        rb1 = *(const float4*)(Bm + (size_t)(k0+bk1)*N + bn + bn0);
    };
    auto storeSmem = [&](int buf){
        As[buf][ak0+0][am0] = ra0.x; As[buf][ak0+1][am0] = ra0.y;
        As[buf][ak0+2][am0] = ra0.z; As[buf][ak0+3][am0] = ra0.w;
        As[buf][ak0+0][am1] = ra1.x; As[buf][ak0+1][am1] = ra1.y;
        As[buf][ak0+2][am1] = ra1.z; As[buf][ak0+3][am1] = ra1.w;
        *(float4*)&Bs[buf][bk0][bn0] = rb0;
        *(float4*)&Bs[buf][bk1][bn0] = rb1;
    };

    loadRegs(0); storeSmem(0); __syncthreads();
    const int ntk = K >> 4;
    for (int kt = 0; kt < ntk; kt++){
        if (kt + 1 < ntk) loadRegs((kt+1) << 4);
        const int buf = kt & 1;
        #pragma unroll
        for (int kk = 0; kk < 16; kk++){
            float4 a0 = *(const float4*)&As[buf][kk][ty<<2];
            float4 a1 = *(const float4*)&As[buf][kk][(ty<<2)+64];
            float4 b0 = *(const float4*)&Bs[buf][kk][tx<<2];
            float4 b1 = *(const float4*)&Bs[buf][kk][(tx<<2)+64];
            float av[8] = {a0.x,a0.y,a0.z,a0.w,a1.x,a1.y,a1.z,a1.w};
            float bv[8] = {b0.x,b0.y,b0.z,b0.w,b1.x,b1.y,b1.z,b1.w};
            #pragma unroll
            for (int i = 0; i < 8; i++)
                #pragma unroll
                for (int j = 0; j < 8; j++) acc[i][j] += av[i]*bv[j];
        }
        if (kt + 1 < ntk) storeSmem(buf ^ 1);
        __syncthreads();
    }
    #pragma unroll
    for (int i = 0; i < 8; i++){
        int m = bm + (ty<<2) + (i&3) + ((i>>2)<<6);
        size_t base = (size_t)m*N;
        #pragma unroll
        for (int jg = 0; jg < 2; jg++){
            int n0 = bn + (tx<<2) + (jg<<6);
            float4 v;
            if (ACC) v = *(const float4*)&Cm[base + n0];
            else     v = *(const float4*)&bias[n0];
            v.x += acc[i][jg*4+0]; v.y += acc[i][jg*4+1];
            v.z += acc[i][jg*4+2]; v.w += acc[i][jg*4+3];
            if (RELU){ v.x = lrelu(v.x); v.y = lrelu(v.y); v.z = lrelu(v.z); v.w = lrelu(v.w); }
            *(float4*)&Cm[base + n0] = v;
        }
    }
}

// ---------------- small-K SGEMM (guards), 64x64 ----------------
template<bool TB, bool RELU>
__global__ void sgemm64(const float* __restrict__ A, const float* __restrict__ Bm,
                        const float* __restrict__ bias, float* __restrict__ Cm,
                        int M, int N, int K){
    __shared__ float As[16][65];
    __shared__ float Bs[16][65];
    int bm = blockIdx.y << 6, bn = blockIdx.x << 6;
    int tid = threadIdx.x;
    int tx = tid & 15, ty = tid >> 4;
    float acc[4][4];
    #pragma unroll
    for (int i = 0; i < 4; i++)
        #pragma unroll
        for (int j = 0; j < 4; j++) acc[i][j] = 0.f;
    int arow = tid >> 2, ak0 = (tid & 3) << 2;
    for (int k0 = 0; k0 < K; k0 += 16){
        #pragma unroll
        for (int q = 0; q < 4; q++){
            int kk = ak0 + q, gm = bm + arow, gk = k0 + kk;
            As[kk][arow] = (gm < M && gk < K) ? A[(size_t)gm*K + gk] : 0.f;
        }
        {
            int kr = tid >> 4, nc0 = (tid & 15) << 2;
            #pragma unroll
            for (int q = 0; q < 4; q++){
                int n = nc0 + q, gk = k0 + kr, gn = bn + n;
                Bs[kr][n] = (gk < K && gn < N) ? Bm[(size_t)gk*N + gn] : 0.f;
            }
        }
        __syncthreads();
        #pragma unroll
        for (int kk = 0; kk < 16; kk++){
            float a[4], b[4];
            #pragma unroll
            for (int i = 0; i < 4; i++) a[i] = As[kk][ty + (i<<4)];
            #pragma unroll
            for (int j = 0; j < 4; j++) b[j] = Bs[kk][tx + (j<<4)];
            #pragma unroll
            for (int i = 0; i < 4; i++)
                #pragma unroll
                for (int j = 0; j < 4; j++) acc[i][j] += a[i]*b[j];
        }
        __syncthreads();
    }
    #pragma unroll
    for (int i = 0; i < 4; i++){
        int gm = bm + ty + (i<<4); if (gm >= M) continue;
        #pragma unroll
        for (int j = 0; j < 4; j++){
            int gn = bn + tx + (j<<4); if (gn >= N) continue;
            float v = acc[i][j] + bias[gn];
            if (RELU) v = lrelu(v);
            Cm[(size_t)gm*N + gn] = v;
        }
    }
}

// ---------------- fused LSTM step ----------------
__global__ void k_lstm(const float* __restrict__ WhhF,
                       const float* __restrict__ WhhB, int t){
    int dir = blockIdx.z;
    const float* Whh = dir ? WhhB : WhhF;
    const float* xb  = dir ? g_xbb : g_xbf;
    const float* hp  = g_hbuf[dir][t & 1];
    float* hn        = g_hbuf[dir][(t & 1) ^ 1];
    float* cc        = g_cbuf[dir];
    float* hs        = dir ? g_hsrev : g_hsf;

    int bBase = blockIdx.x << 5, jBase = blockIdx.y << 5;
    int tid = threadIdx.x, tx = tid & 15, ty = tid >> 4;

    __shared__ float shh[32][17];
    __shared__ float shw[4][16][33];

    float acc[4][4][2];
    #pragma unroll
    for (int a = 0; a < 4; a++)
        #pragma unroll
        for (int g = 0; g < 4; g++){ acc[a][g][0]=0.f; acc[a][g][1]=0.f; }

    for (int kc = 0; kc < H_; kc += 16){
        #pragma unroll
        for (int q = 0; q < 4; q++){
            int e = tid + 128*q;
            int bl = e >> 4, kk = e & 15;
            shh[bl][kk] = hp[(bBase + bl)*H_ + kc + kk];
        }
        #pragma unroll
        for (int q = 0; q < 16; q++){
            int e = tid + 128*q;
            int g = e >> 9, rem = e & 511;
            int jl = rem >> 4, kk = rem & 15;
            shw[g][kk][jl] = Whh[(size_t)(g*H_ + jBase + jl)*H_ + kc + kk];
        }
        __syncthreads();
        #pragma unroll
        for (int kk = 0; kk < 16; kk++){
            float hv[4];
            #pragma unroll
            for (int bb = 0; bb < 4; bb++) hv[bb] = shh[(ty<<2)+bb][kk];
            #pragma unroll
            for (int g = 0; g < 4; g++){
                float w0 = shw[g][kk][(tx<<1)];
                float w1 = shw[g][kk][(tx<<1)+1];
                #pragma unroll
                for (int bb = 0; bb < 4; bb++){
                    acc[bb][g][0] += hv[bb]*w0;
                    acc[bb][g][1] += hv[bb]*w1;
                }
            }
        }
        __syncthreads();
    }
    #pragma unroll
    for (int bb = 0; bb < 4; bb++){
        int b = bBase + (ty<<2) + bb;
        const float* xrow = xb + (size_t)(b*T_ + t)*G_;
        #pragma unroll
        for (int jj = 0; jj < 2; jj++){
            int j = jBase + (tx<<1) + jj;
            float gi = acc[bb][0][jj] + xrow[j];
            float gf = acc[bb][1][jj] + xrow[H_ + j];
            float gg = acc[bb][2][jj] + xrow[2*H_ + j];
            float go = acc[bb][3][jj] + xrow[3*H_ + j];
            float cold = cc[b*H_ + j];
            float cn = sigm(gf)*cold + sigm(gi)*tanhf(gg);
            float hv = sigm(go)*tanhf(cn);
            cc[b*H_ + j] = cn;
            hn[b*H_ + j] = hv;
            hs[(size_t)(b*T_ + t)*H_ + j] = hv;
        }
    }
}

// ---------------- Hs assembly ----------------
__global__ void k_hs(){
    int i = blockIdx.x*256 + threadIdx.x;
    if (i >= BT_*D_) return;
    int bt = i / D_, d = i - bt*D_;
    if (d < H_) g_Hs[i] = g_hsf[bt*H_ + d];
    else {
        int b = bt / T_;
        int rid = g_rev[bt];
        g_Hs[i] = g_hsrev[(b*T_ + rid)*H_ + d - H_];
    }
}

// ---------------- e = t1 @ s2 ----------------
__global__ void k_e(const float* __restrict__ s2){
    int warp = threadIdx.x >> 5, lane = threadIdx.x & 31;
    int row = blockIdx.x*8 + warp; if (row >= BT_) return;
    const float* h = g_t1 + (size_t)row*D_;
    float a = 0.f;
    for (int k = lane; k < D_; k += 32) a += h[k]*s2[k];
    #pragma unroll
    for (int s = 16; s; s >>= 1) a += __shfl_down_sync(0xffffffffu, a, s);
    if (!lane) g_e[row] = a;
}

// ---------------- masked pooling ----------------
__global__ void k_u(const int* __restrict__ slen){
    __shared__ float al[T_];
    __shared__ float red[256];
    int b = blockIdx.x, tid = threadIdx.x;
    int len = slen[b];
    float v = 0.f;
    if (tid < T_){ v = (tid < len) ? g_e[b*T_ + tid] : 0.f; al[tid] = v; }
    red[tid] = v; __syncthreads();
    for (int s = 128; s; s >>= 1){ if (tid < s) red[tid] += red[tid+s]; __syncthreads(); }
    float denom = red[0] + 1e-9f;
    __syncthreads();
    if (tid < T_) al[tid] = al[tid] / denom;
    __syncthreads();
    for (int d = tid; d < D_; d += 256){
        float acc = 0.f;
        for (int t = 0; t < T_; t++) acc += al[t]*g_Hs[(size_t)(b*T_ + t)*D_ + d];
        g_U[b*D_ + d] = acc;
    }
}

// ---------------- gather E / Cu rows ----------------
__global__ void k_gatherR(const int* __restrict__ emo, const int* __restrict__ cau){
    int i = blockIdx.x*256 + threadIdx.x;
    if (i < NE_*D_){ int r = i / D_, d = i - r*D_; g_E[i]  = g_R[(size_t)emo[r]*D_ + d]; }
    if (i < NC_*D_){ int r = i / D_, d = i - r*D_; g_Cu[i] = g_R[(size_t)cau[r]*D_ + d]; }
}

// ---------------- per-chunk cross attention ----------------
__global__ void k_chunk(){
    __shared__ float Esh[D_];
    __shared__ float red[256];
    __shared__ float scs[4];
    int blk = blockIdx.x, tid = threadIdx.x;
    int e = blk >> 6, k = blk & 63;
    const float* Er = g_E + (size_t)e*D_;
    for (int d = tid; d < D_; d += 256) Esh[d] = Er[d];
    __syncthreads();
    float dots[4];
    for (int c = 0; c < 4; c++){
        const float* Cr = g_Cu + (size_t)(k*4 + c)*D_;
        float a = 0.f;
        for (int d = tid; d < D_; d += 256) a += Esh[d]*Cr[d];
        red[tid] = a; __syncthreads();
        for (int s = 128; s; s >>= 1){ if (tid < s) red[tid] += red[tid+s]; __syncthreads(); }
        dots[c] = red[0]; __syncthreads();
    }
    if (tid == 0){
        float m = fmaxf(fmaxf(dots[0],dots[1]), fmaxf(dots[2],dots[3]));
        float ex[4], s = 0.f;
        #pragma unroll
        for (int c = 0; c < 4; c++){ ex[c] = expf(dots[c]-m); s += ex[c]; }
        #pragma unroll
        for (int c = 0; c < 4; c++) scs[c] = ex[c]/s;
    }
    __syncthreads();
    const float* C0 = g_Cu + (size_t)(k*4+0)*D_;
    const float* C1 = g_Cu + (size_t)(k*4+1)*D_;
    const float* C2 = g_Cu + (size_t)(k*4+2)*D_;
    const float* C3 = g_Cu + (size_t)(k*4+3)*D_;
    float s0 = scs[0], s1 = scs[1], s2 = scs[2], s3 = scs[3];
    for (int d = tid; d < D_; d += 256)
        g_cE[(size_t)blk*D_ + d] = s0*C0[d] + s1*C1[d] + s2*C2[d] + s3*C3[d];
}

// ---------------- EY = E⊙Y, nrm2 ----------------
__global__ void k_EY(){
    __shared__ float red[256];
    int row = blockIdx.x, tid = threadIdx.x;
    int e = row >> 6;
    const float* Er = g_E + (size_t)e*D_;
    const float* Y  = g_cE + (size_t)row*D_;
    float a = 0.f;
    for (int d = tid; d < D_; d += 256){
        float ev = Er[d], yv = Y[d];
        float df = ev - yv; a += df*df;
        g_EY[(size_t)row*D_ + d] = ev*yv;
    }
    red[tid] = a; __syncthreads();
    for (int s = 128; s; s >>= 1){ if (tid < s) red[tid] += red[tid+s]; __syncthreads(); }
    if (tid == 0) g_n2[row] = sqrtf(red[0]);
}

// ---------------- EC = E⊙Cu, nrm3 ----------------
__global__ void k_EC(){
    __shared__ float red[256];
    int row = blockIdx.x, tid = threadIdx.x;
    int e = row >> 8, c = row & 255;
    const float* Er = g_E + (size_t)e*D_;
    const float* Cr = g_Cu + (size_t)c*D_;
    float a = 0.f;
    for (int d = tid; d < D_; d += 256){
        float ev = Er[d], cv = Cr[d];
        float df = ev - cv; a += df*df;
        g_EC[(size_t)row*D_ + d] = ev*cv;
    }
    red[tid] = a; __syncthreads();
    for (int s = 128; s; s >>= 1){ if (tid < s) red[tid] += red[tid+s]; __syncthreads(); }
    if (tid == 0) g_n3[row] = sqrtf(red[0]);
}

// ---------------- epilogue adds ----------------
__global__ void k_add2(const float* __restrict__ W2W){
    int idx = blockIdx.x*256 + threadIdx.x;
    if (idx >= NE_*NK_*D_) return;
    int row = idx / D_, n = idx - row*D_;
    int e = row >> 6;
    g_z2[idx] += g_EW2a[e*D_ + n] + g_n2[row]*W2W[(size_t)1536*D_ + n];
}

__global__ void k_add3(const float* __restrict__ W3W){
    int idx = blockIdx.x*256 + threadIdx.x;
    if (idx >= NE_*NC_*D_) return;
    int row = idx / D_, n = idx - row*D_;
    int e = row >> 8, c = row & 255;
    g_z3[idx] += g_EW3a[e*D_ + n] + g_CW3b[c*D_ + n] + g_disW3[c*D_ + n]
               + g_n3[row]*W3W[(size_t)1536*D_ + n]
               + g_of[(e<<6) + (c>>2)]*W3W[(size_t)2355*D_ + n];
}

// ---------------- BatchNorm (biased var) + lrelu ----------------
__global__ void k_bn(float* __restrict__ z, int rows){
    int e = blockIdx.x;
    int d = blockIdx.y*256 + threadIdx.x;
    size_t base = (size_t)e*rows*D_ + d;
    float s = 0.f;
    for (int r = 0; r < rows; r++) s += z[base + (size_t)r*D_];
    float m = s / (float)rows;
    float v = 0.f;
    for (int r = 0; r < rows; r++){ float t = z[base + (size_t)r*D_] - m; v += t*t; }
    v /= (float)rows;
    float inv = 1.f/sqrtf(v + 1e-5f);
    for (int r = 0; r < rows; r++){
        float t = (z[base + (size_t)r*D_] - m)*inv;
        z[base + (size_t)r*D_] = lrelu(t);
    }
}

// ---------------- 2-class head ----------------
__global__ void k_head(const float* __restrict__ Hx, const float* __restrict__ W,
                       const float* __restrict__ b2, float* __restrict__ out,
                       float* __restrict__ of, int rows){
    int warp = threadIdx.x >> 5, lane = threadIdx.x & 31;
    int row = blockIdx.x*8 + warp; if (row >= rows) return;
    const float* h = Hx + (size_t)row*D_;
    const float2* Wv = (const float2*)W;
    float a0 = 0.f, a1 = 0.f;
    for (int k = lane; k < D_; k += 32){
        float hv = h[k]; float2 w = Wv[k];
        a0 += hv*w.x; a1 += hv*w.y;
    }
    #pragma unroll
    for (int s = 16; s; s >>= 1){
        a0 += __shfl_down_sync(0xffffffffu, a0, s);
        a1 += __shfl_down_sync(0xffffffffu, a1, s);
    }
    if (!lane){
        float l0 = a0 + b2[0], l1 = a1 + b2[1];
        float m = fmaxf(l0, l1);
        float lse = m + logf(expf(l0-m) + expf(l1-m));
        out[row*2]   = l0 - lse;
        out[row*2+1] = l1 - lse;
        if (of) of[row] = (l1 > l0) ? 1.f : 0.f;
    }
}

// ---------------- L indicator ----------------
__global__ void k_L(const int* __restrict__ lab, float* __restrict__ out){
    int e = blockIdx.x, c = threadIdx.x;
    int a = lab[e*3], b = lab[e*3+1], d = lab[e*3+2];
    out[e*NC_ + c] = (a == c || b == c || d == c) ? 1.f : 0.f;
}

// ---------------- orchestration ----------------
extern "C" void kernel_launch(void* const* d_in, const int* in_sizes, int n_in,
                              void* d_out, int out_size){
    const float* word = (const float*)d_in[0];
    const float* pos  = (const float*)d_in[1];
    const float* dis  = (const float*)d_in[2];
    const float* WihF = (const float*)d_in[3];
    const float* WhhF = (const float*)d_in[4];
    const float* bihF = (const float*)d_in[5];
    const float* bhhF = (const float*)d_in[6];
    const float* WihB = (const float*)d_in[7];
    const float* WhhB = (const float*)d_in[8];
    const float* bihB = (const float*)d_in[9];
    const float* bhhB = (const float*)d_in[10];
    const float* s1W  = (const float*)d_in[11];
    const float* s1b  = (const float*)d_in[12];
    const float* s2W  = (const float*)d_in[13];
    const float* repW = (const float*)d_in[14];
    const float* repb = (const float*)d_in[15];
    const float* W2W  = (const float*)d_in[16];
    const float* W2b  = (const float*)d_in[17];
    const float* WoW  = (const float*)d_in[18];
    const float* Wob  = (const float*)d_in[19];
    const float* W3W  = (const float*)d_in[20];
    const float* W3b  = (const float*)d_in[21];
    const float* clsW = (const float*)d_in[22];
    const float* clsb = (const float*)d_in[23];
    const int* slen   = (const int*)d_in[24];
    const int* emo    = (const int*)d_in[25];
    const int* cau    = (const int*)d_in[26];
    const int* lab    = (const int*)d_in[27];
    float* out = (float*)d_out;

    void *p_xrev,*p_xbf,*p_xbb,*p_Hs,*p_t1,*p_U,*p_R,*p_E,*p_Cu,*p_cE,*p_EY,*p_EC;
    void *p_z2,*p_z3,*p_EW2a,*p_EW3a,*p_CW3b,*p_disW3,*p_bf,*p_bb,*p_zero,*p_of;
    void *p_WFT,*p_WBT;
    cudaGetSymbolAddress(&p_xrev, g_xrev);
    cudaGetSymbolAddress(&p_xbf,  g_xbf);
    cudaGetSymbolAddress(&p_xbb,  g_xbb);
    cudaGetSymbolAddress(&p_Hs,   g_Hs);
    cudaGetSymbolAddress(&p_t1,   g_t1);
    cudaGetSymbolAddress(&p_U,    g_U);
    cudaGetSymbolAddress(&p_R,    g_R);
    cudaGetSymbolAddress(&p_E,    g_E);
    cudaGetSymbolAddress(&p_Cu,   g_Cu);
    cudaGetSymbolAddress(&p_cE,   g_cE);
    cudaGetSymbolAddress(&p_EY,   g_EY);
    cudaGetSymbolAddress(&p_EC,   g_EC);
    cudaGetSymbolAddress(&p_z2,   g_z2);
    cudaGetSymbolAddress(&p_z3,   g_z3);
    cudaGetSymbolAddress(&p_EW2a, g_EW2a);
    cudaGetSymbolAddress(&p_EW3a, g_EW3a);
    cudaGetSymbolAddress(&p_CW3b, g_CW3b);
    cudaGetSymbolAddress(&p_disW3,g_disW3);
    cudaGetSymbolAddress(&p_bf,   g_bf);
    cudaGetSymbolAddress(&p_bb,   g_bb);
    cudaGetSymbolAddress(&p_zero, g_zero);
    cudaGetSymbolAddress(&p_of,   g_of);
    cudaGetSymbolAddress(&p_WFT,  g_WihFT);
    cudaGetSymbolAddress(&p_WBT,  g_WihBT);

    // prep
    k_prep<<<B_, T_>>>(slen);
    k_gather<<<(BT_*192 + 255)/256, 256>>>((const float4*)word);
    k_bias<<<(G_ + 255)/256, 256>>>(bihF, bhhF, bihB, bhhB);
    k_zero<<<(2*2*B_*H_ + 255)/256, 256>>>();
    k_transW<<<dim3(D_/32, G_/32, 2), dim3(32,8)>>>(WihF, WihB);

    // input projections (NN with transposed weights)
    sgemmF<false,false><<<dim3(G_/128, BT_/128), 256>>>(word, (const float*)p_WFT,
        (const float*)p_bf, (float*)p_xbf, BT_, G_, D_);
    sgemmF<false,false><<<dim3(G_/128, BT_/128), 256>>>((const float*)p_xrev, (const float*)p_WBT,
        (const float*)p_bb, (float*)p_xbb, BT_, G_, D_);

    // recurrence
    for (int t = 0; t < T_; t++)
        k_lstm<<<dim3(B_/32, H_/32, 2), 128>>>(WhhF, WhhB, t);

    k_hs<<<(BT_*D_ + 255)/256, 256>>>();

    // attention pooling
    sgemmF<true,false><<<dim3(D_/128, BT_/128), 256>>>((const float*)p_Hs, s1W, s1b,
        (float*)p_t1, BT_, D_, D_);
    k_e<<<BT_/8, 256>>>(s2W);
    k_u<<<B_, 256>>>(slen);

    // shared representation
    sgemmF<true,false><<<dim3(D_/128, B_/128), 256>>>((const float*)p_U, repW, repb,
        (float*)p_R, B_, D_, D_);
    k_gatherR<<<(NC_*D_ + 255)/256, 256>>>(emo, cau);

    // phase 2
    k_chunk<<<NE_*NK_, 256>>>();
    k_EY<<<NE_*NK_, 256>>>();
    sgemm64<false,false><<<dim3(D_/64, (NE_*NK_)/64), 256>>>(pos, W2W + (size_t)2305*D_,
        W2b, (float*)p_z2, NE_*NK_, D_, POS_);
    sgemmF<false,true><<<dim3(D_/128, (NE_*NK_)/128), 256>>>((const float*)p_cE,
        W2W + (size_t)768*D_, (const float*)p_zero, (float*)p_z2, NE_*NK_, D_, D_);
    sgemmF<false,true><<<dim3(D_/128, (NE_*NK_)/128), 256>>>((const float*)p_EY,
        W2W + (size_t)1537*D_, (const float*)p_zero, (float*)p_z2, NE_*NK_, D_, D_);
    sgemmF<false,false><<<dim3(D_/128, NE_/128), 256>>>((const float*)p_E, W2W,
        (const float*)p_zero, (float*)p_EW2a, NE_, D_, D_);
    k_add2<<<(NE_*NK_*D_ + 255)/256, 256>>>(W2W);
    k_bn<<<dim3(NE_, 3), 256>>>((float*)p_z2, NK_);
    k_head<<<(NE_*NK_)/8, 256>>>((const float*)p_z2, WoW, Wob, out, (float*)p_of, NE_*NK_);

    // phase 3
    k_EC<<<NE_*NC_, 256>>>();
    sgemmF<false,false><<<dim3(D_/128, (NE_*NC_)/128), 256>>>((const float*)p_EC,
        W3W + (size_t)1537*D_, W3b, (float*)p_z3, NE_*NC_, D_, D_);
    sgemmF<false,false><<<dim3(D_/128, NE_/128), 256>>>((const float*)p_E, W3W,
        (const float*)p_zero, (float*)p_EW3a, NE_, D_, D_);
    sgemmF<false,false><<<dim3(D_/128, NC_/128), 256>>>((const float*)p_Cu,
        W3W + (size_t)768*D_, (const float*)p_zero, (float*)p_CW3b, NC_, D_, D_);
    sgemm64<false,false><<<dim3(D_/64, (NC_+63)/64), 256>>>(dis, W3W + (size_t)2305*D_,
        (const float*)p_zero, (float*)p_disW3, NC_, D_, POS_);
    k_add3<<<(NE_*NC_*D_ + 255)/256, 256>>>(W3W);
    k_bn<<<dim3(NE_, 3), 256>>>((float*)p_z3, NC_);
    k_head<<<(NE_*NC_)/8, 256>>>((const float*)p_z3, clsW, clsb,
        out + NE_*NK_*2, nullptr, NE_*NC_);

    // L indicator
    k_L<<<NE_, NC_>>>(lab, out + NE_*NK_*2 + NE_*NC_*2);
}

// round 7
// speedup vs baseline: 1.8188x; 1.0117x over previous
#include <cuda_runtime.h>
#include <math.h>
#include <stdint.h>
#include <stddef.h>

// ---------------- problem dims ----------------
#define B_   256
#define T_   96
#define D_   768
#define H_   384
#define G_   1536          // 4*H
#define BT_  (B_*T_)       // 24576
#define NE_  128
#define NC_  256
#define NK_  64
#define CK_  4
#define POS_ 50

// ---------------- scratch ----------------
__device__ float g_xrev[BT_*D_];
__device__ float g_xbf[BT_*G_];
__device__ float g_xbb[BT_*G_];
__device__ float g_hsf[BT_*H_];
__device__ float g_hsrev[BT_*H_];
__device__ float g_hbuf[2][2][B_*H_];
__device__ float g_cbuf[2][B_*H_];
__device__ float g_Hs[BT_*D_];
__device__ float g_t1[BT_*D_];
__device__ float g_e[BT_];
__device__ float g_U[B_*D_];
__device__ float g_R[NC_*D_];
__device__ float g_E[NE_*D_];
__device__ float g_Cu[NC_*D_];
__device__ float g_cE[NE_*NK_*D_];
__device__ float g_EY[NE_*NK_*D_];
__device__ float g_EC[NE_*NC_*D_];
__device__ float g_n2[NE_*NK_];
__device__ float g_n3[NE_*NC_];
__device__ float g_z2[NE_*NK_*D_];
__device__ float g_z3[NE_*NC_*D_];
__device__ float g_EW2a[NE_*D_];
__device__ float g_EW3a[NE_*D_];
__device__ float g_CW3b[NC_*D_];
__device__ float g_disW3[NC_*D_];
__device__ float g_of[NE_*NK_];
__device__ float g_bf[G_];
__device__ float g_bb[G_];
__device__ float g_zero[G_];
__device__ float g_WihFT[D_*G_];
__device__ float g_WihBT[D_*G_];
__device__ int   g_rev[BT_];

__device__ __forceinline__ float lrelu(float x){ return x >= 0.f ? x : 0.01f*x; }
__device__ __forceinline__ float sigm(float x){ return 1.f/(1.f+expf(-x)); }
__device__ __forceinline__ uint32_t f2tf32(float f){
    uint32_t r; asm("cvt.rna.tf32.f32 %0, %1;" : "=r"(r) : "f"(f)); return r;
}
__device__ __forceinline__ float u2f(uint32_t u){ return __uint_as_float(u); }

#define MMA8(C, A0,A1,A2,A3, B0,B1) \
    asm volatile("mma.sync.aligned.m16n8k8.row.col.f32.tf32.tf32.f32 " \
        "{%0,%1,%2,%3}, {%4,%5,%6,%7}, {%8,%9}, {%0,%1,%2,%3};" \
        : "+f"((C)[0]),"+f"((C)[1]),"+f"((C)[2]),"+f"((C)[3]) \
        : "r"(A0),"r"(A1),"r"(A2),"r"(A3),"r"(B0),"r"(B1))

// ---------------- prep ----------------
__global__ void k_prep(const int* __restrict__ slen){
    int b = blockIdx.x, t = threadIdx.x;
    int len = slen[b];
    g_rev[b*T_ + t] = (t < len) ? (len - 1 - t) : t;
}

__global__ void k_gather(const float4* __restrict__ word){
    int i = blockIdx.x*256 + threadIdx.x;
    if (i >= BT_*192) return;
    int bt = i / 192, q = i - bt*192;
    int b  = bt / T_;
    int rid = g_rev[bt];
    ((float4*)g_xrev)[i] = word[(b*T_ + rid)*192 + q];
}

__global__ void k_bias(const float* bihf, const float* bhhf,
                       const float* bihb, const float* bhhb){
    int i = blockIdx.x*256 + threadIdx.x;
    if (i < G_){ g_bf[i] = bihf[i] + bhhf[i]; g_bb[i] = bihb[i] + bhhb[i]; }
}

__global__ void k_zero(){
    int i = blockIdx.x*256 + threadIdx.x;
    if (i < 2*2*B_*H_) (&g_hbuf[0][0][0])[i] = 0.f;
    if (i < 2*B_*H_)   (&g_cbuf[0][0])[i]    = 0.f;
}

// Wih [G,D] -> Wt [D,G]
__global__ void k_transW(const float* __restrict__ Wf, const float* __restrict__ Wb){
    __shared__ float t[32][33];
    const float* W = blockIdx.z ? Wb : Wf;
    float* Wt = blockIdx.z ? g_WihBT : g_WihFT;
    int k0 = blockIdx.x*32, n0 = blockIdx.y*32;
    int tx = threadIdx.x, ty = threadIdx.y;
    #pragma unroll
    for (int q = 0; q < 32; q += 8)
        t[ty+q][tx] = W[(size_t)(n0+ty+q)*D_ + k0+tx];
    __syncthreads();
    #pragma unroll
    for (int q = 0; q < 32; q += 8)
        Wt[(size_t)(k0+ty+q)*G_ + n0+tx] = t[tx][ty+q];
}

// ---------------- fp32 SGEMM: NN, exact tiles, 128x128x16, 8x8/thread --------
// Used UPSTREAM of the masked-attention normalization (catastrophic-cancellation
// amplifier): input projections + s1 GEMM. Proven rel_err 6.6e-5 in R3.
template<bool RELU, bool ACC>
__global__ __launch_bounds__(256, 2)
void sgemmF(const float* __restrict__ A, const float* __restrict__ Bm,
            const float* __restrict__ bias, float* __restrict__ Cm,
            int M, int N, int K){
    __shared__ float As[2][16][136];
    __shared__ float Bs[2][16][128];
    const int tid = threadIdx.x;
    const int bm = blockIdx.y << 7, bn = blockIdx.x << 7;
    const int tx = tid & 15, ty = tid >> 4;

    const int am0 = tid >> 2, ak0 = (tid & 3) << 2;
    const int am1 = am0 + 64;
    const int bk0 = tid >> 5, bn0 = (tid & 31) << 2;
    const int bk1 = bk0 + 8;

    float4 ra0, ra1, rb0, rb1;
    float acc[8][8];
    #pragma unroll
    for (int i = 0; i < 8; i++)
        #pragma unroll
        for (int j = 0; j < 8; j++) acc[i][j] = 0.f;

    auto loadRegs = [&](int k0){
        ra0 = *(const float4*)(A  + (size_t)(bm+am0)*K + k0 + ak0);
        ra1 = *(const float4*)(A  + (size_t)(bm+am1)*K + k0 + ak0);
        rb0 = *(const float4*)(Bm + (size_t)(k0+bk0)*N + bn + bn0);
        rb1 = *(const float4*)(Bm + (size_t)(k0+bk1)*N + bn + bn0);
    };
    auto storeSmem = [&](int buf){
        As[buf][ak0+0][am0] = ra0.x; As[buf][ak0+1][am0] = ra0.y;
        As[buf][ak0+2][am0] = ra0.z; As[buf][ak0+3][am0] = ra0.w;
        As[buf][ak0+0][am1] = ra1.x; As[buf][ak0+1][am1] = ra1.y;
        As[buf][ak0+2][am1] = ra1.z; As[buf][ak0+3][am1] = ra1.w;
        *(float4*)&Bs[buf][bk0][bn0] = rb0;
        *(float4*)&Bs[buf][bk1][bn0] = rb1;
    };

    loadRegs(0); storeSmem(0); __syncthreads();
    const int ntk = K >> 4;
    for (int kt = 0; kt < ntk; kt++){
        if (kt + 1 < ntk) loadRegs((kt+1) << 4);
        const int buf = kt & 1;
        #pragma unroll
        for (int kk = 0; kk < 16; kk++){
            float4 a0 = *(const float4*)&As[buf][kk][ty<<2];
            float4 a1 = *(const float4*)&As[buf][kk][(ty<<2)+64];
            float4 b0 = *(const float4*)&Bs[buf][kk][tx<<2];
            float4 b1 = *(const float4*)&Bs[buf][kk][(tx<<2)+64];
            float av[8] = {a0.x,a0.y,a0.z,a0.w,a1.x,a1.y,a1.z,a1.w};
            float bv[8] = {b0.x,b0.y,b0.z,b0.w,b1.x,b1.y,b1.z,b1.w};
            #pragma unroll
            for (int i = 0; i < 8; i++)
                #pragma unroll
                for (int j = 0; j < 8; j++) acc[i][j] += av[i]*bv[j];
        }
        if (kt + 1 < ntk) storeSmem(buf ^ 1);
        __syncthreads();
    }
    #pragma unroll
    for (int i = 0; i < 8; i++){
        int m = bm + (ty<<2) + (i&3) + ((i>>2)<<6);
        size_t base = (size_t)m*N;
        #pragma unroll
        for (int jg = 0; jg < 2; jg++){
            int n0 = bn + (tx<<2) + (jg<<6);
            float4 v;
            if (ACC) v = *(const float4*)&Cm[base + n0];
            else     v = *(const float4*)&bias[n0];
            v.x += acc[i][jg*4+0]; v.y += acc[i][jg*4+1];
            v.z += acc[i][jg*4+2]; v.w += acc[i][jg*4+3];
            if (RELU){ v.x = lrelu(v.x); v.y = lrelu(v.y); v.z = lrelu(v.z); v.w = lrelu(v.w); }
            *(float4*)&Cm[base + n0] = v;
        }
    }
}

// ---------------- TF32 4x GEMM: NN, exact tiles, 128x128x16 -------------------
// Used DOWNSTREAM of the amplifier only (bounded operators after it).
template<bool RELU, bool ACC>
__global__ __launch_bounds__(256)
void tgemm(const float* __restrict__ A, const float* __restrict__ Bm,
           const float* __restrict__ bias, float* __restrict__ Cm,
           int M, int N, int K){
    __shared__ float As[2][16][136];   // transposed A tile
    __shared__ float Bs[2][16][136];
    const int tid = threadIdx.x;
    const int bm = blockIdx.y << 7, bn = blockIdx.x << 7;
    const int warp = tid >> 5, lane = tid & 31;
    const int gid = lane >> 2, tig = lane & 3;
    const int wm = (warp & 1) << 6;
    const int wn = (warp >> 1) << 5;

    const int am0 = tid >> 2, ak0 = (tid & 3) << 2;
    const int am1 = am0 + 64;
    const int bk0 = tid >> 5, bn0 = (tid & 31) << 2;
    const int bk1 = bk0 + 8;

    float4 ra0, ra1, rb0, rb1;
    float acc[4][4][4];
    #pragma unroll
    for (int i = 0; i < 4; i++)
        #pragma unroll
        for (int j = 0; j < 4; j++)
            #pragma unroll
            for (int q = 0; q < 4; q++) acc[i][j][q] = 0.f;

    auto loadRegs = [&](int k0){
        ra0 = *(const float4*)(A  + (size_t)(bm+am0)*K + k0 + ak0);
        ra1 = *(const float4*)(A  + (size_t)(bm+am1)*K + k0 + ak0);
        rb0 = *(const float4*)(Bm + (size_t)(k0+bk0)*N + bn + bn0);
        rb1 = *(const float4*)(Bm + (size_t)(k0+bk1)*N + bn + bn0);
    };
    auto storeSmem = [&](int buf){
        As[buf][ak0+0][am0] = ra0.x; As[buf][ak0+1][am0] = ra0.y;
        As[buf][ak0+2][am0] = ra0.z; As[buf][ak0+3][am0] = ra0.w;
        As[buf][ak0+0][am1] = ra1.x; As[buf][ak0+1][am1] = ra1.y;
        As[buf][ak0+2][am1] = ra1.z; As[buf][ak0+3][am1] = ra1.w;
        *(float4*)&Bs[buf][bk0][bn0] = rb0;
        *(float4*)&Bs[buf][bk1][bn0] = rb1;
    };

    loadRegs(0); storeSmem(0); __syncthreads();
    const int ntk = K >> 4;
    for (int kt = 0; kt < ntk; kt++){
        if (kt + 1 < ntk) loadRegs((kt+1) << 4);
        const int buf = kt & 1;
        #pragma unroll
        for (int k8 = 0; k8 < 2; k8++){
            const int kk = (k8 << 3) + tig;
            uint32_t ah[4][4], al[4][4];
            #pragma unroll
            for (int mt = 0; mt < 4; mt++){
                int r = wm + (mt << 4) + gid;
                float v0 = As[buf][kk][r];
                float v1 = As[buf][kk][r+8];
                float v2 = As[buf][kk+4][r];
                float v3 = As[buf][kk+4][r+8];
                ah[mt][0] = f2tf32(v0); al[mt][0] = f2tf32(v0 - u2f(ah[mt][0]));
                ah[mt][1] = f2tf32(v1); al[mt][1] = f2tf32(v1 - u2f(ah[mt][1]));
                ah[mt][2] = f2tf32(v2); al[mt][2] = f2tf32(v2 - u2f(ah[mt][2]));
                ah[mt][3] = f2tf32(v3); al[mt][3] = f2tf32(v3 - u2f(ah[mt][3]));
            }
            #pragma unroll
            for (int nt = 0; nt < 4; nt++){
                int c = wn + (nt << 3) + gid;
                float w0 = Bs[buf][kk][c];
                float w1 = Bs[buf][kk+4][c];
                uint32_t bh0 = f2tf32(w0), bl0 = f2tf32(w0 - u2f(bh0));
                uint32_t bh1 = f2tf32(w1), bl1 = f2tf32(w1 - u2f(bh1));
                #pragma unroll
                for (int mt = 0; mt < 4; mt++){
                    MMA8(acc[mt][nt], ah[mt][0],ah[mt][1],ah[mt][2],ah[mt][3], bh0,bh1);
                    MMA8(acc[mt][nt], ah[mt][0],ah[mt][1],ah[mt][2],ah[mt][3], bl0,bl1);
                    MMA8(acc[mt][nt], al[mt][0],al[mt][1],al[mt][2],al[mt][3], bh0,bh1);
                    MMA8(acc[mt][nt], al[mt][0],al[mt][1],al[mt][2],al[mt][3], bl0,bl1);
                }
            }
        }
        if (kt + 1 < ntk) storeSmem(buf ^ 1);
        __syncthreads();
    }
    #pragma unroll
    for (int mt = 0; mt < 4; mt++){
        int r0 = bm + wm + (mt << 4) + gid;
        #pragma unroll
        for (int nt = 0; nt < 4; nt++){
            int c = bn + wn + (nt << 3) + (tig << 1);
            #pragma unroll
            for (int half = 0; half < 2; half++){
                int r = r0 + (half << 3);
                float* dst = Cm + (size_t)r*N + c;
                float x0, x1;
                if (ACC){ x0 = dst[0]; x1 = dst[1]; }
                else    { x0 = bias[c]; x1 = bias[c+1]; }
                x0 += acc[mt][nt][half*2+0];
                x1 += acc[mt][nt][half*2+1];
                if (RELU){ x0 = lrelu(x0); x1 = lrelu(x1); }
                dst[0] = x0; dst[1] = x1;
            }
        }
    }
}

// ---------------- small-K SGEMM (guards), 64x64 ----------------
template<bool TB, bool RELU>
__global__ void sgemm64(const float* __restrict__ A, const float* __restrict__ Bm,
                        const float* __restrict__ bias, float* __restrict__ Cm,
                        int M, int N, int K){
    __shared__ float As[16][65];
    __shared__ float Bs[16][65];
    int bm = blockIdx.y << 6, bn = blockIdx.x << 6;
    int tid = threadIdx.x;
    int tx = tid & 15, ty = tid >> 4;
    float acc[4][4];
    #pragma unroll
    for (int i = 0; i < 4; i++)
        #pragma unroll
        for (int j = 0; j < 4; j++) acc[i][j] = 0.f;
    int arow = tid >> 2, ak0 = (tid & 3) << 2;
    for (int k0 = 0; k0 < K; k0 += 16){
        #pragma unroll
        for (int q = 0; q < 4; q++){
            int kk = ak0 + q, gm = bm + arow, gk = k0 + kk;
            As[kk][arow] = (gm < M && gk < K) ? A[(size_t)gm*K + gk] : 0.f;
        }
        {
            int kr = tid >> 4, nc0 = (tid & 15) << 2;
            #pragma unroll
            for (int q = 0; q < 4; q++){
                int n = nc0 + q, gk = k0 + kr, gn = bn + n;
                Bs[kr][n] = (gk < K && gn < N) ? Bm[(size_t)gk*N + gn] : 0.f;
            }
        }
        __syncthreads();
        #pragma unroll
        for (int kk = 0; kk < 16; kk++){
            float a[4], b[4];
            #pragma unroll
            for (int i = 0; i < 4; i++) a[i] = As[kk][ty + (i<<4)];
            #pragma unroll
            for (int j = 0; j < 4; j++) b[j] = Bs[kk][tx + (j<<4)];
            #pragma unroll
            for (int i = 0; i < 4; i++)
                #pragma unroll
                for (int j = 0; j < 4; j++) acc[i][j] += a[i]*b[j];
        }
        __syncthreads();
    }
    #pragma unroll
    for (int i = 0; i < 4; i++){
        int gm = bm + ty + (i<<4); if (gm >= M) continue;
        #pragma unroll
        for (int j = 0; j < 4; j++){
            int gn = bn + tx + (j<<4); if (gn >= N) continue;
            float v = acc[i][j] + bias[gn];
            if (RELU) v = lrelu(v);
            Cm[(size_t)gm*N + gn] = v;
        }
    }
}

// ---------------- fused LSTM step ----------------
__global__ void k_lstm(const float* __restrict__ WhhF,
                       const float* __restrict__ WhhB, int t){
    int dir = blockIdx.z;
    const float* Whh = dir ? WhhB : WhhF;
    const float* xb  = dir ? g_xbb : g_xbf;
    const float* hp  = g_hbuf[dir][t & 1];
    float* hn        = g_hbuf[dir][(t & 1) ^ 1];
    float* cc        = g_cbuf[dir];
    float* hs        = dir ? g_hsrev : g_hsf;

    int bBase = blockIdx.x << 5, jBase = blockIdx.y << 5;
    int tid = threadIdx.x, tx = tid & 15, ty = tid >> 4;

    __shared__ float shh[32][17];
    __shared__ float shw[4][16][33];

    float acc[4][4][2];
    #pragma unroll
    for (int a = 0; a < 4; a++)
        #pragma unroll
        for (int g = 0; g < 4; g++){ acc[a][g][0]=0.f; acc[a][g][1]=0.f; }

    for (int kc = 0; kc < H_; kc += 16){
        #pragma unroll
        for (int q = 0; q < 4; q++){
            int e = tid + 128*q;
            int bl = e >> 4, kk = e & 15;
            shh[bl][kk] = hp[(bBase + bl)*H_ + kc + kk];
        }
        #pragma unroll
        for (int q = 0; q < 16; q++){
            int e = tid + 128*q;
            int g = e >> 9, rem = e & 511;
            int jl = rem >> 4, kk = rem & 15;
            shw[g][kk][jl] = Whh[(size_t)(g*H_ + jBase + jl)*H_ + kc + kk];
        }
        __syncthreads();
        #pragma unroll
        for (int kk = 0; kk < 16; kk++){
            float hv[4];
            #pragma unroll
            for (int bb = 0; bb < 4; bb++) hv[bb] = shh[(ty<<2)+bb][kk];
            #pragma unroll
            for (int g = 0; g < 4; g++){
                float w0 = shw[g][kk][(tx<<1)];
                float w1 = shw[g][kk][(tx<<1)+1];
                #pragma unroll
                for (int bb = 0; bb < 4; bb++){
                    acc[bb][g][0] += hv[bb]*w0;
                    acc[bb][g][1] += hv[bb]*w1;
                }
            }
        }
        __syncthreads();
    }
    #pragma unroll
    for (int bb = 0; bb < 4; bb++){
        int b = bBase + (ty<<2) + bb;
        const float* xrow = xb + (size_t)(b*T_ + t)*G_;
        #pragma unroll
        for (int jj = 0; jj < 2; jj++){
            int j = jBase + (tx<<1) + jj;
            float gi = acc[bb][0][jj] + xrow[j];
            float gf = acc[bb][1][jj] + xrow[H_ + j];
            float gg = acc[bb][2][jj] + xrow[2*H_ + j];
            float go = acc[bb][3][jj] + xrow[3*H_ + j];
            float cold = cc[b*H_ + j];
            float cn = sigm(gf)*cold + sigm(gi)*tanhf(gg);
            float hv = sigm(go)*tanhf(cn);
            cc[b*H_ + j] = cn;
            hn[b*H_ + j] = hv;
            hs[(size_t)(b*T_ + t)*H_ + j] = hv;
        }
    }
}

// ---------------- Hs assembly ----------------
__global__ void k_hs(){
    int i = blockIdx.x*256 + threadIdx.x;
    if (i >= BT_*D_) return;
    int bt = i / D_, d = i - bt*D_;
    if (d < H_) g_Hs[i] = g_hsf[bt*H_ + d];
    else {
        int b = bt / T_;
        int rid = g_rev[bt];
        g_Hs[i] = g_hsrev[(b*T_ + rid)*H_ + d - H_];
    }
}

// ---------------- e = t1 @ s2 ----------------
__global__ void k_e(const float* __restrict__ s2){
    int warp = threadIdx.x >> 5, lane = threadIdx.x & 31;
    int row = blockIdx.x*8 + warp; if (row >= BT_) return;
    const float* h = g_t1 + (size_t)row*D_;
    float a = 0.f;
    for (int k = lane; k < D_; k += 32) a += h[k]*s2[k];
    #pragma unroll
    for (int s = 16; s; s >>= 1) a += __shfl_down_sync(0xffffffffu, a, s);
    if (!lane) g_e[row] = a;
}

// ---------------- masked pooling ----------------
__global__ void k_u(const int* __restrict__ slen){
    __shared__ float al[T_];
    __shared__ float red[256];
    int b = blockIdx.x, tid = threadIdx.x;
    int len = slen[b];
    float v = 0.f;
    if (tid < T_){ v = (tid < len) ? g_e[b*T_ + tid] : 0.f; al[tid] = v; }
    red[tid] = v; __syncthreads();
    for (int s = 128; s; s >>= 1){ if (tid < s) red[tid] += red[tid+s]; __syncthreads(); }
    float denom = red[0] + 1e-9f;
    __syncthreads();
    if (tid < T_) al[tid] = al[tid] / denom;
    __syncthreads();
    for (int d = tid; d < D_; d += 256){
        float acc = 0.f;
        for (int t = 0; t < T_; t++) acc += al[t]*g_Hs[(size_t)(b*T_ + t)*D_ + d];
        g_U[b*D_ + d] = acc;
    }
}

// ---------------- gather E / Cu rows ----------------
__global__ void k_gatherR(const int* __restrict__ emo, const int* __restrict__ cau){
    int i = blockIdx.x*256 + threadIdx.x;
    if (i < NE_*D_){ int r = i / D_, d = i - r*D_; g_E[i]  = g_R[(size_t)emo[r]*D_ + d]; }
    if (i < NC_*D_){ int r = i / D_, d = i - r*D_; g_Cu[i] = g_R[(size_t)cau[r]*D_ + d]; }
}

// ---------------- per-chunk cross attention ----------------
__global__ void k_chunk(){
    __shared__ float Esh[D_];
    __shared__ float red[256];
    __shared__ float scs[4];
    int blk = blockIdx.x, tid = threadIdx.x;
    int e = blk >> 6, k = blk & 63;
    const float* Er = g_E + (size_t)e*D_;
    for (int d = tid; d < D_; d += 256) Esh[d] = Er[d];
    __syncthreads();
    float dots[4];
    for (int c = 0; c < 4; c++){
        const float* Cr = g_Cu + (size_t)(k*4 + c)*D_;
        float a = 0.f;
        for (int d = tid; d < D_; d += 256) a += Esh[d]*Cr[d];
        red[tid] = a; __syncthreads();
        for (int s = 128; s; s >>= 1){ if (tid < s) red[tid] += red[tid+s]; __syncthreads(); }
        dots[c] = red[0]; __syncthreads();
    }
    if (tid == 0){
        float m = fmaxf(fmaxf(dots[0],dots[1]), fmaxf(dots[2],dots[3]));
        float ex[4], s = 0.f;
        #pragma unroll
        for (int c = 0; c < 4; c++){ ex[c] = expf(dots[c]-m); s += ex[c]; }
        #pragma unroll
        for (int c = 0; c < 4; c++) scs[c] = ex[c]/s;
    }
    __syncthreads();
    const float* C0 = g_Cu + (size_t)(k*4+0)*D_;
    const float* C1 = g_Cu + (size_t)(k*4+1)*D_;
    const float* C2 = g_Cu + (size_t)(k*4+2)*D_;
    const float* C3 = g_Cu + (size_t)(k*4+3)*D_;
    float s0 = scs[0], s1 = scs[1], s2 = scs[2], s3 = scs[3];
    for (int d = tid; d < D_; d += 256)
        g_cE[(size_t)blk*D_ + d] = s0*C0[d] + s1*C1[d] + s2*C2[d] + s3*C3[d];
}

// ---------------- EY = E⊙Y, nrm2 ----------------
__global__ void k_EY(){
    __shared__ float red[256];
    int row = blockIdx.x, tid = threadIdx.x;
    int e = row >> 6;
    const float* Er = g_E + (size_t)e*D_;
    const float* Y  = g_cE + (size_t)row*D_;
    float a = 0.f;
    for (int d = tid; d < D_; d += 256){
        float ev = Er[d], yv = Y[d];
        float df = ev - yv; a += df*df;
        g_EY[(size_t)row*D_ + d] = ev*yv;
    }
    red[tid] = a; __syncthreads();
    for (int s = 128; s; s >>= 1){ if (tid < s) red[tid] += red[tid+s]; __syncthreads(); }
    if (tid == 0) g_n2[row] = sqrtf(red[0]);
}

// ---------------- EC = E⊙Cu, nrm3 ----------------
__global__ void k_EC(){
    __shared__ float red[256];
    int row = blockIdx.x, tid = threadIdx.x;
    int e = row >> 8, c = row & 255;
    const float* Er = g_E + (size_t)e*D_;
    const float* Cr = g_Cu + (size_t)c*D_;
    float a = 0.f;
    for (int d = tid; d < D_; d += 256){
        float ev = Er[d], cv = Cr[d];
        float df = ev - cv; a += df*df;
        g_EC[(size_t)row*D_ + d] = ev*cv;
    }
    red[tid] = a; __syncthreads();
    for (int s = 128; s; s >>= 1){ if (tid < s) red[tid] += red[tid+s]; __syncthreads(); }
    if (tid == 0) g_n3[row] = sqrtf(red[0]);
}

// ---------------- epilogue adds ----------------
__global__ void k_add2(const float* __restrict__ W2W){
    int idx = blockIdx.x*256 + threadIdx.x;
    if (idx >= NE_*NK_*D_) return;
    int row = idx / D_, n = idx - row*D_;
    int e = row >> 6;
    g_z2[idx] += g_EW2a[e*D_ + n] + g_n2[row]*W2W[(size_t)1536*D_ + n];
}

__global__ void k_add3(const float* __restrict__ W3W){
    int idx = blockIdx.x*256 + threadIdx.x;
    if (idx >= NE_*NC_*D_) return;
    int row = idx / D_, n = idx - row*D_;
    int e = row >> 8, c = row & 255;
    g_z3[idx] += g_EW3a[e*D_ + n] + g_CW3b[c*D_ + n] + g_disW3[c*D_ + n]
               + g_n3[row]*W3W[(size_t)1536*D_ + n]
               + g_of[(e<<6) + (c>>2)]*W3W[(size_t)2355*D_ + n];
}

// ---------------- BatchNorm (biased var) + lrelu ----------------
__global__ void k_bn(float* __restrict__ z, int rows){
    int e = blockIdx.x;
    int d = blockIdx.y*256 + threadIdx.x;
    size_t base = (size_t)e*rows*D_ + d;
    float s = 0.f;
    for (int r = 0; r < rows; r++) s += z[base + (size_t)r*D_];
    float m = s / (float)rows;
    float v = 0.f;
    for (int r = 0; r < rows; r++){ float t = z[base + (size_t)r*D_] - m; v += t*t; }
    v /= (float)rows;
    float inv = 1.f/sqrtf(v + 1e-5f);
    for (int r = 0; r < rows; r++){
        float t = (z[base + (size_t)r*D_] - m)*inv;
        z[base + (size_t)r*D_] = lrelu(t);
    }
}

// ---------------- 2-class head ----------------
__global__ void k_head(const float* __restrict__ Hx, const float* __restrict__ W,
                       const float* __restrict__ b2, float* __restrict__ out,
                       float* __restrict__ of, int rows){
    int warp = threadIdx.x >> 5, lane = threadIdx.x & 31;
    int row = blockIdx.x*8 + warp; if (row >= rows) return;
    const float* h = Hx + (size_t)row*D_;
    const float2* Wv = (const float2*)W;
    float a0 = 0.f, a1 = 0.f;
    for (int k = lane; k < D_; k += 32){
        float hv = h[k]; float2 w = Wv[k];
        a0 += hv*w.x; a1 += hv*w.y;
    }
    #pragma unroll
    for (int s = 16; s; s >>= 1){
        a0 += __shfl_down_sync(0xffffffffu, a0, s);
        a1 += __shfl_down_sync(0xffffffffu, a1, s);
    }
    if (!lane){
        float l0 = a0 + b2[0], l1 = a1 + b2[1];
        float m = fmaxf(l0, l1);
        float lse = m + logf(expf(l0-m) + expf(l1-m));
        out[row*2]   = l0 - lse;
        out[row*2+1] = l1 - lse;
        if (of) of[row] = (l1 > l0) ? 1.f : 0.f;
    }
}

// ---------------- L indicator ----------------
__global__ void k_L(const int* __restrict__ lab, float* __restrict__ out){
    int e = blockIdx.x, c = threadIdx.x;
    int a = lab[e*3], b = lab[e*3+1], d = lab[e*3+2];
    out[e*NC_ + c] = (a == c || b == c || d == c) ? 1.f : 0.f;
}

// ---------------- orchestration ----------------
extern "C" void kernel_launch(void* const* d_in, const int* in_sizes, int n_in,
                              void* d_out, int out_size){
    const float* word = (const float*)d_in[0];
    const float* pos  = (const float*)d_in[1];
    const float* dis  = (const float*)d_in[2];
    const float* WihF = (const float*)d_in[3];
    const float* WhhF = (const float*)d_in[4];
    const float* bihF = (const float*)d_in[5];
    const float* bhhF = (const float*)d_in[6];
    const float* WihB = (const float*)d_in[7];
    const float* WhhB = (const float*)d_in[8];
    const float* bihB = (const float*)d_in[9];
    const float* bhhB = (const float*)d_in[10];
    const float* s1W  = (const float*)d_in[11];
    const float* s1b  = (const float*)d_in[12];
    const float* s2W  = (const float*)d_in[13];
    const float* repW = (const float*)d_in[14];
    const float* repb = (const float*)d_in[15];
    const float* W2W  = (const float*)d_in[16];
    const float* W2b  = (const float*)d_in[17];
    const float* WoW  = (const float*)d_in[18];
    const float* Wob  = (const float*)d_in[19];
    const float* W3W  = (const float*)d_in[20];
    const float* W3b  = (const float*)d_in[21];
    const float* clsW = (const float*)d_in[22];
    const float* clsb = (const float*)d_in[23];
    const int* slen   = (const int*)d_in[24];
    const int* emo    = (const int*)d_in[25];
    const int* cau    = (const int*)d_in[26];
    const int* lab    = (const int*)d_in[27];
    float* out = (float*)d_out;

    void *p_xrev,*p_xbf,*p_xbb,*p_Hs,*p_t1,*p_U,*p_R,*p_E,*p_Cu,*p_cE,*p_EY,*p_EC;
    void *p_z2,*p_z3,*p_EW2a,*p_EW3a,*p_CW3b,*p_disW3,*p_bf,*p_bb,*p_zero,*p_of;
    void *p_WFT,*p_WBT;
    cudaGetSymbolAddress(&p_xrev, g_xrev);
    cudaGetSymbolAddress(&p_xbf,  g_xbf);
    cudaGetSymbolAddress(&p_xbb,  g_xbb);
    cudaGetSymbolAddress(&p_Hs,   g_Hs);
    cudaGetSymbolAddress(&p_t1,   g_t1);
    cudaGetSymbolAddress(&p_U,    g_U);
    cudaGetSymbolAddress(&p_R,    g_R);
    cudaGetSymbolAddress(&p_E,    g_E);
    cudaGetSymbolAddress(&p_Cu,   g_Cu);
    cudaGetSymbolAddress(&p_cE,   g_cE);
    cudaGetSymbolAddress(&p_EY,   g_EY);
    cudaGetSymbolAddress(&p_EC,   g_EC);
    cudaGetSymbolAddress(&p_z2,   g_z2);
    cudaGetSymbolAddress(&p_z3,   g_z3);
    cudaGetSymbolAddress(&p_EW2a, g_EW2a);
    cudaGetSymbolAddress(&p_EW3a, g_EW3a);
    cudaGetSymbolAddress(&p_CW3b, g_CW3b);
    cudaGetSymbolAddress(&p_disW3,g_disW3);
    cudaGetSymbolAddress(&p_bf,   g_bf);
    cudaGetSymbolAddress(&p_bb,   g_bb);
    cudaGetSymbolAddress(&p_zero, g_zero);
    cudaGetSymbolAddress(&p_of,   g_of);
    cudaGetSymbolAddress(&p_WFT,  g_WihFT);
    cudaGetSymbolAddress(&p_WBT,  g_WihBT);

    // prep
    k_prep<<<B_, T_>>>(slen);
    k_gather<<<(BT_*192 + 255)/256, 256>>>((const float4*)word);
    k_bias<<<(G_ + 255)/256, 256>>>(bihF, bhhF, bihB, bhhB);
    k_zero<<<(2*2*B_*H_ + 255)/256, 256>>>();
    k_transW<<<dim3(D_/32, G_/32, 2), dim3(32,8)>>>(WihF, WihB);

    // input projections — fp32 (upstream of the alpha amplifier)
    sgemmF<false,false><<<dim3(G_/128, BT_/128), 256>>>(word, (const float*)p_WFT,
        (const float*)p_bf, (float*)p_xbf, BT_, G_, D_);
    sgemmF<false,false><<<dim3(G_/128, BT_/128), 256>>>((const float*)p_xrev, (const float*)p_WBT,
        (const float*)p_bb, (float*)p_xbb, BT_, G_, D_);

    // recurrence
    for (int t = 0; t < T_; t++)
        k_lstm<<<dim3(B_/32, H_/32, 2), 128>>>(WhhF, WhhB, t);

    k_hs<<<(BT_*D_ + 255)/256, 256>>>();

    // attention pooling — fp32 (feeds e -> alpha, catastrophic cancellation)
    sgemmF<true,false><<<dim3(D_/128, BT_/128), 256>>>((const float*)p_Hs, s1W, s1b,
        (float*)p_t1, BT_, D_, D_);
    k_e<<<BT_/8, 256>>>(s2W);
    k_u<<<B_, 256>>>(slen);

    // shared representation — tf32 (downstream of alpha, bounded operators)
    tgemm<true,false><<<dim3(D_/128, B_/128), 256>>>((const float*)p_U, repW, repb,
        (float*)p_R, B_, D_, D_);
    k_gatherR<<<(NC_*D_ + 255)/256, 256>>>(emo, cau);

    // phase 2
    k_chunk<<<NE_*NK_, 256>>>();
    k_EY<<<NE_*NK_, 256>>>();
    sgemm64<false,false><<<dim3(D_/64, (NE_*NK_)/64), 256>>>(pos, W2W + (size_t)2305*D_,
        W2b, (float*)p_z2, NE_*NK_, D_, POS_);
    tgemm<false,true><<<dim3(D_/128, (NE_*NK_)/128), 256>>>((const float*)p_cE,
        W2W + (size_t)768*D_, (const float*)p_zero, (float*)p_z2, NE_*NK_, D_, D_);
    tgemm<false,true><<<dim3(D_/128, (NE_*NK_)/128), 256>>>((const float*)p_EY,
        W2W + (size_t)1537*D_, (const float*)p_zero, (float*)p_z2, NE_*NK_, D_, D_);
    tgemm<false,false><<<dim3(D_/128, NE_/128), 256>>>((const float*)p_E, W2W,
        (const float*)p_zero, (float*)p_EW2a, NE_, D_, D_);
    k_add2<<<(NE_*NK_*D_ + 255)/256, 256>>>(W2W);
    k_bn<<<dim3(NE_, 3), 256>>>((float*)p_z2, NK_);
    k_head<<<(NE_*NK_)/8, 256>>>((const float*)p_z2, WoW, Wob, out, (float*)p_of, NE_*NK_);

    // phase 3
    k_EC<<<NE_*NC_, 256>>>();
    tgemm<false,false><<<dim3(D_/128, (NE_*NC_)/128), 256>>>((const float*)p_EC,
        W3W + (size_t)1537*D_, W3b, (float*)p_z3, NE_*NC_, D_, D_);
    tgemm<false,false><<<dim3(D_/128, NE_/128), 256>>>((const float*)p_E, W3W,
        (const float*)p_zero, (float*)p_EW3a, NE_, D_, D_);
    tgemm<false,false><<<dim3(D_/128, NC_/128), 256>>>((const float*)p_Cu,
        W3W + (size_t)768*D_, (const float*)p_zero, (float*)p_CW3b, NC_, D_, D_);
    sgemm64<false,false><<<dim3(D_/64, (NC_+63)/64), 256>>>(dis, W3W + (size_t)2305*D_,
        (const float*)p_zero, (float*)p_disW3, NC_, D_, POS_);
    k_add3<<<(NE_*NC_*D_ + 255)/256, 256>>>(W3W);
    k_bn<<<dim3(NE_, 3), 256>>>((float*)p_z3, NC_);
    k_head<<<(NE_*NC_)/8, 256>>>((const float*)p_z3, clsW, clsb,
        out + NE_*NK_*2, nullptr, NE_*NC_);

    // L indicator
    k_L<<<NE_, NC_>>>(lab, out + NE_*NK_*2 + NE_*NC_*2);
}

// round 12
// speedup vs baseline: 1.8423x; 1.0130x over previous
#include <cuda_runtime.h>
#include <cuda_bf16.h>
#include <math.h>
#include <stdint.h>
#include <stddef.h>

// ---------------- problem dims ----------------
#define B_   256
#define T_   96
#define D_   768
#define H_   384
#define G_   1536          // 4*H
#define BT_  (B_*T_)       // 24576
#define NE_  128
#define NC_  256
#define NK_  64
#define POS_ 50
#define AMAX_ ((size_t)NE_*NC_*D_)
#define BMAX_ ((size_t)D_*D_)

// ---------------- scratch ----------------
__device__ float g_xrev[BT_*D_];
__device__ float g_xbf[BT_*G_];
__device__ float g_xbb[BT_*G_];
__device__ float g_hsf[BT_*H_];
__device__ float g_hsrev[BT_*H_];
__device__ float g_hbuf[2][2][B_*H_];
__device__ float g_cbuf[2][B_*H_];
__device__ float g_Hs[BT_*D_];
__device__ float g_t1[BT_*D_];
__device__ float g_e[BT_];
__device__ float g_U[B_*D_];
__device__ float g_R[NC_*D_];
__device__ float g_E[NE_*D_];
__device__ float g_Cu[NC_*D_];
__device__ float g_cE[NE_*NK_*D_];
__device__ float g_n2[NE_*NK_];
__device__ float g_n3[NE_*NC_];
__device__ float g_z2[NE_*NK_*D_];
__device__ float g_z3[NE_*NC_*D_];
__device__ float g_EW2a[NE_*D_];
__device__ float g_EW3a[NE_*D_];
__device__ float g_CW3b[NC_*D_];
__device__ float g_disW3[NC_*D_];
__device__ float g_of[NE_*NK_];
__device__ float g_bf[G_];
__device__ float g_bb[G_];
__device__ float g_zero[G_];
__device__ int   g_rev[BT_];
// dedicated Wih transposes [D, G]
__device__ float g_WihFT[D_*G_];
__device__ float g_WihBT[D_*G_];
// transposed weight blocks [N, K=768]
__device__ float g_repWT[D_*D_];
__device__ float g_W2aT [D_*D_];
__device__ float g_W2yT [D_*D_];
__device__ float g_W2eyT[D_*D_];
__device__ float g_W3aT [D_*D_];
__device__ float g_W3bT [D_*D_];
__device__ float g_W3cT [D_*D_];
// bf16 split planes (sequential reuse)
__device__ __nv_bfloat16 g_A1[AMAX_];
__device__ __nv_bfloat16 g_A2[AMAX_];
__device__ __nv_bfloat16 g_A3[AMAX_];
__device__ __nv_bfloat16 g_B1[BMAX_];
__device__ __nv_bfloat16 g_B2[BMAX_];
__device__ __nv_bfloat16 g_B3[BMAX_];

__device__ __forceinline__ float lrelu(float x){ return x >= 0.f ? x : 0.01f*x; }
__device__ __forceinline__ float sigm(float x){ return 1.f/(1.f+expf(-x)); }

__device__ __forceinline__ void split3(float a, __nv_bfloat16& x1,
                                       __nv_bfloat16& x2, __nv_bfloat16& x3){
    x1 = __float2bfloat16(a);
    float r = a - __bfloat162float(x1);
    x2 = __float2bfloat16(r);
    float r2 = r - __bfloat162float(x2);
    x3 = __float2bfloat16(r2);
}

#define MMAB(C, A0,A1,A2,A3, B0,B1) \
    asm volatile("mma.sync.aligned.m16n8k16.row.col.f32.bf16.bf16.f32 " \
        "{%0,%1,%2,%3}, {%4,%5,%6,%7}, {%8,%9}, {%0,%1,%2,%3};" \
        : "+f"((C)[0]),"+f"((C)[1]),"+f"((C)[2]),"+f"((C)[3]) \
        : "r"(A0),"r"(A1),"r"(A2),"r"(A3),"r"(B0),"r"(B1))

// ---------------- fp32 SGEMM (UPSTREAM of the alpha amplifier) ----------------
template<bool RELU, bool ACC>
__global__ __launch_bounds__(256, 2)
void sgemmF(const float* __restrict__ A, const float* __restrict__ Bm,
            const float* __restrict__ bias, float* __restrict__ Cm,
            int M, int N, int K){
    __shared__ float As[2][16][136];
    __shared__ float Bs[2][16][128];
    const int tid = threadIdx.x;
    const int bm = blockIdx.y << 7, bn = blockIdx.x << 7;
    const int tx = tid & 15, ty = tid >> 4;

    const int am0 = tid >> 2, ak0 = (tid & 3) << 2;
    const int am1 = am0 + 64;
    const int bk0 = tid >> 5, bn0 = (tid & 31) << 2;
    const int bk1 = bk0 + 8;

    float4 ra0, ra1, rb0, rb1;
    float acc[8][8];
    #pragma unroll
    for (int i = 0; i < 8; i++)
        #pragma unroll
        for (int j = 0; j < 8; j++) acc[i][j] = 0.f;

    auto loadRegs = [&](int k0){
        ra0 = *(const float4*)(A  + (size_t)(bm+am0)*K + k0 + ak0);
        ra1 = *(const float4*)(A  + (size_t)(bm+am1)*K + k0 + ak0);
        rb0 = *(const float4*)(Bm + (size_t)(k0+bk0)*N + bn + bn0);
        rb1 = *(const float4*)(Bm + (size_t)(k0+bk1)*N + bn + bn0);
    };
    auto storeSmem = [&](int buf){
        As[buf][ak0+0][am0] = ra0.x; As[buf][ak0+1][am0] = ra0.y;
        As[buf][ak0+2][am0] = ra0.z; As[buf][ak0+3][am0] = ra0.w;
        As[buf][ak0+0][am1] = ra1.x; As[buf][ak0+1][am1] = ra1.y;
        As[buf][ak0+2][am1] = ra1.z; As[buf][ak0+3][am1] = ra1.w;
        *(float4*)&Bs[buf][bk0][bn0] = rb0;
        *(float4*)&Bs[buf][bk1][bn0] = rb1;
    };

    loadRegs(0); storeSmem(0); __syncthreads();
    const int ntk = K >> 4;
    for (int kt = 0; kt < ntk; kt++){
        if (kt + 1 < ntk) loadRegs((kt+1) << 4);
        const int buf = kt & 1;
        #pragma unroll
        for (int kk = 0; kk < 16; kk++){
            float4 a0 = *(const float4*)&As[buf][kk][ty<<2];
            float4 a1 = *(const float4*)&As[buf][kk][(ty<<2)+64];
            float4 b0 = *(const float4*)&Bs[buf][kk][tx<<2];
            float4 b1 = *(const float4*)&Bs[buf][kk][(tx<<2)+64];
            float av[8] = {a0.x,a0.y,a0.z,a0.w,a1.x,a1.y,a1.z,a1.w};
            float bv[8] = {b0.x,b0.y,b0.z,b0.w,b1.x,b1.y,b1.z,b1.w};
            #pragma unroll
            for (int i = 0; i < 8; i++)
                #pragma unroll
                for (int j = 0; j < 8; j++) acc[i][j] += av[i]*bv[j];
        }
        if (kt + 1 < ntk) storeSmem(buf ^ 1);
        __syncthreads();
    }
    #pragma unroll
    for (int i = 0; i < 8; i++){
        int m = bm + (ty<<2) + (i&3) + ((i>>2)<<6);
        size_t base = (size_t)m*N;
        #pragma unroll
        for (int jg = 0; jg < 2; jg++){
            int n0 = bn + (tx<<2) + (jg<<6);
            float4 v;
            if (ACC) v = *(const float4*)&Cm[base + n0];
            else     v = *(const float4*)&bias[n0];
            v.x += acc[i][jg*4+0]; v.y += acc[i][jg*4+1];
            v.z += acc[i][jg*4+2]; v.w += acc[i][jg*4+3];
            if (RELU){ v.x = lrelu(v.x); v.y = lrelu(v.y); v.z = lrelu(v.z); v.w = lrelu(v.w); }
            *(float4*)&Cm[base + n0] = v;
        }
    }
}

// ---------------- fp32 -> 3x bf16 split ----------------
__global__ void k_split(const float* __restrict__ src,
                        __nv_bfloat16* __restrict__ p1,
                        __nv_bfloat16* __restrict__ p2,
                        __nv_bfloat16* __restrict__ p3, int n){
    int i = blockIdx.x*256 + threadIdx.x;
    if (i >= n) return;
    __nv_bfloat16 h1, h2, h3;
    split3(src[i], h1, h2, h3);
    p1[i] = h1; p2[i] = h2; p3[i] = h3;
}

// ============ bf16x6 GEMM (DOWNSTREAM only): C = A[M,K] @ Bt[N,K]^T ==========
#define BGP_  10240
#define BGS_  67584

template<bool RELU, bool ACC>
__global__ void __launch_bounds__(256)
bgemm(const __nv_bfloat16* __restrict__ A1, const __nv_bfloat16* __restrict__ A2,
      const __nv_bfloat16* __restrict__ A3, const __nv_bfloat16* __restrict__ Bt1,
      const __nv_bfloat16* __restrict__ Bt2, const __nv_bfloat16* __restrict__ Bt3,
      const float* __restrict__ bias, float* __restrict__ Cm,
      int M, int N, int K){
    extern __shared__ char sm[];
    const int tid = threadIdx.x, warp = tid >> 5, lane = tid & 31;
    const int gid = lane >> 2, tig = lane & 3;
    const int bm = blockIdx.y << 7, bn = blockIdx.x << 7;
    const int wm = (warp & 1) << 6, wn = (warp >> 1) << 5;

    const __nv_bfloat16* Ap[3] = {A1, A2, A3};
    const __nv_bfloat16* Bp[3] = {Bt1, Bt2, Bt3};

    float acc[4][4][4];
    #pragma unroll
    for (int i = 0; i < 4; i++)
        #pragma unroll
        for (int j = 0; j < 4; j++)
            #pragma unroll
            for (int q = 0; q < 4; q++) acc[i][j][q] = 0.f;

    for (int k0 = 0; k0 < K; k0 += 32){
        __syncthreads();
        for (int idx = tid; idx < 128*16; idx += 256){
            int r = idx >> 4, kq = idx & 15;
            size_t ga = (((size_t)(bm + r)*K + k0) >> 1) + kq;
            size_t gb = (((size_t)(bn + r)*K + k0) >> 1) + kq;
            uint32_t so = (uint32_t)(r*80 + kq*4);
            #pragma unroll
            for (int p = 0; p < 3; p++){
                *(uint32_t*)(sm + p*BGP_ + so)           = ((const uint32_t*)Ap[p])[ga];
                *(uint32_t*)(sm + 3*BGP_ + p*BGP_ + so)  = ((const uint32_t*)Bp[p])[gb];
            }
        }
        __syncthreads();
        #pragma unroll
        for (int s = 0; s < 2; s++){
            uint32_t bfr[3][4][2];
            #pragma unroll
            for (int p = 0; p < 3; p++)
                #pragma unroll
                for (int nt = 0; nt < 4; nt++){
                    int n = wn + (nt << 3) + gid;
                    const char* bb = sm + 3*BGP_ + p*BGP_ + n*80 + s*32 + tig*4;
                    bfr[p][nt][0] = *(const uint32_t*)bb;
                    bfr[p][nt][1] = *(const uint32_t*)(bb + 16);
                }
            #pragma unroll
            for (int pa = 0; pa < 3; pa++){
                #pragma unroll
                for (int mt = 0; mt < 4; mt++){
                    int r = wm + (mt << 4) + gid;
                    const char* ab = sm + pa*BGP_ + r*80 + s*32 + tig*4;
                    uint32_t a0 = *(const uint32_t*)ab;
                    uint32_t a1 = *(const uint32_t*)(ab + 640);
                    uint32_t a2 = *(const uint32_t*)(ab + 16);
                    uint32_t a3 = *(const uint32_t*)(ab + 656);
                    if (pa == 0){
                        #pragma unroll
                        for (int nt = 0; nt < 4; nt++){
                            MMAB(acc[mt][nt], a0,a1,a2,a3, bfr[0][nt][0], bfr[0][nt][1]);
                            MMAB(acc[mt][nt], a0,a1,a2,a3, bfr[1][nt][0], bfr[1][nt][1]);
                            MMAB(acc[mt][nt], a0,a1,a2,a3, bfr[2][nt][0], bfr[2][nt][1]);
                        }
                    } else if (pa == 1){
                        #pragma unroll
                        for (int nt = 0; nt < 4; nt++){
                            MMAB(acc[mt][nt], a0,a1,a2,a3, bfr[0][nt][0], bfr[0][nt][1]);
                            MMAB(acc[mt][nt], a0,a1,a2,a3, bfr[1][nt][0], bfr[1][nt][1]);
                        }
                    } else {
                        #pragma unroll
                        for (int nt = 0; nt < 4; nt++)
                            MMAB(acc[mt][nt], a0,a1,a2,a3, bfr[0][nt][0], bfr[0][nt][1]);
                    }
                }
            }
        }
    }
    __syncthreads();
    float* fs = (float*)sm;
    #pragma unroll
    for (int mt = 0; mt < 4; mt++){
        int r0 = wm + (mt << 4) + gid;
        #pragma unroll
        for (int nt = 0; nt < 4; nt++){
            int c = wn + (nt << 3) + (tig << 1);
            fs[r0*132 + c]       = acc[mt][nt][0];
            fs[r0*132 + c + 1]   = acc[mt][nt][1];
            fs[(r0+8)*132 + c]   = acc[mt][nt][2];
            fs[(r0+8)*132 + c+1] = acc[mt][nt][3];
        }
    }
    __syncthreads();
    for (int i = tid; i < 128*128; i += 256){
        int r = i >> 7, c = i & 127;
        float v = fs[r*132 + c];
        float* dst = Cm + (size_t)(bm + r)*N + bn + c;
        float base = ACC ? *dst : bias[bn + c];
        v += base;
        if (RELU) v = lrelu(v);
        *dst = v;
    }
}

// ---------------- prep ----------------
__global__ void k_prep(const int* __restrict__ slen){
    int b = blockIdx.x, t = threadIdx.x;
    int len = slen[b];
    g_rev[b*T_ + t] = (t < len) ? (len - 1 - t) : t;
}

__global__ void k_gather(const float4* __restrict__ word){
    int i = blockIdx.x*256 + threadIdx.x;
    if (i >= BT_*192) return;
    int bt = i / 192, q = i - bt*192;
    int b  = bt / T_;
    int rid = g_rev[bt];
    ((float4*)g_xrev)[i] = word[(b*T_ + rid)*192 + q];
}

__global__ void k_bias(const float* bihf, const float* bhhf,
                       const float* bihb, const float* bhhb){
    int i = blockIdx.x*256 + threadIdx.x;
    if (i < G_){ g_bf[i] = bihf[i] + bhhf[i]; g_bb[i] = bihb[i] + bhhb[i]; }
}

__global__ void k_zero(){
    int i = blockIdx.x*256 + threadIdx.x;
    if (i < 2*2*B_*H_) (&g_hbuf[0][0][0])[i] = 0.f;
    if (i < 2*B_*H_)   (&g_cbuf[0][0])[i]    = 0.f;
}

// 768x768 block transpose
__global__ void k_transT(const float* __restrict__ src, float* __restrict__ dst){
    __shared__ float t[32][33];
    int r0 = blockIdx.y*32, c0 = blockIdx.x*32;
    int tx = threadIdx.x, ty = threadIdx.y;
    #pragma unroll
    for (int q = 0; q < 32; q += 8)
        t[ty+q][tx] = src[(size_t)(r0+ty+q)*D_ + c0+tx];
    __syncthreads();
    #pragma unroll
    for (int q = 0; q < 32; q += 8)
        dst[(size_t)(c0+ty+q)*D_ + r0+tx] = t[tx][ty+q];
}

// Wih [G,D] -> [D,G] transpose (grid: D/32 x G/32)
__global__ void k_transW2(const float* __restrict__ src, float* __restrict__ dst){
    __shared__ float t[32][33];
    int k0 = blockIdx.x*32, n0 = blockIdx.y*32;
    int tx = threadIdx.x, ty = threadIdx.y;
    #pragma unroll
    for (int q = 0; q < 32; q += 8)
        t[ty+q][tx] = src[(size_t)(n0+ty+q)*D_ + k0+tx];
    __syncthreads();
    #pragma unroll
    for (int q = 0; q < 32; q += 8)
        dst[(size_t)(k0+ty+q)*G_ + n0+tx] = t[tx][ty+q];
}

// ---------------- small-K SGEMM (guards), 64x64 ----------------
template<bool TB, bool RELU>
__global__ void sgemm64(const float* __restrict__ A, const float* __restrict__ Bm,
                        const float* __restrict__ bias, float* __restrict__ Cm,
                        int M, int N, int K){
    __shared__ float As[16][65];
    __shared__ float Bs[16][65];
    int bm = blockIdx.y << 6, bn = blockIdx.x << 6;
    int tid = threadIdx.x;
    int tx = tid & 15, ty = tid >> 4;
    float acc[4][4];
    #pragma unroll
    for (int i = 0; i < 4; i++)
        #pragma unroll
        for (int j = 0; j < 4; j++) acc[i][j] = 0.f;
    int arow = tid >> 2, ak0 = (tid & 3) << 2;
    for (int k0 = 0; k0 < K; k0 += 16){
        #pragma unroll
        for (int q = 0; q < 4; q++){
            int kk = ak0 + q, gm = bm + arow, gk = k0 + kk;
            As[kk][arow] = (gm < M && gk < K) ? A[(size_t)gm*K + gk] : 0.f;
        }
        {
            int kr = tid >> 4, nc0 = (tid & 15) << 2;
            #pragma unroll
            for (int q = 0; q < 4; q++){
                int n = nc0 + q, gk = k0 + kr, gn = bn + n;
                Bs[kr][n] = (gk < K && gn < N) ? Bm[(size_t)gk*N + gn] : 0.f;
            }
        }
        __syncthreads();
        #pragma unroll
        for (int kk = 0; kk < 16; kk++){
            float a[4], b[4];
            #pragma unroll
            for (int i = 0; i < 4; i++) a[i] = As[kk][ty + (i<<4)];
            #pragma unroll
            for (int j = 0; j < 4; j++) b[j] = Bs[kk][tx + (j<<4)];
            #pragma unroll
            for (int i = 0; i < 4; i++)
                #pragma unroll
                for (int j = 0; j < 4; j++) acc[i][j] += a[i]*b[j];
        }
        __syncthreads();
    }
    #pragma unroll
    for (int i = 0; i < 4; i++){
        int gm = bm + ty + (i<<4); if (gm >= M) continue;
        #pragma unroll
        for (int j = 0; j < 4; j++){
            int gn = bn + tx + (j<<4); if (gn >= N) continue;
            float v = acc[i][j] + bias[gn];
            if (RELU) v = lrelu(v);
            Cm[(size_t)gm*N + gn] = v;
        }
    }
}

// ---------------- fused LSTM step ----------------
__global__ void k_lstm(const float* __restrict__ WhhF,
                       const float* __restrict__ WhhB, int t){
    int dir = blockIdx.z;
    const float* Whh = dir ? WhhB : WhhF;
    const float* xb  = dir ? g_xbb : g_xbf;
    const float* hp  = g_hbuf[dir][t & 1];
    float* hn        = g_hbuf[dir][(t & 1) ^ 1];
    float* cc        = g_cbuf[dir];
    float* hs        = dir ? g_hsrev : g_hsf;

    int bBase = blockIdx.x << 5, jBase = blockIdx.y << 5;
    int tid = threadIdx.x, tx = tid & 15, ty = tid >> 4;

    __shared__ float shh[32][17];
    __shared__ float shw[4][16][33];

    float acc[4][4][2];
    #pragma unroll
    for (int a = 0; a < 4; a++)
        #pragma unroll
        for (int g = 0; g < 4; g++){ acc[a][g][0]=0.f; acc[a][g][1]=0.f; }

    for (int kc = 0; kc < H_; kc += 16){
        #pragma unroll
        for (int q = 0; q < 4; q++){
            int e = tid + 128*q;
            int bl = e >> 4, kk = e & 15;
            shh[bl][kk] = hp[(bBase + bl)*H_ + kc + kk];
        }
        #pragma unroll
        for (int q = 0; q < 16; q++){
            int e = tid + 128*q;
            int g = e >> 9, rem = e & 511;
            int jl = rem >> 4, kk = rem & 15;
            shw[g][kk][jl] = Whh[(size_t)(g*H_ + jBase + jl)*H_ + kc + kk];
        }
        __syncthreads();
        #pragma unroll
        for (int kk = 0; kk < 16; kk++){
            float hv[4];
            #pragma unroll
            for (int bb = 0; bb < 4; bb++) hv[bb] = shh[(ty<<2)+bb][kk];
            #pragma unroll
            for (int g = 0; g < 4; g++){
                float w0 = shw[g][kk][(tx<<1)];
                float w1 = shw[g][kk][(tx<<1)+1];
                #pragma unroll
                for (int bb = 0; bb < 4; bb++){
                    acc[bb][g][0] += hv[bb]*w0;
                    acc[bb][g][1] += hv[bb]*w1;
                }
            }
        }
        __syncthreads();
    }
    #pragma unroll
    for (int bb = 0; bb < 4; bb++){
        int b = bBase + (ty<<2) + bb;
        const float* xrow = xb + (size_t)(b*T_ + t)*G_;
        #pragma unroll
        for (int jj = 0; jj < 2; jj++){
            int j = jBase + (tx<<1) + jj;
            float gi = acc[bb][0][jj] + xrow[j];
            float gf = acc[bb][1][jj] + xrow[H_ + j];
            float gg = acc[bb][2][jj] + xrow[2*H_ + j];
            float go = acc[bb][3][jj] + xrow[3*H_ + j];
            float cold = cc[b*H_ + j];
            float cn = sigm(gf)*cold + sigm(gi)*tanhf(gg);
            float hv = sigm(go)*tanhf(cn);
            cc[b*H_ + j] = cn;
            hn[b*H_ + j] = hv;
            hs[(size_t)(b*T_ + t)*H_ + j] = hv;
        }
    }
}

// ---------------- Hs assembly ----------------
__global__ void k_hs(){
    int i = blockIdx.x*256 + threadIdx.x;
    if (i >= BT_*D_) return;
    int bt = i / D_, d = i - bt*D_;
    if (d < H_) g_Hs[i] = g_hsf[bt*H_ + d];
    else {
        int b = bt / T_;
        int rid = g_rev[bt];
        g_Hs[i] = g_hsrev[(b*T_ + rid)*H_ + d - H_];
    }
}

// ---------------- e = t1 @ s2 ----------------
__global__ void k_e(const float* __restrict__ s2){
    int warp = threadIdx.x >> 5, lane = threadIdx.x & 31;
    int row = blockIdx.x*8 + warp; if (row >= BT_) return;
    const float* h = g_t1 + (size_t)row*D_;
    float a = 0.f;
    for (int k = lane; k < D_; k += 32) a += h[k]*s2[k];
    #pragma unroll
    for (int s = 16; s; s >>= 1) a += __shfl_down_sync(0xffffffffu, a, s);
    if (!lane) g_e[row] = a;
}

// ---------------- masked pooling ----------------
__global__ void k_u(const int* __restrict__ slen){
    __shared__ float al[T_];
    __shared__ float red[256];
    int b = blockIdx.x, tid = threadIdx.x;
    int len = slen[b];
    float v = 0.f;
    if (tid < T_){ v = (tid < len) ? g_e[b*T_ + tid] : 0.f; al[tid] = v; }
    red[tid] = v; __syncthreads();
    for (int s = 128; s; s >>= 1){ if (tid < s) red[tid] += red[tid+s]; __syncthreads(); }
    float denom = red[0] + 1e-9f;
    __syncthreads();
    if (tid < T_) al[tid] = al[tid] / denom;
    __syncthreads();
    for (int d = tid; d < D_; d += 256){
        float acc = 0.f;
        for (int t = 0; t < T_; t++) acc += al[t]*g_Hs[(size_t)(b*T_ + t)*D_ + d];
        g_U[b*D_ + d] = acc;
    }
}

// ---------------- gather E / Cu rows ----------------
__global__ void k_gatherR(const int* __restrict__ emo, const int* __restrict__ cau){
    int i = blockIdx.x*256 + threadIdx.x;
    if (i < NE_*D_){ int r = i / D_, d = i - r*D_; g_E[i]  = g_R[(size_t)emo[r]*D_ + d]; }
    if (i < NC_*D_){ int r = i / D_, d = i - r*D_; g_Cu[i] = g_R[(size_t)cau[r]*D_ + d]; }
}

// ---------------- per-chunk cross attention ----------------
__global__ void k_chunk(){
    __shared__ float Esh[D_];
    __shared__ float red[256];
    __shared__ float scs[4];
    int blk = blockIdx.x, tid = threadIdx.x;
    int e = blk >> 6, k = blk & 63;
    const float* Er = g_E + (size_t)e*D_;
    for (int d = tid; d < D_; d += 256) Esh[d] = Er[d];
    __syncthreads();
    float dots[4];
    for (int c = 0; c < 4; c++){
        const float* Cr = g_Cu + (size_t)(k*4 + c)*D_;
        float a = 0.f;
        for (int d = tid; d < D_; d += 256) a += Esh[d]*Cr[d];
        red[tid] = a; __syncthreads();
        for (int s = 128; s; s >>= 1){ if (tid < s) red[tid] += red[tid+s]; __syncthreads(); }
        dots[c] = red[0]; __syncthreads();
    }
    if (tid == 0){
        float m = fmaxf(fmaxf(dots[0],dots[1]), fmaxf(dots[2],dots[3]));
        float ex[4], s = 0.f;
        #pragma unroll
        for (int c = 0; c < 4; c++){ ex[c] = expf(dots[c]-m); s += ex[c]; }
        #pragma unroll
        for (int c = 0; c < 4; c++) scs[c] = ex[c]/s;
    }
    __syncthreads();
    const float* C0 = g_Cu + (size_t)(k*4+0)*D_;
    const float* C1 = g_Cu + (size_t)(k*4+1)*D_;
    const float* C2 = g_Cu + (size_t)(k*4+2)*D_;
    const float* C3 = g_Cu + (size_t)(k*4+3)*D_;
    float s0 = scs[0], s1 = scs[1], s2 = scs[2], s3 = scs[3];
    for (int d = tid; d < D_; d += 256)
        g_cE[(size_t)blk*D_ + d] = s0*C0[d] + s1*C1[d] + s2*C2[d] + s3*C3[d];
}

// ---------------- EY = E⊙Y: split planes + nrm2 ----------------
__global__ void k_EYsplit(__nv_bfloat16* __restrict__ p1,
                          __nv_bfloat16* __restrict__ p2,
                          __nv_bfloat16* __restrict__ p3){
    __shared__ float red[256];
    int row = blockIdx.x, tid = threadIdx.x;
    int e = row >> 6;
    const float* Er = g_E + (size_t)e*D_;
    const float* Y  = g_cE + (size_t)row*D_;
    float a = 0.f;
    for (int d = tid; d < D_; d += 256){
        float ev = Er[d], yv = Y[d];
        float df = ev - yv; a += df*df;
        __nv_bfloat16 h1, h2, h3;
        split3(ev*yv, h1, h2, h3);
        size_t idx = (size_t)row*D_ + d;
        p1[idx] = h1; p2[idx] = h2; p3[idx] = h3;
    }
    red[tid] = a; __syncthreads();
    for (int s = 128; s; s >>= 1){ if (tid < s) red[tid] += red[tid+s]; __syncthreads(); }
    if (tid == 0) g_n2[row] = sqrtf(red[0]);
}

// ---------------- EC = E⊙Cu: split planes + nrm3 ----------------
__global__ void k_ECsplit(__nv_bfloat16* __restrict__ p1,
                          __nv_bfloat16* __restrict__ p2,
                          __nv_bfloat16* __restrict__ p3){
    __shared__ float red[256];
    int row = blockIdx.x, tid = threadIdx.x;
    int e = row >> 8, c = row & 255;
    const float* Er = g_E + (size_t)e*D_;
    const float* Cr = g_Cu + (size_t)c*D_;
    float a = 0.f;
    for (int d = tid; d < D_; d += 256){
        float ev = Er[d], cv = Cr[d];
        float df = ev - cv; a += df*df;
        __nv_bfloat16 h1, h2, h3;
        split3(ev*cv, h1, h2, h3);
        size_t idx = (size_t)row*D_ + d;
        p1[idx] = h1; p2[idx] = h2; p3[idx] = h3;
    }
    red[tid] = a; __syncthreads();
    for (int s = 128; s; s >>= 1){ if (tid < s) red[tid] += red[tid+s]; __syncthreads(); }
    if (tid == 0) g_n3[row] = sqrtf(red[0]);
}

// ---------------- epilogue adds ----------------
__global__ void k_add2(const float* __restrict__ W2W){
    int idx = blockIdx.x*256 + threadIdx.x;
    if (idx >= NE_*NK_*D_) return;
    int row = idx / D_, n = idx - row*D_;
    int e = row >> 6;
    g_z2[idx] += g_EW2a[e*D_ + n] + g_n2[row]*W2W[(size_t)1536*D_ + n];
}

__global__ void k_add3(const float* __restrict__ W3W){
    int idx = blockIdx.x*256 + threadIdx.x;
    if (idx >= NE_*NC_*D_) return;
    int row = idx / D_, n = idx - row*D_;
    int e = row >> 8, c = row & 255;
    g_z3[idx] += g_EW3a[e*D_ + n] + g_CW3b[c*D_ + n] + g_disW3[c*D_ + n]
               + g_n3[row]*W3W[(size_t)1536*D_ + n]
               + g_of[(e<<6) + (c>>2)]*W3W[(size_t)2355*D_ + n];
}

// ---------------- BatchNorm (biased var) + lrelu ----------------
__global__ void k_bn(float* __restrict__ z, int rows){
    int e = blockIdx.x;
    int d = blockIdx.y*256 + threadIdx.x;
    size_t base = (size_t)e*rows*D_ + d;
    float s = 0.f;
    for (int r = 0; r < rows; r++) s += z[base + (size_t)r*D_];
    float m = s / (float)rows;
    float v = 0.f;
    for (int r = 0; r < rows; r++){ float t = z[base + (size_t)r*D_] - m; v += t*t; }
    v /= (float)rows;
    float inv = 1.f/sqrtf(v + 1e-5f);
    for (int r = 0; r < rows; r++){
        float t = (z[base + (size_t)r*D_] - m)*inv;
        z[base + (size_t)r*D_] = lrelu(t);
    }
}

// ---------------- 2-class head ----------------
__global__ void k_head(const float* __restrict__ Hx, const float* __restrict__ W,
                       const float* __restrict__ b2, float* __restrict__ out,
                       float* __restrict__ of, int rows){
    int warp = threadIdx.x >> 5, lane = threadIdx.x & 31;
    int row = blockIdx.x*8 + warp; if (row >= rows) return;
    const float* h = Hx + (size_t)row*D_;
    const float2* Wv = (const float2*)W;
    float a0 = 0.f, a1 = 0.f;
    for (int k = lane; k < D_; k += 32){
        float hv = h[k]; float2 w = Wv[k];
        a0 += hv*w.x; a1 += hv*w.y;
    }
    #pragma unroll
    for (int s = 16; s; s >>= 1){
        a0 += __shfl_down_sync(0xffffffffu, a0, s);
        a1 += __shfl_down_sync(0xffffffffu, a1, s);
    }
    if (!lane){
        float l0 = a0 + b2[0], l1 = a1 + b2[1];
        float m = fmaxf(l0, l1);
        float lse = m + logf(expf(l0-m) + expf(l1-m));
        out[row*2]   = l0 - lse;
        out[row*2+1] = l1 - lse;
        if (of) of[row] = (l1 > l0) ? 1.f : 0.f;
    }
}

// ---------------- L indicator ----------------
__global__ void k_L(const int* __restrict__ lab, float* __restrict__ out){
    int e = blockIdx.x, c = threadIdx.x;
    int a = lab[e*3], b = lab[e*3+1], d = lab[e*3+2];
    out[e*NC_ + c] = (a == c || b == c || d == c) ? 1.f : 0.f;
}

// ---------------- orchestration ----------------
extern "C" void kernel_launch(void* const* d_in, const int* in_sizes, int n_in,
                              void* d_out, int out_size){
    const float* word = (const float*)d_in[0];
    const float* pos  = (const float*)d_in[1];
    const float* dis  = (const float*)d_in[2];
    const float* WihF = (const float*)d_in[3];
    const float* WhhF = (const float*)d_in[4];
    const float* bihF = (const float*)d_in[5];
    const float* bhhF = (const float*)d_in[6];
    const float* WihB = (const float*)d_in[7];
    const float* WhhB = (const float*)d_in[8];
    const float* bihB = (const float*)d_in[9];
    const float* bhhB = (const float*)d_in[10];
    const float* s1W  = (const float*)d_in[11];
    const float* s1b  = (const float*)d_in[12];
    const float* s2W  = (const float*)d_in[13];
    const float* repW = (const float*)d_in[14];
    const float* repb = (const float*)d_in[15];
    const float* W2W  = (const float*)d_in[16];
    const float* W2b  = (const float*)d_in[17];
    const float* WoW  = (const float*)d_in[18];
    const float* Wob  = (const float*)d_in[19];
    const float* W3W  = (const float*)d_in[20];
    const float* W3b  = (const float*)d_in[21];
    const float* clsW = (const float*)d_in[22];
    const float* clsb = (const float*)d_in[23];
    const int* slen   = (const int*)d_in[24];
    const int* emo    = (const int*)d_in[25];
    const int* cau    = (const int*)d_in[26];
    const int* lab    = (const int*)d_in[27];
    float* out = (float*)d_out;

    cudaFuncSetAttribute(bgemm<false,false>, cudaFuncAttributeMaxDynamicSharedMemorySize, BGS_);
    cudaFuncSetAttribute(bgemm<true ,false>, cudaFuncAttributeMaxDynamicSharedMemorySize, BGS_);
    cudaFuncSetAttribute(bgemm<false,true >, cudaFuncAttributeMaxDynamicSharedMemorySize, BGS_);
    cudaFuncSetAttribute(bgemm<true ,true >, cudaFuncAttributeMaxDynamicSharedMemorySize, BGS_);

    void *p_xrev,*p_xbf,*p_xbb,*p_Hs,*p_t1,*p_U,*p_R,*p_E,*p_Cu,*p_cE;
    void *p_z2,*p_z3,*p_EW2a,*p_EW3a,*p_CW3b,*p_disW3,*p_bf,*p_bb,*p_zero,*p_of;
    void *p_WFT,*p_WBT,*p_repWT,*p_W2aT,*p_W2yT,*p_W2eyT,*p_W3aT,*p_W3bT,*p_W3cT;
    void *p_A1,*p_A2,*p_A3,*p_B1,*p_B2,*p_B3;
    cudaGetSymbolAddress(&p_xrev, g_xrev);
    cudaGetSymbolAddress(&p_xbf,  g_xbf);
    cudaGetSymbolAddress(&p_xbb,  g_xbb);
    cudaGetSymbolAddress(&p_Hs,   g_Hs);
    cudaGetSymbolAddress(&p_t1,   g_t1);
    cudaGetSymbolAddress(&p_U,    g_U);
    cudaGetSymbolAddress(&p_R,    g_R);
    cudaGetSymbolAddress(&p_E,    g_E);
    cudaGetSymbolAddress(&p_Cu,   g_Cu);
    cudaGetSymbolAddress(&p_cE,   g_cE);
    cudaGetSymbolAddress(&p_z2,   g_z2);
    cudaGetSymbolAddress(&p_z3,   g_z3);
    cudaGetSymbolAddress(&p_EW2a, g_EW2a);
    cudaGetSymbolAddress(&p_EW3a, g_EW3a);
    cudaGetSymbolAddress(&p_CW3b, g_CW3b);
    cudaGetSymbolAddress(&p_disW3,g_disW3);
    cudaGetSymbolAddress(&p_bf,   g_bf);
    cudaGetSymbolAddress(&p_bb,   g_bb);
    cudaGetSymbolAddress(&p_zero, g_zero);
    cudaGetSymbolAddress(&p_of,   g_of);
    cudaGetSymbolAddress(&p_WFT,  g_WihFT);
    cudaGetSymbolAddress(&p_WBT,  g_WihBT);
    cudaGetSymbolAddress(&p_repWT,g_repWT);
    cudaGetSymbolAddress(&p_W2aT, g_W2aT);
    cudaGetSymbolAddress(&p_W2yT, g_W2yT);
    cudaGetSymbolAddress(&p_W2eyT,g_W2eyT);
    cudaGetSymbolAddress(&p_W3aT, g_W3aT);
    cudaGetSymbolAddress(&p_W3bT, g_W3bT);
    cudaGetSymbolAddress(&p_W3cT, g_W3cT);
    cudaGetSymbolAddress(&p_A1, g_A1);
    cudaGetSymbolAddress(&p_A2, g_A2);
    cudaGetSymbolAddress(&p_A3, g_A3);
    cudaGetSymbolAddress(&p_B1, g_B1);
    cudaGetSymbolAddress(&p_B2, g_B2);
    cudaGetSymbolAddress(&p_B3, g_B3);

    __nv_bfloat16 *A1 = (__nv_bfloat16*)p_A1, *A2 = (__nv_bfloat16*)p_A2,
                  *A3 = (__nv_bfloat16*)p_A3, *B1 = (__nv_bfloat16*)p_B1,
                  *B2 = (__nv_bfloat16*)p_B2, *B3 = (__nv_bfloat16*)p_B3;

    auto splitA = [&](const float* src, int n){
        k_split<<<(n + 255)/256, 256>>>(src, A1, A2, A3, n);
    };
    auto splitB = [&](const float* src, int n){
        k_split<<<(n + 255)/256, 256>>>(src, B1, B2, B3, n);
    };

    dim3 tb(32, 8);
    dim3 tg(D_/32, D_/32);

    // prep
    k_prep<<<B_, T_>>>(slen);
    k_gather<<<(BT_*192 + 255)/256, 256>>>((const float4*)word);
    k_bias<<<(G_ + 255)/256, 256>>>(bihF, bhhF, bihB, bhhB);
    k_zero<<<(2*2*B_*H_ + 255)/256, 256>>>();
    k_transT<<<tg, tb>>>(repW, (float*)p_repWT);
    k_transT<<<tg, tb>>>(W2W,                   (float*)p_W2aT);
    k_transT<<<tg, tb>>>(W2W + (size_t)768*D_,  (float*)p_W2yT);
    k_transT<<<tg, tb>>>(W2W + (size_t)1537*D_, (float*)p_W2eyT);
    k_transT<<<tg, tb>>>(W3W,                   (float*)p_W3aT);
    k_transT<<<tg, tb>>>(W3W + (size_t)768*D_,  (float*)p_W3bT);
    k_transT<<<tg, tb>>>(W3W + (size_t)1537*D_, (float*)p_W3cT);
    k_transW2<<<dim3(D_/32, G_/32), tb>>>(WihF, (float*)p_WFT);
    k_transW2<<<dim3(D_/32, G_/32), tb>>>(WihB, (float*)p_WBT);

    // UPSTREAM (fp32 — amplifier-sensitive): input projections
    sgemmF<false,false><<<dim3(G_/128, BT_/128), 256>>>(word, (const float*)p_WFT,
        (const float*)p_bf, (float*)p_xbf, BT_, G_, D_);
    sgemmF<false,false><<<dim3(G_/128, BT_/128), 256>>>((const float*)p_xrev, (const float*)p_WBT,
        (const float*)p_bb, (float*)p_xbb, BT_, G_, D_);

    // recurrence
    for (int t = 0; t < T_; t++)
        k_lstm<<<dim3(B_/32, H_/32, 2), 128>>>(WhhF, WhhB, t);

    k_hs<<<(BT_*D_ + 255)/256, 256>>>();

    // attention pooling — fp32 (feeds alpha)
    sgemmF<true,false><<<dim3(D_/128, BT_/128), 256>>>((const float*)p_Hs, s1W, s1b,
        (float*)p_t1, BT_, D_, D_);
    k_e<<<BT_/8, 256>>>(s2W);
    k_u<<<B_, 256>>>(slen);

    // DOWNSTREAM (bf16x6 tensor)
    splitA((const float*)p_U, B_*D_); splitB((const float*)p_repWT, D_*D_);
    bgemm<true,false><<<dim3(D_/128, B_/128), 256, BGS_>>>(A1,A2,A3, B1,B2,B3,
        repb, (float*)p_R, B_, D_, D_);
    k_gatherR<<<(NC_*D_ + 255)/256, 256>>>(emo, cau);

    // phase 2
    k_chunk<<<NE_*NK_, 256>>>();
    sgemm64<false,false><<<dim3(D_/64, (NE_*NK_)/64), 256>>>(pos, W2W + (size_t)2305*D_,
        W2b, (float*)p_z2, NE_*NK_, D_, POS_);
    splitA((const float*)p_cE, NE_*NK_*D_); splitB((const float*)p_W2yT, D_*D_);
    bgemm<false,true><<<dim3(D_/128, (NE_*NK_)/128), 256, BGS_>>>(A1,A2,A3, B1,B2,B3,
        (const float*)p_zero, (float*)p_z2, NE_*NK_, D_, D_);
    k_EYsplit<<<NE_*NK_, 256>>>(A1, A2, A3);
    splitB((const float*)p_W2eyT, D_*D_);
    bgemm<false,true><<<dim3(D_/128, (NE_*NK_)/128), 256, BGS_>>>(A1,A2,A3, B1,B2,B3,
        (const float*)p_zero, (float*)p_z2, NE_*NK_, D_, D_);
    splitA((const float*)p_E, NE_*D_); splitB((const float*)p_W2aT, D_*D_);
    bgemm<false,false><<<dim3(D_/128, NE_/128), 256, BGS_>>>(A1,A2,A3, B1,B2,B3,
        (const float*)p_zero, (float*)p_EW2a, NE_, D_, D_);
    k_add2<<<(NE_*NK_*D_ + 255)/256, 256>>>(W2W);
    k_bn<<<dim3(NE_, 3), 256>>>((float*)p_z2, NK_);
    k_head<<<(NE_*NK_)/8, 256>>>((const float*)p_z2, WoW, Wob, out, (float*)p_of, NE_*NK_);

    // phase 3
    k_ECsplit<<<NE_*NC_, 256>>>(A1, A2, A3);
    splitB((const float*)p_W3cT, D_*D_);
    bgemm<false,false><<<dim3(D_/128, (NE_*NC_)/128), 256, BGS_>>>(A1,A2,A3, B1,B2,B3,
        W3b, (float*)p_z3, NE_*NC_, D_, D_);
    splitA((const float*)p_E, NE_*D_); splitB((const float*)p_W3aT, D_*D_);
    bgemm<false,false><<<dim3(D_/128, NE_/128), 256, BGS_>>>(A1,A2,A3, B1,B2,B3,
        (const float*)p_zero, (float*)p_EW3a, NE_, D_, D_);
    splitA((const float*)p_Cu, NC_*D_); splitB((const float*)p_W3bT, D_*D_);
    bgemm<false,false><<<dim3(D_/128, NC_/128), 256, BGS_>>>(A1,A2,A3, B1,B2,B3,
        (const float*)p_zero, (float*)p_CW3b, NC_, D_, D_);
    sgemm64<false,false><<<dim3(D_/64, (NC_+63)/64), 256>>>(dis, W3W + (size_t)2305*D_,
        (const float*)p_zero, (float*)p_disW3, NC_, D_, POS_);
    k_add3<<<(NE_*NC_*D_ + 255)/256, 256>>>(W3W);
    k_bn<<<dim3(NE_, 3), 256>>>((float*)p_z3, NC_);
    k_head<<<(NE_*NC_)/8, 256>>>((const float*)p_z3, clsW, clsb,
        out + NE_*NK_*2, nullptr, NE_*NC_);

    // L indicator
    k_L<<<NE_, NC_>>>(lab, out + NE_*NK_*2 + NE_*NC_*2);
}

// round 13
// speedup vs baseline: 1.8678x; 1.0138x over previous
#include <cuda_runtime.h>
#include <cuda_bf16.h>
#include <math.h>
#include <stdint.h>
#include <stddef.h>

// ---------------- problem dims ----------------
#define B_   256
#define T_   96
#define D_   768
#define H_   384
#define G_   1536          // 4*H
#define G2_  3072          // both directions merged
#define BT_  (B_*T_)       // 24576
#define NE_  128
#define NC_  256
#define NK_  64
#define POS_ 50
#define AMAX_ ((size_t)NE_*NC_*D_)
#define BMAX_ ((size_t)D_*D_)

// ---------------- scratch ----------------
__device__ float g_xall[(size_t)BT_*G2_];   // merged gate pre-activations
__device__ float g_hbuf[2][2][B_*H_];
__device__ float g_cbuf[2][B_*H_];
__device__ float g_Hs[BT_*D_];
__device__ float g_t1[BT_*D_];
__device__ float g_e[BT_];
__device__ float g_U[B_*D_];
__device__ float g_R[NC_*D_];
__device__ float g_E[NE_*D_];
__device__ float g_Cu[NC_*D_];
__device__ float g_cE[NE_*NK_*D_];
__device__ float g_n2[NE_*NK_];
__device__ float g_n3[NE_*NC_];
__device__ float g_z2[NE_*NK_*D_];
__device__ float g_z3[NE_*NC_*D_];
__device__ float g_EW2a[NE_*D_];
__device__ float g_EW3a[NE_*D_];
__device__ float g_CW3b[NC_*D_];
__device__ float g_disW3[NC_*D_];
__device__ float g_of[NE_*NK_];
__device__ float g_bm[G2_];
__device__ float g_zero[G_];
__device__ int   g_rev[BT_];
__device__ float g_WcT[(size_t)D_*G2_];     // [768, 3072] merged Wih^T
__device__ float g_W2yT [D_*D_];
__device__ float g_W2eyT[D_*D_];
__device__ float g_W3cT [D_*D_];
__device__ __nv_bfloat16 g_A1[AMAX_];
__device__ __nv_bfloat16 g_A2[AMAX_];
__device__ __nv_bfloat16 g_A3[AMAX_];
__device__ __nv_bfloat16 g_B1[BMAX_];
__device__ __nv_bfloat16 g_B2[BMAX_];
__device__ __nv_bfloat16 g_B3[BMAX_];

__device__ __forceinline__ float lrelu(float x){ return x >= 0.f ? x : 0.01f*x; }
__device__ __forceinline__ float sigm(float x){ return 1.f/(1.f+expf(-x)); }

__device__ __forceinline__ void split3(float a, __nv_bfloat16& x1,
                                       __nv_bfloat16& x2, __nv_bfloat16& x3){
    x1 = __float2bfloat16(a);
    float r = a - __bfloat162float(x1);
    x2 = __float2bfloat16(r);
    float r2 = r - __bfloat162float(x2);
    x3 = __float2bfloat16(r2);
}

#define MMAB(C, A0,A1,A2,A3, B0,B1) \
    asm volatile("mma.sync.aligned.m16n8k16.row.col.f32.bf16.bf16.f32 " \
        "{%0,%1,%2,%3}, {%4,%5,%6,%7}, {%8,%9}, {%0,%1,%2,%3};" \
        : "+f"((C)[0]),"+f"((C)[1]),"+f"((C)[2]),"+f"((C)[3]) \
        : "r"(A0),"r"(A1),"r"(A2),"r"(A3),"r"(B0),"r"(B1))

// ---------------- fp32 SGEMM (UPSTREAM; exact-tile 128x128x16) ----------------
template<bool RELU, bool ACC>
__global__ __launch_bounds__(256, 2)
void sgemmF(const float* __restrict__ A, const float* __restrict__ Bm,
            const float* __restrict__ bias, float* __restrict__ Cm,
            int M, int N, int K){
    __shared__ float As[2][16][136];
    __shared__ float Bs[2][16][128];
    const int tid = threadIdx.x;
    const int bm = blockIdx.y << 7, bn = blockIdx.x << 7;
    const int tx = tid & 15, ty = tid >> 4;

    const int am0 = tid >> 2, ak0 = (tid & 3) << 2;
    const int am1 = am0 + 64;
    const int bk0 = tid >> 5, bn0 = (tid & 31) << 2;
    const int bk1 = bk0 + 8;

    float4 ra0, ra1, rb0, rb1;
    float acc[8][8];
    #pragma unroll
    for (int i = 0; i < 8; i++)
        #pragma unroll
        for (int j = 0; j < 8; j++) acc[i][j] = 0.f;

    auto loadRegs = [&](int k0){
        ra0 = *(const float4*)(A  + (size_t)(bm+am0)*K + k0 + ak0);
        ra1 = *(const float4*)(A  + (size_t)(bm+am1)*K + k0 + ak0);
        rb0 = *(const float4*)(Bm + (size_t)(k0+bk0)*N + bn + bn0);
        rb1 = *(const float4*)(Bm + (size_t)(k0+bk1)*N + bn + bn0);
    };
    auto storeSmem = [&](int buf){
        As[buf][ak0+0][am0] = ra0.x; As[buf][ak0+1][am0] = ra0.y;
        As[buf][ak0+2][am0] = ra0.z; As[buf][ak0+3][am0] = ra0.w;
        As[buf][ak0+0][am1] = ra1.x; As[buf][ak0+1][am1] = ra1.y;
        As[buf][ak0+2][am1] = ra1.z; As[buf][ak0+3][am1] = ra1.w;
        *(float4*)&Bs[buf][bk0][bn0] = rb0;
        *(float4*)&Bs[buf][bk1][bn0] = rb1;
    };

    loadRegs(0); storeSmem(0); __syncthreads();
    const int ntk = K >> 4;
    for (int kt = 0; kt < ntk; kt++){
        if (kt + 1 < ntk) loadRegs((kt+1) << 4);
        const int buf = kt & 1;
        #pragma unroll
        for (int kk = 0; kk < 16; kk++){
            float4 a0 = *(const float4*)&As[buf][kk][ty<<2];
            float4 a1 = *(const float4*)&As[buf][kk][(ty<<2)+64];
            float4 b0 = *(const float4*)&Bs[buf][kk][tx<<2];
            float4 b1 = *(const float4*)&Bs[buf][kk][(tx<<2)+64];
            float av[8] = {a0.x,a0.y,a0.z,a0.w,a1.x,a1.y,a1.z,a1.w};
            float bv[8] = {b0.x,b0.y,b0.z,b0.w,b1.x,b1.y,b1.z,b1.w};
            #pragma unroll
            for (int i = 0; i < 8; i++)
                #pragma unroll
                for (int j = 0; j < 8; j++) acc[i][j] += av[i]*bv[j];
        }
        if (kt + 1 < ntk) storeSmem(buf ^ 1);
        __syncthreads();
    }
    #pragma unroll
    for (int i = 0; i < 8; i++){
        int m = bm + (ty<<2) + (i&3) + ((i>>2)<<6);
        size_t base = (size_t)m*N;
        #pragma unroll
        for (int jg = 0; jg < 2; jg++){
            int n0 = bn + (tx<<2) + (jg<<6);
            float4 v;
            if (ACC) v = *(const float4*)&Cm[base + n0];
            else     v = *(const float4*)&bias[n0];
            v.x += acc[i][jg*4+0]; v.y += acc[i][jg*4+1];
            v.z += acc[i][jg*4+2]; v.w += acc[i][jg*4+3];
            if (RELU){ v.x = lrelu(v.x); v.y = lrelu(v.y); v.z = lrelu(v.z); v.w = lrelu(v.w); }
            *(float4*)&Cm[base + n0] = v;
        }
    }
}

// ---------------- fp32 -> 3x bf16 split ----------------
__global__ void k_split(const float* __restrict__ src,
                        __nv_bfloat16* __restrict__ p1,
                        __nv_bfloat16* __restrict__ p2,
                        __nv_bfloat16* __restrict__ p3, int n){
    int i = blockIdx.x*256 + threadIdx.x;
    if (i >= n) return;
    __nv_bfloat16 h1, h2, h3;
    split3(src[i], h1, h2, h3);
    p1[i] = h1; p2[i] = h2; p3[i] = h3;
}

// ============ bf16x6 GEMM (big downstream GEMMs) ==========
#define BGP_  10240
#define BGS_  67584

template<bool RELU, bool ACC>
__global__ void __launch_bounds__(256)
bgemm(const __nv_bfloat16* __restrict__ A1, const __nv_bfloat16* __restrict__ A2,
      const __nv_bfloat16* __restrict__ A3, const __nv_bfloat16* __restrict__ Bt1,
      const __nv_bfloat16* __restrict__ Bt2, const __nv_bfloat16* __restrict__ Bt3,
      const float* __restrict__ bias, float* __restrict__ Cm,
      int M, int N, int K){
    extern __shared__ char sm[];
    const int tid = threadIdx.x, warp = tid >> 5, lane = tid & 31;
    const int gid = lane >> 2, tig = lane & 3;
    const int bm = blockIdx.y << 7, bn = blockIdx.x << 7;
    const int wm = (warp & 1) << 6, wn = (warp >> 1) << 5;

    const __nv_bfloat16* Ap[3] = {A1, A2, A3};
    const __nv_bfloat16* Bp[3] = {Bt1, Bt2, Bt3};

    float acc[4][4][4];
    #pragma unroll
    for (int i = 0; i < 4; i++)
        #pragma unroll
        for (int j = 0; j < 4; j++)
            #pragma unroll
            for (int q = 0; q < 4; q++) acc[i][j][q] = 0.f;

    for (int k0 = 0; k0 < K; k0 += 32){
        __syncthreads();
        for (int idx = tid; idx < 128*16; idx += 256){
            int r = idx >> 4, kq = idx & 15;
            size_t ga = (((size_t)(bm + r)*K + k0) >> 1) + kq;
            size_t gb = (((size_t)(bn + r)*K + k0) >> 1) + kq;
            uint32_t so = (uint32_t)(r*80 + kq*4);
            #pragma unroll
            for (int p = 0; p < 3; p++){
                *(uint32_t*)(sm + p*BGP_ + so)           = ((const uint32_t*)Ap[p])[ga];
                *(uint32_t*)(sm + 3*BGP_ + p*BGP_ + so)  = ((const uint32_t*)Bp[p])[gb];
            }
        }
        __syncthreads();
        #pragma unroll
        for (int s = 0; s < 2; s++){
            uint32_t bfr[3][4][2];
            #pragma unroll
            for (int p = 0; p < 3; p++)
                #pragma unroll
                for (int nt = 0; nt < 4; nt++){
                    int n = wn + (nt << 3) + gid;
                    const char* bb = sm + 3*BGP_ + p*BGP_ + n*80 + s*32 + tig*4;
                    bfr[p][nt][0] = *(const uint32_t*)bb;
                    bfr[p][nt][1] = *(const uint32_t*)(bb + 16);
                }
            #pragma unroll
            for (int pa = 0; pa < 3; pa++){
                #pragma unroll
                for (int mt = 0; mt < 4; mt++){
                    int r = wm + (mt << 4) + gid;
                    const char* ab = sm + pa*BGP_ + r*80 + s*32 + tig*4;
                    uint32_t a0 = *(const uint32_t*)ab;
                    uint32_t a1 = *(const uint32_t*)(ab + 640);
                    uint32_t a2 = *(const uint32_t*)(ab + 16);
                    uint32_t a3 = *(const uint32_t*)(ab + 656);
                    if (pa == 0){
                        #pragma unroll
                        for (int nt = 0; nt < 4; nt++){
                            MMAB(acc[mt][nt], a0,a1,a2,a3, bfr[0][nt][0], bfr[0][nt][1]);
                            MMAB(acc[mt][nt], a0,a1,a2,a3, bfr[1][nt][0], bfr[1][nt][1]);
                            MMAB(acc[mt][nt], a0,a1,a2,a3, bfr[2][nt][0], bfr[2][nt][1]);
                        }
                    } else if (pa == 1){
                        #pragma unroll
                        for (int nt = 0; nt < 4; nt++){
                            MMAB(acc[mt][nt], a0,a1,a2,a3, bfr[0][nt][0], bfr[0][nt][1]);
                            MMAB(acc[mt][nt], a0,a1,a2,a3, bfr[1][nt][0], bfr[1][nt][1]);
                        }
                    } else {
                        #pragma unroll
                        for (int nt = 0; nt < 4; nt++)
                            MMAB(acc[mt][nt], a0,a1,a2,a3, bfr[0][nt][0], bfr[0][nt][1]);
                    }
                }
            }
        }
    }
    __syncthreads();
    float* fs = (float*)sm;
    #pragma unroll
    for (int mt = 0; mt < 4; mt++){
        int r0 = wm + (mt << 4) + gid;
        #pragma unroll
        for (int nt = 0; nt < 4; nt++){
            int c = wn + (nt << 3) + (tig << 1);
            fs[r0*132 + c]       = acc[mt][nt][0];
            fs[r0*132 + c + 1]   = acc[mt][nt][1];
            fs[(r0+8)*132 + c]   = acc[mt][nt][2];
            fs[(r0+8)*132 + c+1] = acc[mt][nt][3];
        }
    }
    __syncthreads();
    for (int i = tid; i < 128*128; i += 256){
        int r = i >> 7, c = i & 127;
        float v = fs[r*132 + c];
        float* dst = Cm + (size_t)(bm + r)*N + bn + c;
        float base = ACC ? *dst : bias[bn + c];
        v += base;
        if (RELU) v = lrelu(v);
        *dst = v;
    }
}

// ---------------- prep ----------------
__global__ void k_prep(const int* __restrict__ slen){
    int b = blockIdx.x, t = threadIdx.x;
    int len = slen[b];
    g_rev[b*T_ + t] = (t < len) ? (len - 1 - t) : t;
}

__global__ void k_biasM(const float* bihf, const float* bhhf,
                        const float* bihb, const float* bhhb){
    int i = blockIdx.x*256 + threadIdx.x;
    if (i < G_)       g_bm[i]      = bihf[i] + bhhf[i];
    else if (i < G2_) g_bm[i]      = bihb[i-G_] + bhhb[i-G_];
}

__global__ void k_zero(){
    int i = blockIdx.x*256 + threadIdx.x;
    if (i < 2*2*B_*H_) (&g_hbuf[0][0][0])[i] = 0.f;
    if (i < 2*B_*H_)   (&g_cbuf[0][0])[i]    = 0.f;
}

// 768x768 block transpose
__global__ void k_transT(const float* __restrict__ src, float* __restrict__ dst){
    __shared__ float t[32][33];
    int r0 = blockIdx.y*32, c0 = blockIdx.x*32;
    int tx = threadIdx.x, ty = threadIdx.y;
    #pragma unroll
    for (int q = 0; q < 32; q += 8)
        t[ty+q][tx] = src[(size_t)(r0+ty+q)*D_ + c0+tx];
    __syncthreads();
    #pragma unroll
    for (int q = 0; q < 32; q += 8)
        dst[(size_t)(c0+ty+q)*D_ + r0+tx] = t[tx][ty+q];
}

// Wih [G,D] -> merged [D, G2] at column offset
__global__ void k_transWM(const float* __restrict__ src, int colOff){
    __shared__ float t[32][33];
    int k0 = blockIdx.x*32, n0 = blockIdx.y*32;
    int tx = threadIdx.x, ty = threadIdx.y;
    #pragma unroll
    for (int q = 0; q < 32; q += 8)
        t[ty+q][tx] = src[(size_t)(n0+ty+q)*D_ + k0+tx];
    __syncthreads();
    #pragma unroll
    for (int q = 0; q < 32; q += 8)
        g_WcT[(size_t)(k0+ty+q)*G2_ + colOff + n0+tx] = t[tx][ty+q];
}

// ---------------- small-K SGEMM (guards), 64x64 ----------------
template<bool TB, bool RELU>
__global__ void sgemm64(const float* __restrict__ A, const float* __restrict__ Bm,
                        const float* __restrict__ bias, float* __restrict__ Cm,
                        int M, int N, int K, int ldb){
    __shared__ float As[16][65];
    __shared__ float Bs[16][65];
    int bm = blockIdx.y << 6, bn = blockIdx.x << 6;
    int tid = threadIdx.x;
    int tx = tid & 15, ty = tid >> 4;
    float acc[4][4];
    #pragma unroll
    for (int i = 0; i < 4; i++)
        #pragma unroll
        for (int j = 0; j < 4; j++) acc[i][j] = 0.f;
    int arow = tid >> 2, ak0 = (tid & 3) << 2;
    for (int k0 = 0; k0 < K; k0 += 16){
        #pragma unroll
        for (int q = 0; q < 4; q++){
            int kk = ak0 + q, gm = bm + arow, gk = k0 + kk;
            As[kk][arow] = (gm < M && gk < K) ? A[(size_t)gm*K + gk] : 0.f;
        }
        {
            int kr = tid >> 4, nc0 = (tid & 15) << 2;
            #pragma unroll
            for (int q = 0; q < 4; q++){
                int n = nc0 + q, gk = k0 + kr, gn = bn + n;
                Bs[kr][n] = (gk < K && gn < N) ? Bm[(size_t)gk*ldb + gn] : 0.f;
            }
        }
        __syncthreads();
        #pragma unroll
        for (int kk = 0; kk < 16; kk++){
            float a[4], b[4];
            #pragma unroll
            for (int i = 0; i < 4; i++) a[i] = As[kk][ty + (i<<4)];
            #pragma unroll
            for (int j = 0; j < 4; j++) b[j] = Bs[kk][tx + (j<<4)];
            #pragma unroll
            for (int i = 0; i < 4; i++)
                #pragma unroll
                for (int j = 0; j < 4; j++) acc[i][j] += a[i]*b[j];
        }
        __syncthreads();
    }
    #pragma unroll
    for (int i = 0; i < 4; i++){
        int gm = bm + ty + (i<<4); if (gm >= M) continue;
        #pragma unroll
        for (int j = 0; j < 4; j++){
            int gn = bn + tx + (j<<4); if (gn >= N) continue;
            float v = acc[i][j] + bias[gn];
            if (RELU) v = lrelu(v);
            Cm[(size_t)gm*N + gn] = v;
        }
    }
}

// ---------------- fused LSTM step (merged x-proj; Hs-direct writes) ----------
__global__ void k_lstm2(const float* __restrict__ WhhF,
                        const float* __restrict__ WhhB, int t){
    int dir = blockIdx.z;
    const float* Whh = dir ? WhhB : WhhF;
    const float* hp  = g_hbuf[dir][t & 1];
    float* hn        = g_hbuf[dir][(t & 1) ^ 1];
    float* cc        = g_cbuf[dir];

    int bBase = blockIdx.x << 5, jBase = blockIdx.y << 5;
    int tid = threadIdx.x, tx = tid & 15, ty = tid >> 4;

    __shared__ float shh[32][17];
    __shared__ float shw[4][16][33];

    float acc[4][4][2];
    #pragma unroll
    for (int a = 0; a < 4; a++)
        #pragma unroll
        for (int g = 0; g < 4; g++){ acc[a][g][0]=0.f; acc[a][g][1]=0.f; }

    for (int kc = 0; kc < H_; kc += 16){
        #pragma unroll
        for (int q = 0; q < 4; q++){
            int e = tid + 128*q;
            int bl = e >> 4, kk = e & 15;
            shh[bl][kk] = hp[(bBase + bl)*H_ + kc + kk];
        }
        #pragma unroll
        for (int q = 0; q < 16; q++){
            int e = tid + 128*q;
            int g = e >> 9, rem = e & 511;
            int jl = rem >> 4, kk = rem & 15;
            shw[g][kk][jl] = Whh[(size_t)(g*H_ + jBase + jl)*H_ + kc + kk];
        }
        __syncthreads();
        #pragma unroll
        for (int kk = 0; kk < 16; kk++){
            float hv[4];
            #pragma unroll
            for (int bb = 0; bb < 4; bb++) hv[bb] = shh[(ty<<2)+bb][kk];
            #pragma unroll
            for (int g = 0; g < 4; g++){
                float w0 = shw[g][kk][(tx<<1)];
                float w1 = shw[g][kk][(tx<<1)+1];
                #pragma unroll
                for (int bb = 0; bb < 4; bb++){
                    acc[bb][g][0] += hv[bb]*w0;
                    acc[bb][g][1] += hv[bb]*w1;
                }
            }
        }
        __syncthreads();
    }
    #pragma unroll
    for (int bb = 0; bb < 4; bb++){
        int b = bBase + (ty<<2) + bb;
        int rid = g_rev[b*T_ + t];
        // fwd: x-proj at (b,t), cols [0,1536); bwd: at (b,rev(t)), cols [1536,3072)
        const float* xrow = g_xall + (size_t)(b*T_ + (dir ? rid : t))*G2_ + (dir ? G_ : 0);
        // fwd h -> Hs row (b,t) left half; bwd h -> Hs row (b,rev(t)) right half
        float* hsrow = g_Hs + (size_t)(b*T_ + (dir ? rid : t))*D_ + (dir ? H_ : 0);
        #pragma unroll
        for (int jj = 0; jj < 2; jj++){
            int j = jBase + (tx<<1) + jj;
            float gi = acc[bb][0][jj] + xrow[j];
            float gf = acc[bb][1][jj] + xrow[H_ + j];
            float gg = acc[bb][2][jj] + xrow[2*H_ + j];
            float go = acc[bb][3][jj] + xrow[3*H_ + j];
            float cold = cc[b*H_ + j];
            float cn = sigm(gf)*cold + sigm(gi)*tanhf(gg);
            float hv = sigm(go)*tanhf(cn);
            cc[b*H_ + j] = cn;
            hn[b*H_ + j] = hv;
            hsrow[j] = hv;
        }
    }
}

// ---------------- e = t1 @ s2 ----------------
__global__ void k_e(const float* __restrict__ s2){
    int warp = threadIdx.x >> 5, lane = threadIdx.x & 31;
    int row = blockIdx.x*8 + warp; if (row >= BT_) return;
    const float* h = g_t1 + (size_t)row*D_;
    float a = 0.f;
    for (int k = lane; k < D_; k += 32) a += h[k]*s2[k];
    #pragma unroll
    for (int s = 16; s; s >>= 1) a += __shfl_down_sync(0xffffffffu, a, s);
    if (!lane) g_e[row] = a;
}

// ---------------- masked pooling ----------------
__global__ void k_u(const int* __restrict__ slen){
    __shared__ float al[T_];
    __shared__ float red[256];
    int b = blockIdx.x, tid = threadIdx.x;
    int len = slen[b];
    float v = 0.f;
    if (tid < T_){ v = (tid < len) ? g_e[b*T_ + tid] : 0.f; al[tid] = v; }
    red[tid] = v; __syncthreads();
    for (int s = 128; s; s >>= 1){ if (tid < s) red[tid] += red[tid+s]; __syncthreads(); }
    float denom = red[0] + 1e-9f;
    __syncthreads();
    if (tid < T_) al[tid] = al[tid] / denom;
    __syncthreads();
    for (int d = tid; d < D_; d += 256){
        float acc = 0.f;
        for (int t = 0; t < T_; t++) acc += al[t]*g_Hs[(size_t)(b*T_ + t)*D_ + d];
        g_U[b*D_ + d] = acc;
    }
}

// ---------------- gather E / Cu rows ----------------
__global__ void k_gatherR(const int* __restrict__ emo, const int* __restrict__ cau){
    int i = blockIdx.x*256 + threadIdx.x;
    if (i < NE_*D_){ int r = i / D_, d = i - r*D_; g_E[i]  = g_R[(size_t)emo[r]*D_ + d]; }
    if (i < NC_*D_){ int r = i / D_, d = i - r*D_; g_Cu[i] = g_R[(size_t)cau[r]*D_ + d]; }
}

// ---------------- per-chunk cross attention ----------------
__global__ void k_chunk(){
    __shared__ float Esh[D_];
    __shared__ float red[256];
    __shared__ float scs[4];
    int blk = blockIdx.x, tid = threadIdx.x;
    int e = blk >> 6, k = blk & 63;
    const float* Er = g_E + (size_t)e*D_;
    for (int d = tid; d < D_; d += 256) Esh[d] = Er[d];
    __syncthreads();
    float dots[4];
    for (int c = 0; c < 4; c++){
        const float* Cr = g_Cu + (size_t)(k*4 + c)*D_;
        float a = 0.f;
        for (int d = tid; d < D_; d += 256) a += Esh[d]*Cr[d];
        red[tid] = a; __syncthreads();
        for (int s = 128; s; s >>= 1){ if (tid < s) red[tid] += red[tid+s]; __syncthreads(); }
        dots[c] = red[0]; __syncthreads();
    }
    if (tid == 0){
        float m = fmaxf(fmaxf(dots[0],dots[1]), fmaxf(dots[2],dots[3]));
        float ex[4], s = 0.f;
        #pragma unroll
        for (int c = 0; c < 4; c++){ ex[c] = expf(dots[c]-m); s += ex[c]; }
        #pragma unroll
        for (int c = 0; c < 4; c++) scs[c] = ex[c]/s;
    }
    __syncthreads();
    const float* C0 = g_Cu + (size_t)(k*4+0)*D_;
    const float* C1 = g_Cu + (size_t)(k*4+1)*D_;
    const float* C2 = g_Cu + (size_t)(k*4+2)*D_;
    const float* C3 = g_Cu + (size_t)(k*4+3)*D_;
    float s0 = scs[0], s1 = scs[1], s2 = scs[2], s3 = scs[3];
    for (int d = tid; d < D_; d += 256)
        g_cE[(size_t)blk*D_ + d] = s0*C0[d] + s1*C1[d] + s2*C2[d] + s3*C3[d];
}

// ---------------- EY = E⊙Y: split planes + nrm2 ----------------
__global__ void k_EYsplit(__nv_bfloat16* __restrict__ p1,
                          __nv_bfloat16* __restrict__ p2,
                          __nv_bfloat16* __restrict__ p3){
    __shared__ float red[256];
    int row = blockIdx.x, tid = threadIdx.x;
    int e = row >> 6;
    const float* Er = g_E + (size_t)e*D_;
    const float* Y  = g_cE + (size_t)row*D_;
    float a = 0.f;
    for (int d = tid; d < D_; d += 256){
        float ev = Er[d], yv = Y[d];
        float df = ev - yv; a += df*df;
        __nv_bfloat16 h1, h2, h3;
        split3(ev*yv, h1, h2, h3);
        size_t idx = (size_t)row*D_ + d;
        p1[idx] = h1; p2[idx] = h2; p3[idx] = h3;
    }
    red[tid] = a; __syncthreads();
    for (int s = 128; s; s >>= 1){ if (tid < s) red[tid] += red[tid+s]; __syncthreads(); }
    if (tid == 0) g_n2[row] = sqrtf(red[0]);
}

// ---------------- EC = E⊙Cu: split planes + nrm3 ----------------
__global__ void k_ECsplit(__nv_bfloat16* __restrict__ p1,
                          __nv_bfloat16* __restrict__ p2,
                          __nv_bfloat16* __restrict__ p3){
    __shared__ float red[256];
    int row = blockIdx.x, tid = threadIdx.x;
    int e = row >> 8, c = row & 255;
    const float* Er = g_E + (size_t)e*D_;
    const float* Cr = g_Cu + (size_t)c*D_;
    float a = 0.f;
    for (int d = tid; d < D_; d += 256){
        float ev = Er[d], cv = Cr[d];
        float df = ev - cv; a += df*df;
        __nv_bfloat16 h1, h2, h3;
        split3(ev*cv, h1, h2, h3);
        size_t idx = (size_t)row*D_ + d;
        p1[idx] = h1; p2[idx] = h2; p3[idx] = h3;
    }
    red[tid] = a; __syncthreads();
    for (int s = 128; s; s >>= 1){ if (tid < s) red[tid] += red[tid+s]; __syncthreads(); }
    if (tid == 0) g_n3[row] = sqrtf(red[0]);
}

// ---------------- epilogue adds ----------------
__global__ void k_add2(const float* __restrict__ W2W){
    int idx = blockIdx.x*256 + threadIdx.x;
    if (idx >= NE_*NK_*D_) return;
    int row = idx / D_, n = idx - row*D_;
    int e = row >> 6;
    g_z2[idx] += g_EW2a[e*D_ + n] + g_n2[row]*W2W[(size_t)1536*D_ + n];
}

__global__ void k_add3(const float* __restrict__ W3W){
    int idx = blockIdx.x*256 + threadIdx.x;
    if (idx >= NE_*NC_*D_) return;
    int row = idx / D_, n = idx - row*D_;
    int e = row >> 8, c = row & 255;
    g_z3[idx] += g_EW3a[e*D_ + n] + g_CW3b[c*D_ + n] + g_disW3[c*D_ + n]
               + g_n3[row]*W3W[(size_t)1536*D_ + n]
               + g_of[(e<<6) + (c>>2)]*W3W[(size_t)2355*D_ + n];
}

// ---------------- BatchNorm (biased var) + lrelu ----------------
__global__ void k_bn(float* __restrict__ z, int rows){
    int e = blockIdx.x;
    int d = blockIdx.y*256 + threadIdx.x;
    size_t base = (size_t)e*rows*D_ + d;
    float s = 0.f;
    for (int r = 0; r < rows; r++) s += z[base + (size_t)r*D_];
    float m = s / (float)rows;
    float v = 0.f;
    for (int r = 0; r < rows; r++){ float t = z[base + (size_t)r*D_] - m; v += t*t; }
    v /= (float)rows;
    float inv = 1.f/sqrtf(v + 1e-5f);
    for (int r = 0; r < rows; r++){
        float t = (z[base + (size_t)r*D_] - m)*inv;
        z[base + (size_t)r*D_] = lrelu(t);
    }
}

// ---------------- 2-class head ----------------
__global__ void k_head(const float* __restrict__ Hx, const float* __restrict__ W,
                       const float* __restrict__ b2, float* __restrict__ out,
                       float* __restrict__ of, int rows){
    int warp = threadIdx.x >> 5, lane = threadIdx.x & 31;
    int row = blockIdx.x*8 + warp; if (row >= rows) return;
    const float* h = Hx + (size_t)row*D_;
    const float2* Wv = (const float2*)W;
    float a0 = 0.f, a1 = 0.f;
    for (int k = lane; k < D_; k += 32){
        float hv = h[k]; float2 w = Wv[k];
        a0 += hv*w.x; a1 += hv*w.y;
    }
    #pragma unroll
    for (int s = 16; s; s >>= 1){
        a0 += __shfl_down_sync(0xffffffffu, a0, s);
        a1 += __shfl_down_sync(0xffffffffu, a1, s);
    }
    if (!lane){
        float l0 = a0 + b2[0], l1 = a1 + b2[1];
        float m = fmaxf(l0, l1);
        float lse = m + logf(expf(l0-m) + expf(l1-m));
        out[row*2]   = l0 - lse;
        out[row*2+1] = l1 - lse;
        if (of) of[row] = (l1 > l0) ? 1.f : 0.f;
    }
}

// ---------------- L indicator ----------------
__global__ void k_L(const int* __restrict__ lab, float* __restrict__ out){
    int e = blockIdx.x, c = threadIdx.x;
    int a = lab[e*3], b = lab[e*3+1], d = lab[e*3+2];
    out[e*NC_ + c] = (a == c || b == c || d == c) ? 1.f : 0.f;
}

// ---------------- orchestration ----------------
extern "C" void kernel_launch(void* const* d_in, const int* in_sizes, int n_in,
                              void* d_out, int out_size){
    const float* word = (const float*)d_in[0];
    const float* pos  = (const float*)d_in[1];
    const float* dis  = (const float*)d_in[2];
    const float* WihF = (const float*)d_in[3];
    const float* WhhF = (const float*)d_in[4];
    const float* bihF = (const float*)d_in[5];
    const float* bhhF = (const float*)d_in[6];
    const float* WihB = (const float*)d_in[7];
    const float* WhhB = (const float*)d_in[8];
    const float* bihB = (const float*)d_in[9];
    const float* bhhB = (const float*)d_in[10];
    const float* s1W  = (const float*)d_in[11];
    const float* s1b  = (const float*)d_in[12];
    const float* s2W  = (const float*)d_in[13];
    const float* repW = (const float*)d_in[14];
    const float* repb = (const float*)d_in[15];
    const float* W2W  = (const float*)d_in[16];
    const float* W2b  = (const float*)d_in[17];
    const float* WoW  = (const float*)d_in[18];
    const float* Wob  = (const float*)d_in[19];
    const float* W3W  = (const float*)d_in[20];
    const float* W3b  = (const float*)d_in[21];
    const float* clsW = (const float*)d_in[22];
    const float* clsb = (const float*)d_in[23];
    const int* slen   = (const int*)d_in[24];
    const int* emo    = (const int*)d_in[25];
    const int* cau    = (const int*)d_in[26];
    const int* lab    = (const int*)d_in[27];
    float* out = (float*)d_out;

    cudaFuncSetAttribute(bgemm<false,true >, cudaFuncAttributeMaxDynamicSharedMemorySize, BGS_);
    cudaFuncSetAttribute(bgemm<false,false>, cudaFuncAttributeMaxDynamicSharedMemorySize, BGS_);

    void *p_xall,*p_Hs,*p_t1,*p_U,*p_R,*p_E,*p_Cu,*p_cE;
    void *p_z2,*p_z3,*p_EW2a,*p_EW3a,*p_CW3b,*p_disW3,*p_bm,*p_zero,*p_of;
    void *p_WcT,*p_W2yT,*p_W2eyT,*p_W3cT;
    void *p_A1,*p_A2,*p_A3,*p_B1,*p_B2,*p_B3;
    cudaGetSymbolAddress(&p_xall, g_xall);
    cudaGetSymbolAddress(&p_Hs,   g_Hs);
    cudaGetSymbolAddress(&p_t1,   g_t1);
    cudaGetSymbolAddress(&p_U,    g_U);
    cudaGetSymbolAddress(&p_R,    g_R);
    cudaGetSymbolAddress(&p_E,    g_E);
    cudaGetSymbolAddress(&p_Cu,   g_Cu);
    cudaGetSymbolAddress(&p_cE,   g_cE);
    cudaGetSymbolAddress(&p_z2,   g_z2);
    cudaGetSymbolAddress(&p_z3,   g_z3);
    cudaGetSymbolAddress(&p_EW2a, g_EW2a);
    cudaGetSymbolAddress(&p_EW3a, g_EW3a);
    cudaGetSymbolAddress(&p_CW3b, g_CW3b);
    cudaGetSymbolAddress(&p_disW3,g_disW3);
    cudaGetSymbolAddress(&p_bm,   g_bm);
    cudaGetSymbolAddress(&p_zero, g_zero);
    cudaGetSymbolAddress(&p_of,   g_of);
    cudaGetSymbolAddress(&p_WcT,  g_WcT);
    cudaGetSymbolAddress(&p_W2yT, g_W2yT);
    cudaGetSymbolAddress(&p_W2eyT,g_W2eyT);
    cudaGetSymbolAddress(&p_W3cT, g_W3cT);
    cudaGetSymbolAddress(&p_A1, g_A1);
    cudaGetSymbolAddress(&p_A2, g_A2);
    cudaGetSymbolAddress(&p_A3, g_A3);
    cudaGetSymbolAddress(&p_B1, g_B1);
    cudaGetSymbolAddress(&p_B2, g_B2);
    cudaGetSymbolAddress(&p_B3, g_B3);

    __nv_bfloat16 *A1 = (__nv_bfloat16*)p_A1, *A2 = (__nv_bfloat16*)p_A2,
                  *A3 = (__nv_bfloat16*)p_A3, *B1 = (__nv_bfloat16*)p_B1,
                  *B2 = (__nv_bfloat16*)p_B2, *B3 = (__nv_bfloat16*)p_B3;

    auto splitA = [&](const float* src, int n){
        k_split<<<(n + 255)/256, 256>>>(src, A1, A2, A3, n);
    };
    auto splitB = [&](const float* src, int n){
        k_split<<<(n + 255)/256, 256>>>(src, B1, B2, B3, n);
    };

    dim3 tb(32, 8);
    dim3 tg(D_/32, D_/32);

    // prep
    k_prep<<<B_, T_>>>(slen);
    k_biasM<<<(G2_ + 255)/256, 256>>>(bihF, bhhF, bihB, bhhB);
    k_zero<<<(2*2*B_*H_ + 255)/256, 256>>>();
    k_transT<<<tg, tb>>>(W2W + (size_t)768*D_,  (float*)p_W2yT);
    k_transT<<<tg, tb>>>(W2W + (size_t)1537*D_, (float*)p_W2eyT);
    k_transT<<<tg, tb>>>(W3W + (size_t)1537*D_, (float*)p_W3cT);
    k_transWM<<<dim3(D_/32, G_/32), tb>>>(WihF, 0);
    k_transWM<<<dim3(D_/32, G_/32), tb>>>(WihB, G_);

    // UPSTREAM (fp32): merged input projection, N=3072
    sgemmF<false,false><<<dim3(G2_/128, BT_/128), 256>>>(word, (const float*)p_WcT,
        (const float*)p_bm, (float*)p_xall, BT_, G2_, D_);

    // recurrence (writes g_Hs directly; backward uses rev-indexed x and h rows)
    for (int t = 0; t < T_; t++)
        k_lstm2<<<dim3(B_/32, H_/32, 2), 128>>>(WhhF, WhhB, t);

    // attention pooling — fp32
    sgemmF<true,false><<<dim3(D_/128, BT_/128), 256>>>((const float*)p_Hs, s1W, s1b,
        (float*)p_t1, BT_, D_, D_);
    k_e<<<BT_/8, 256>>>(s2W);
    k_u<<<B_, 256>>>(slen);

    // shared representation — fp32 (small; skips split overhead)
    sgemmF<true,false><<<dim3(D_/128, B_/128), 256>>>((const float*)p_U, repW, repb,
        (float*)p_R, B_, D_, D_);
    k_gatherR<<<(NC_*D_ + 255)/256, 256>>>(emo, cau);

    // phase 2
    k_chunk<<<NE_*NK_, 256>>>();
    sgemm64<false,false><<<dim3(D_/64, (NE_*NK_)/64), 256>>>(pos, W2W + (size_t)2305*D_,
        W2b, (float*)p_z2, NE_*NK_, D_, POS_, D_);
    splitA((const float*)p_cE, NE_*NK_*D_); splitB((const float*)p_W2yT, D_*D_);
    bgemm<false,true><<<dim3(D_/128, (NE_*NK_)/128), 256, BGS_>>>(A1,A2,A3, B1,B2,B3,
        (const float*)p_zero, (float*)p_z2, NE_*NK_, D_, D_);
    k_EYsplit<<<NE_*NK_, 256>>>(A1, A2, A3);
    splitB((const float*)p_W2eyT, D_*D_);
    bgemm<false,true><<<dim3(D_/128, (NE_*NK_)/128), 256, BGS_>>>(A1,A2,A3, B1,B2,B3,
        (const float*)p_zero, (float*)p_z2, NE_*NK_, D_, D_);
    // EW2a = E @ W2W[0:768,:]  (already [K,N], NN)
    sgemm64<false,false><<<dim3(D_/64, (NE_+63)/64), 256>>>((const float*)p_E, W2W,
        (const float*)p_zero, (float*)p_EW2a, NE_, D_, D_, D_);
    k_add2<<<(NE_*NK_*D_ + 255)/256, 256>>>(W2W);
    k_bn<<<dim3(NE_, 3), 256>>>((float*)p_z2, NK_);
    k_head<<<(NE_*NK_)/8, 256>>>((const float*)p_z2, WoW, Wob, out, (float*)p_of, NE_*NK_);

    // phase 3
    k_ECsplit<<<NE_*NC_, 256>>>(A1, A2, A3);
    splitB((const float*)p_W3cT, D_*D_);
    bgemm<false,false><<<dim3(D_/128, (NE_*NC_)/128), 256, BGS_>>>(A1,A2,A3, B1,B2,B3,
        W3b, (float*)p_z3, NE_*NC_, D_, D_);
    sgemm64<false,false><<<dim3(D_/64, (NE_+63)/64), 256>>>((const float*)p_E, W3W,
        (const float*)p_zero, (float*)p_EW3a, NE_, D_, D_, D_);
    sgemm64<false,false><<<dim3(D_/64, (NC_+63)/64), 256>>>((const float*)p_Cu,
        W3W + (size_t)768*D_, (const float*)p_zero, (float*)p_CW3b, NC_, D_, D_, D_);
    sgemm64<false,false><<<dim3(D_/64, (NC_+63)/64), 256>>>(dis, W3W + (size_t)2305*D_,
        (const float*)p_zero, (float*)p_disW3, NC_, D_, POS_, D_);
    k_add3<<<(NE_*NC_*D_ + 255)/256, 256>>>(W3W);
    k_bn<<<dim3(NE_, 3), 256>>>((float*)p_z3, NC_);
    k_head<<<(NE_*NC_)/8, 256>>>((const float*)p_z3, clsW, clsb,
        out + NE_*NK_*2, nullptr, NE_*NC_);

    // L indicator
    k_L<<<NE_, NC_>>>(lab, out + NE_*NK_*2 + NE_*NC_*2);
}

// round 14
// speedup vs baseline: 1.8844x; 1.0089x over previous
#include <cuda_runtime.h>
#include <cuda_bf16.h>
#include <math.h>
#include <stdint.h>
#include <stddef.h>

// ---------------- problem dims ----------------
#define B_   256
#define T_   96
#define D_   768
#define H_   384
#define G_   1536          // 4*H
#define G2_  3072          // both directions merged
#define BT_  (B_*T_)       // 24576
#define NE_  128
#define NC_  256
#define NK_  64
#define POS_ 50
#define AMAX_ ((size_t)NE_*NC_*D_)
#define BMAX_ ((size_t)D_*D_)

// ---------------- scratch ----------------
__device__ float g_xall[(size_t)BT_*G2_];   // merged gate pre-activations
__device__ float g_hbuf[2][2][B_*H_];
__device__ float g_cbuf[2][B_*H_];
__device__ float g_Hs[BT_*D_];
__device__ float g_t1[BT_*D_];
__device__ float g_e[BT_];
__device__ float g_U[B_*D_];
__device__ float g_R[NC_*D_];
__device__ float g_E[NE_*D_];
__device__ float g_Cu[NC_*D_];
__device__ float g_cE[NE_*NK_*D_];
__device__ float g_n2[NE_*NK_];
__device__ float g_n3[NE_*NC_];
__device__ float g_z2[NE_*NK_*D_];
__device__ float g_z3[NE_*NC_*D_];
__device__ float g_EW2a[NE_*D_];
__device__ float g_EW3a[NE_*D_];
__device__ float g_CW3b[NC_*D_];
__device__ float g_disW3[NC_*D_];
__device__ float g_of[NE_*NK_];
__device__ float g_bm[G2_];
__device__ float g_zero[G_];
__device__ int   g_rev[BT_];
__device__ float g_WcT[(size_t)D_*G2_];     // [768, 3072] merged Wih^T
__device__ float g_W2yT [D_*D_];
__device__ float g_W2eyT[D_*D_];
__device__ float g_W3cT [D_*D_];
__device__ __nv_bfloat16 g_A1[AMAX_];
__device__ __nv_bfloat16 g_A2[AMAX_];
__device__ __nv_bfloat16 g_A3[AMAX_];
__device__ __nv_bfloat16 g_B1[BMAX_];
__device__ __nv_bfloat16 g_B2[BMAX_];
__device__ __nv_bfloat16 g_B3[BMAX_];

__device__ __forceinline__ float lrelu(float x){ return x >= 0.f ? x : 0.01f*x; }
__device__ __forceinline__ float sigm(float x){ return 1.f/(1.f+expf(-x)); }

__device__ __forceinline__ void split3(float a, __nv_bfloat16& x1,
                                       __nv_bfloat16& x2, __nv_bfloat16& x3){
    x1 = __float2bfloat16(a);
    float r = a - __bfloat162float(x1);
    x2 = __float2bfloat16(r);
    float r2 = r - __bfloat162float(x2);
    x3 = __float2bfloat16(r2);
}

#define MMAB(C, A0,A1,A2,A3, B0,B1) \
    asm volatile("mma.sync.aligned.m16n8k16.row.col.f32.bf16.bf16.f32 " \
        "{%0,%1,%2,%3}, {%4,%5,%6,%7}, {%8,%9}, {%0,%1,%2,%3};" \
        : "+f"((C)[0]),"+f"((C)[1]),"+f"((C)[2]),"+f"((C)[3]) \
        : "r"(A0),"r"(A1),"r"(A2),"r"(A3),"r"(B0),"r"(B1))

// ---------------- fp32 SGEMM (UPSTREAM; exact-tile 128x128x16) ----------------
template<bool RELU, bool ACC>
__global__ __launch_bounds__(256, 2)
void sgemmF(const float* __restrict__ A, const float* __restrict__ Bm,
            const float* __restrict__ bias, float* __restrict__ Cm,
            int M, int N, int K){
    __shared__ float As[2][16][136];
    __shared__ float Bs[2][16][128];
    const int tid = threadIdx.x;
    const int bm = blockIdx.y << 7, bn = blockIdx.x << 7;
    const int tx = tid & 15, ty = tid >> 4;

    const int am0 = tid >> 2, ak0 = (tid & 3) << 2;
    const int am1 = am0 + 64;
    const int bk0 = tid >> 5, bn0 = (tid & 31) << 2;
    const int bk1 = bk0 + 8;

    float4 ra0, ra1, rb0, rb1;
    float acc[8][8];
    #pragma unroll
    for (int i = 0; i < 8; i++)
        #pragma unroll
        for (int j = 0; j < 8; j++) acc[i][j] = 0.f;

    auto loadRegs = [&](int k0){
        ra0 = *(const float4*)(A  + (size_t)(bm+am0)*K + k0 + ak0);
        ra1 = *(const float4*)(A  + (size_t)(bm+am1)*K + k0 + ak0);
        rb0 = *(const float4*)(Bm + (size_t)(k0+bk0)*N + bn + bn0);
        rb1 = *(const float4*)(Bm + (size_t)(k0+bk1)*N + bn + bn0);
    };
    auto storeSmem = [&](int buf){
        As[buf][ak0+0][am0] = ra0.x; As[buf][ak0+1][am0] = ra0.y;
        As[buf][ak0+2][am0] = ra0.z; As[buf][ak0+3][am0] = ra0.w;
        As[buf][ak0+0][am1] = ra1.x; As[buf][ak0+1][am1] = ra1.y;
        As[buf][ak0+2][am1] = ra1.z; As[buf][ak0+3][am1] = ra1.w;
        *(float4*)&Bs[buf][bk0][bn0] = rb0;
        *(float4*)&Bs[buf][bk1][bn0] = rb1;
    };

    loadRegs(0); storeSmem(0); __syncthreads();
    const int ntk = K >> 4;
    for (int kt = 0; kt < ntk; kt++){
        if (kt + 1 < ntk) loadRegs((kt+1) << 4);
        const int buf = kt & 1;
        #pragma unroll
        for (int kk = 0; kk < 16; kk++){
            float4 a0 = *(const float4*)&As[buf][kk][ty<<2];
            float4 a1 = *(const float4*)&As[buf][kk][(ty<<2)+64];
            float4 b0 = *(const float4*)&Bs[buf][kk][tx<<2];
            float4 b1 = *(const float4*)&Bs[buf][kk][(tx<<2)+64];
            float av[8] = {a0.x,a0.y,a0.z,a0.w,a1.x,a1.y,a1.z,a1.w};
            float bv[8] = {b0.x,b0.y,b0.z,b0.w,b1.x,b1.y,b1.z,b1.w};
            #pragma unroll
            for (int i = 0; i < 8; i++)
                #pragma unroll
                for (int j = 0; j < 8; j++) acc[i][j] += av[i]*bv[j];
        }
        if (kt + 1 < ntk) storeSmem(buf ^ 1);
        __syncthreads();
    }
    #pragma unroll
    for (int i = 0; i < 8; i++){
        int m = bm + (ty<<2) + (i&3) + ((i>>2)<<6);
        size_t base = (size_t)m*N;
        #pragma unroll
        for (int jg = 0; jg < 2; jg++){
            int n0 = bn + (tx<<2) + (jg<<6);
            float4 v;
            if (ACC) v = *(const float4*)&Cm[base + n0];
            else     v = *(const float4*)&bias[n0];
            v.x += acc[i][jg*4+0]; v.y += acc[i][jg*4+1];
            v.z += acc[i][jg*4+2]; v.w += acc[i][jg*4+3];
            if (RELU){ v.x = lrelu(v.x); v.y = lrelu(v.y); v.z = lrelu(v.z); v.w = lrelu(v.w); }
            *(float4*)&Cm[base + n0] = v;
        }
    }
}

// ---------------- fp32 -> 3x bf16 split ----------------
__global__ void k_split(const float* __restrict__ src,
                        __nv_bfloat16* __restrict__ p1,
                        __nv_bfloat16* __restrict__ p2,
                        __nv_bfloat16* __restrict__ p3, int n){
    int i = blockIdx.x*256 + threadIdx.x;
    if (i >= n) return;
    __nv_bfloat16 h1, h2, h3;
    split3(src[i], h1, h2, h3);
    p1[i] = h1; p2[i] = h2; p3[i] = h3;
}

// ============ bf16x6 GEMM (big downstream GEMMs) ==========
#define BGP_  10240
#define BGS_  67584

template<bool RELU, bool ACC>
__global__ void __launch_bounds__(256)
bgemm(const __nv_bfloat16* __restrict__ A1, const __nv_bfloat16* __restrict__ A2,
      const __nv_bfloat16* __restrict__ A3, const __nv_bfloat16* __restrict__ Bt1,
      const __nv_bfloat16* __restrict__ Bt2, const __nv_bfloat16* __restrict__ Bt3,
      const float* __restrict__ bias, float* __restrict__ Cm,
      int M, int N, int K){
    extern __shared__ char sm[];
    const int tid = threadIdx.x, warp = tid >> 5, lane = tid & 31;
    const int gid = lane >> 2, tig = lane & 3;
    const int bm = blockIdx.y << 7, bn = blockIdx.x << 7;
    const int wm = (warp & 1) << 6, wn = (warp >> 1) << 5;

    const __nv_bfloat16* Ap[3] = {A1, A2, A3};
    const __nv_bfloat16* Bp[3] = {Bt1, Bt2, Bt3};

    float acc[4][4][4];
    #pragma unroll
    for (int i = 0; i < 4; i++)
        #pragma unroll
        for (int j = 0; j < 4; j++)
            #pragma unroll
            for (int q = 0; q < 4; q++) acc[i][j][q] = 0.f;

    for (int k0 = 0; k0 < K; k0 += 32){
        __syncthreads();
        for (int idx = tid; idx < 128*16; idx += 256){
            int r = idx >> 4, kq = idx & 15;
            size_t ga = (((size_t)(bm + r)*K + k0) >> 1) + kq;
            size_t gb = (((size_t)(bn + r)*K + k0) >> 1) + kq;
            uint32_t so = (uint32_t)(r*80 + kq*4);
            #pragma unroll
            for (int p = 0; p < 3; p++){
                *(uint32_t*)(sm + p*BGP_ + so)           = ((const uint32_t*)Ap[p])[ga];
                *(uint32_t*)(sm + 3*BGP_ + p*BGP_ + so)  = ((const uint32_t*)Bp[p])[gb];
            }
        }
        __syncthreads();
        #pragma unroll
        for (int s = 0; s < 2; s++){
            uint32_t bfr[3][4][2];
            #pragma unroll
            for (int p = 0; p < 3; p++)
                #pragma unroll
                for (int nt = 0; nt < 4; nt++){
                    int n = wn + (nt << 3) + gid;
                    const char* bb = sm + 3*BGP_ + p*BGP_ + n*80 + s*32 + tig*4;
                    bfr[p][nt][0] = *(const uint32_t*)bb;
                    bfr[p][nt][1] = *(const uint32_t*)(bb + 16);
                }
            #pragma unroll
            for (int pa = 0; pa < 3; pa++){
                #pragma unroll
                for (int mt = 0; mt < 4; mt++){
                    int r = wm + (mt << 4) + gid;
                    const char* ab = sm + pa*BGP_ + r*80 + s*32 + tig*4;
                    uint32_t a0 = *(const uint32_t*)ab;
                    uint32_t a1 = *(const uint32_t*)(ab + 640);
                    uint32_t a2 = *(const uint32_t*)(ab + 16);
                    uint32_t a3 = *(const uint32_t*)(ab + 656);
                    if (pa == 0){
                        #pragma unroll
                        for (int nt = 0; nt < 4; nt++){
                            MMAB(acc[mt][nt], a0,a1,a2,a3, bfr[0][nt][0], bfr[0][nt][1]);
                            MMAB(acc[mt][nt], a0,a1,a2,a3, bfr[1][nt][0], bfr[1][nt][1]);
                            MMAB(acc[mt][nt], a0,a1,a2,a3, bfr[2][nt][0], bfr[2][nt][1]);
                        }
                    } else if (pa == 1){
                        #pragma unroll
                        for (int nt = 0; nt < 4; nt++){
                            MMAB(acc[mt][nt], a0,a1,a2,a3, bfr[0][nt][0], bfr[0][nt][1]);
                            MMAB(acc[mt][nt], a0,a1,a2,a3, bfr[1][nt][0], bfr[1][nt][1]);
                        }
                    } else {
                        #pragma unroll
                        for (int nt = 0; nt < 4; nt++)
                            MMAB(acc[mt][nt], a0,a1,a2,a3, bfr[0][nt][0], bfr[0][nt][1]);
                    }
                }
            }
        }
    }
    __syncthreads();
    float* fs = (float*)sm;
    #pragma unroll
    for (int mt = 0; mt < 4; mt++){
        int r0 = wm + (mt << 4) + gid;
        #pragma unroll
        for (int nt = 0; nt < 4; nt++){
            int c = wn + (nt << 3) + (tig << 1);
            fs[r0*132 + c]       = acc[mt][nt][0];
            fs[r0*132 + c + 1]   = acc[mt][nt][1];
            fs[(r0+8)*132 + c]   = acc[mt][nt][2];
            fs[(r0+8)*132 + c+1] = acc[mt][nt][3];
        }
    }
    __syncthreads();
    for (int i = tid; i < 128*128; i += 256){
        int r = i >> 7, c = i & 127;
        float v = fs[r*132 + c];
        float* dst = Cm + (size_t)(bm + r)*N + bn + c;
        float base = ACC ? *dst : bias[bn + c];
        v += base;
        if (RELU) v = lrelu(v);
        *dst = v;
    }
}

// ---------------- prep ----------------
__global__ void k_prep(const int* __restrict__ slen){
    int b = blockIdx.x, t = threadIdx.x;
    int len = slen[b];
    g_rev[b*T_ + t] = (t < len) ? (len - 1 - t) : t;
}

__global__ void k_biasM(const float* bihf, const float* bhhf,
                        const float* bihb, const float* bhhb){
    int i = blockIdx.x*256 + threadIdx.x;
    if (i < G_)       g_bm[i]      = bihf[i] + bhhf[i];
    else if (i < G2_) g_bm[i]      = bihb[i-G_] + bhhb[i-G_];
}

__global__ void k_zero(){
    int i = blockIdx.x*256 + threadIdx.x;
    if (i < 2*2*B_*H_) (&g_hbuf[0][0][0])[i] = 0.f;
    if (i < 2*B_*H_)   (&g_cbuf[0][0])[i]    = 0.f;
}

// 768x768 block transpose
__global__ void k_transT(const float* __restrict__ src, float* __restrict__ dst){
    __shared__ float t[32][33];
    int r0 = blockIdx.y*32, c0 = blockIdx.x*32;
    int tx = threadIdx.x, ty = threadIdx.y;
    #pragma unroll
    for (int q = 0; q < 32; q += 8)
        t[ty+q][tx] = src[(size_t)(r0+ty+q)*D_ + c0+tx];
    __syncthreads();
    #pragma unroll
    for (int q = 0; q < 32; q += 8)
        dst[(size_t)(c0+ty+q)*D_ + r0+tx] = t[tx][ty+q];
}

// Wih [G,D] -> merged [D, G2] at column offset
__global__ void k_transWM(const float* __restrict__ src, int colOff){
    __shared__ float t[32][33];
    int k0 = blockIdx.x*32, n0 = blockIdx.y*32;
    int tx = threadIdx.x, ty = threadIdx.y;
    #pragma unroll
    for (int q = 0; q < 32; q += 8)
        t[ty+q][tx] = src[(size_t)(n0+ty+q)*D_ + k0+tx];
    __syncthreads();
    #pragma unroll
    for (int q = 0; q < 32; q += 8)
        g_WcT[(size_t)(k0+ty+q)*G2_ + colOff + n0+tx] = t[tx][ty+q];
}

// ---------------- small-K SGEMM (guards), 64x64 ----------------
template<bool TB, bool RELU>
__global__ void sgemm64(const float* __restrict__ A, const float* __restrict__ Bm,
                        const float* __restrict__ bias, float* __restrict__ Cm,
                        int M, int N, int K, int ldb){
    __shared__ float As[16][65];
    __shared__ float Bs[16][65];
    int bm = blockIdx.y << 6, bn = blockIdx.x << 6;
    int tid = threadIdx.x;
    int tx = tid & 15, ty = tid >> 4;
    float acc[4][4];
    #pragma unroll
    for (int i = 0; i < 4; i++)
        #pragma unroll
        for (int j = 0; j < 4; j++) acc[i][j] = 0.f;
    int arow = tid >> 2, ak0 = (tid & 3) << 2;
    for (int k0 = 0; k0 < K; k0 += 16){
        #pragma unroll
        for (int q = 0; q < 4; q++){
            int kk = ak0 + q, gm = bm + arow, gk = k0 + kk;
            As[kk][arow] = (gm < M && gk < K) ? A[(size_t)gm*K + gk] : 0.f;
        }
        {
            int kr = tid >> 4, nc0 = (tid & 15) << 2;
            #pragma unroll
            for (int q = 0; q < 4; q++){
                int n = nc0 + q, gk = k0 + kr, gn = bn + n;
                Bs[kr][n] = (gk < K && gn < N) ? Bm[(size_t)gk*ldb + gn] : 0.f;
            }
        }
        __syncthreads();
        #pragma unroll
        for (int kk = 0; kk < 16; kk++){
            float a[4], b[4];
            #pragma unroll
            for (int i = 0; i < 4; i++) a[i] = As[kk][ty + (i<<4)];
            #pragma unroll
            for (int j = 0; j < 4; j++) b[j] = Bs[kk][tx + (j<<4)];
            #pragma unroll
            for (int i = 0; i < 4; i++)
                #pragma unroll
                for (int j = 0; j < 4; j++) acc[i][j] += a[i]*b[j];
        }
        __syncthreads();
    }
    #pragma unroll
    for (int i = 0; i < 4; i++){
        int gm = bm + ty + (i<<4); if (gm >= M) continue;
        #pragma unroll
        for (int j = 0; j < 4; j++){
            int gn = bn + tx + (j<<4); if (gn >= N) continue;
            float v = acc[i][j] + bias[gn];
            if (RELU) v = lrelu(v);
            Cm[(size_t)gm*N + gn] = v;
        }
    }
}

// ---------------- fused LSTM step, k-split x2 (256 thr) ----------------------
// tz = k-half; each half accumulates K in [tz*192,(tz+1)*192), then half-1
// spills partials via smem and half-0 adds + runs the epilogue.
__global__ void __launch_bounds__(256)
k_lstm3(const float* __restrict__ WhhF, const float* __restrict__ WhhB, int t){
    int dir = blockIdx.z;
    const float* Whh = dir ? WhhB : WhhF;
    const float* hp  = g_hbuf[dir][t & 1];
    float* hn        = g_hbuf[dir][(t & 1) ^ 1];
    float* cc        = g_cbuf[dir];

    int bBase = blockIdx.x << 5, jBase = blockIdx.y << 5;
    int tid = threadIdx.x;
    int tz = tid >> 7, tl = tid & 127;
    int tx = tl & 15, ty = tl >> 4;

    __shared__ float shh[2][32][17];
    __shared__ float shw[2][4][16][33];
    __shared__ float red[128][33];

    float acc[4][4][2];
    #pragma unroll
    for (int a = 0; a < 4; a++)
        #pragma unroll
        for (int g = 0; g < 4; g++){ acc[a][g][0]=0.f; acc[a][g][1]=0.f; }

    const int kcBase = tz * (H_/2);
    for (int c = 0; c < (H_/2)/16; c++){
        int kc = kcBase + c*16;
        #pragma unroll
        for (int q = 0; q < 4; q++){
            int e = tl + 128*q;
            int bl = e >> 4, kk = e & 15;
            shh[tz][bl][kk] = hp[(bBase + bl)*H_ + kc + kk];
        }
        #pragma unroll
        for (int q = 0; q < 16; q++){
            int e = tl + 128*q;
            int g = e >> 9, rem = e & 511;
            int jl = rem >> 4, kk = rem & 15;
            shw[tz][g][kk][jl] = Whh[(size_t)(g*H_ + jBase + jl)*H_ + kc + kk];
        }
        __syncthreads();
        #pragma unroll
        for (int kk = 0; kk < 16; kk++){
            float hv[4];
            #pragma unroll
            for (int bb = 0; bb < 4; bb++) hv[bb] = shh[tz][(ty<<2)+bb][kk];
            #pragma unroll
            for (int g = 0; g < 4; g++){
                float w0 = shw[tz][g][kk][(tx<<1)];
                float w1 = shw[tz][g][kk][(tx<<1)+1];
                #pragma unroll
                for (int bb = 0; bb < 4; bb++){
                    acc[bb][g][0] += hv[bb]*w0;
                    acc[bb][g][1] += hv[bb]*w1;
                }
            }
        }
        __syncthreads();
    }

    // half-1 spills its partials
    if (tz == 1){
        #pragma unroll
        for (int bb = 0; bb < 4; bb++)
            #pragma unroll
            for (int g = 0; g < 4; g++){
                red[tl][bb*8 + g*2 + 0] = acc[bb][g][0];
                red[tl][bb*8 + g*2 + 1] = acc[bb][g][1];
            }
    }
    __syncthreads();
    if (tz == 0){
        #pragma unroll
        for (int bb = 0; bb < 4; bb++)
            #pragma unroll
            for (int g = 0; g < 4; g++){
                acc[bb][g][0] += red[tl][bb*8 + g*2 + 0];
                acc[bb][g][1] += red[tl][bb*8 + g*2 + 1];
            }
        #pragma unroll
        for (int bb = 0; bb < 4; bb++){
            int b = bBase + (ty<<2) + bb;
            int rid = g_rev[b*T_ + t];
            const float* xrow = g_xall + (size_t)(b*T_ + (dir ? rid : t))*G2_ + (dir ? G_ : 0);
            float* hsrow = g_Hs + (size_t)(b*T_ + (dir ? rid : t))*D_ + (dir ? H_ : 0);
            #pragma unroll
            for (int jj = 0; jj < 2; jj++){
                int j = jBase + (tx<<1) + jj;
                float gi = acc[bb][0][jj] + xrow[j];
                float gf = acc[bb][1][jj] + xrow[H_ + j];
                float gg = acc[bb][2][jj] + xrow[2*H_ + j];
                float go = acc[bb][3][jj] + xrow[3*H_ + j];
                float cold = cc[b*H_ + j];
                float cn = sigm(gf)*cold + sigm(gi)*tanhf(gg);
                float hv = sigm(go)*tanhf(cn);
                cc[b*H_ + j] = cn;
                hn[b*H_ + j] = hv;
                hsrow[j] = hv;
            }
        }
    }
}

// ---------------- e = t1 @ s2 ----------------
__global__ void k_e(const float* __restrict__ s2){
    int warp = threadIdx.x >> 5, lane = threadIdx.x & 31;
    int row = blockIdx.x*8 + warp; if (row >= BT_) return;
    const float* h = g_t1 + (size_t)row*D_;
    float a = 0.f;
    for (int k = lane; k < D_; k += 32) a += h[k]*s2[k];
    #pragma unroll
    for (int s = 16; s; s >>= 1) a += __shfl_down_sync(0xffffffffu, a, s);
    if (!lane) g_e[row] = a;
}

// ---------------- masked pooling ----------------
__global__ void k_u(const int* __restrict__ slen){
    __shared__ float al[T_];
    __shared__ float red[256];
    int b = blockIdx.x, tid = threadIdx.x;
    int len = slen[b];
    float v = 0.f;
    if (tid < T_){ v = (tid < len) ? g_e[b*T_ + tid] : 0.f; al[tid] = v; }
    red[tid] = v; __syncthreads();
    for (int s = 128; s; s >>= 1){ if (tid < s) red[tid] += red[tid+s]; __syncthreads(); }
    float denom = red[0] + 1e-9f;
    __syncthreads();
    if (tid < T_) al[tid] = al[tid] / denom;
    __syncthreads();
    for (int d = tid; d < D_; d += 256){
        float acc = 0.f;
        for (int t = 0; t < T_; t++) acc += al[t]*g_Hs[(size_t)(b*T_ + t)*D_ + d];
        g_U[b*D_ + d] = acc;
    }
}

// ---------------- gather E / Cu rows ----------------
__global__ void k_gatherR(const int* __restrict__ emo, const int* __restrict__ cau){
    int i = blockIdx.x*256 + threadIdx.x;
    if (i < NE_*D_){ int r = i / D_, d = i - r*D_; g_E[i]  = g_R[(size_t)emo[r]*D_ + d]; }
    if (i < NC_*D_){ int r = i / D_, d = i - r*D_; g_Cu[i] = g_R[(size_t)cau[r]*D_ + d]; }
}

// ---------------- per-chunk cross attention ----------------
__global__ void k_chunk(){
    __shared__ float Esh[D_];
    __shared__ float red[256];
    __shared__ float scs[4];
    int blk = blockIdx.x, tid = threadIdx.x;
    int e = blk >> 6, k = blk & 63;
    const float* Er = g_E + (size_t)e*D_;
    for (int d = tid; d < D_; d += 256) Esh[d] = Er[d];
    __syncthreads();
    float dots[4];
    for (int c = 0; c < 4; c++){
        const float* Cr = g_Cu + (size_t)(k*4 + c)*D_;
        float a = 0.f;
        for (int d = tid; d < D_; d += 256) a += Esh[d]*Cr[d];
        red[tid] = a; __syncthreads();
        for (int s = 128; s; s >>= 1){ if (tid < s) red[tid] += red[tid+s]; __syncthreads(); }
        dots[c] = red[0]; __syncthreads();
    }
    if (tid == 0){
        float m = fmaxf(fmaxf(dots[0],dots[1]), fmaxf(dots[2],dots[3]));
        float ex[4], s = 0.f;
        #pragma unroll
        for (int c = 0; c < 4; c++){ ex[c] = expf(dots[c]-m); s += ex[c]; }
        #pragma unroll
        for (int c = 0; c < 4; c++) scs[c] = ex[c]/s;
    }
    __syncthreads();
    const float* C0 = g_Cu + (size_t)(k*4+0)*D_;
    const float* C1 = g_Cu + (size_t)(k*4+1)*D_;
    const float* C2 = g_Cu + (size_t)(k*4+2)*D_;
    const float* C3 = g_Cu + (size_t)(k*4+3)*D_;
    float s0 = scs[0], s1 = scs[1], s2 = scs[2], s3 = scs[3];
    for (int d = tid; d < D_; d += 256)
        g_cE[(size_t)blk*D_ + d] = s0*C0[d] + s1*C1[d] + s2*C2[d] + s3*C3[d];
}

// ---------------- EY = E⊙Y: split planes + nrm2 ----------------
__global__ void k_EYsplit(__nv_bfloat16* __restrict__ p1,
                          __nv_bfloat16* __restrict__ p2,
                          __nv_bfloat16* __restrict__ p3){
    __shared__ float red[256];
    int row = blockIdx.x, tid = threadIdx.x;
    int e = row >> 6;
    const float* Er = g_E + (size_t)e*D_;
    const float* Y  = g_cE + (size_t)row*D_;
    float a = 0.f;
    for (int d = tid; d < D_; d += 256){
        float ev = Er[d], yv = Y[d];
        float df = ev - yv; a += df*df;
        __nv_bfloat16 h1, h2, h3;
        split3(ev*yv, h1, h2, h3);
        size_t idx = (size_t)row*D_ + d;
        p1[idx] = h1; p2[idx] = h2; p3[idx] = h3;
    }
    red[tid] = a; __syncthreads();
    for (int s = 128; s; s >>= 1){ if (tid < s) red[tid] += red[tid+s]; __syncthreads(); }
    if (tid == 0) g_n2[row] = sqrtf(red[0]);
}

// ---------------- EC = E⊙Cu: split planes + nrm3 ----------------
__global__ void k_ECsplit(__nv_bfloat16* __restrict__ p1,
                          __nv_bfloat16* __restrict__ p2,
                          __nv_bfloat16* __restrict__ p3){
    __shared__ float red[256];
    int row = blockIdx.x, tid = threadIdx.x;
    int e = row >> 8, c = row & 255;
    const float* Er = g_E + (size_t)e*D_;
    const float* Cr = g_Cu + (size_t)c*D_;
    float a = 0.f;
    for (int d = tid; d < D_; d += 256){
        float ev = Er[d], cv = Cr[d];
        float df = ev - cv; a += df*df;
        __nv_bfloat16 h1, h2, h3;
        split3(ev*cv, h1, h2, h3);
        size_t idx = (size_t)row*D_ + d;
        p1[idx] = h1; p2[idx] = h2; p3[idx] = h3;
    }
    red[tid] = a; __syncthreads();
    for (int s = 128; s; s >>= 1){ if (tid < s) red[tid] += red[tid+s]; __syncthreads(); }
    if (tid == 0) g_n3[row] = sqrtf(red[0]);
}

// ---------------- epilogue adds ----------------
__global__ void k_add2(const float* __restrict__ W2W){
    int idx = blockIdx.x*256 + threadIdx.x;
    if (idx >= NE_*NK_*D_) return;
    int row = idx / D_, n = idx - row*D_;
    int e = row >> 6;
    g_z2[idx] += g_EW2a[e*D_ + n] + g_n2[row]*W2W[(size_t)1536*D_ + n];
}

__global__ void k_add3(const float* __restrict__ W3W){
    int idx = blockIdx.x*256 + threadIdx.x;
    if (idx >= NE_*NC_*D_) return;
    int row = idx / D_, n = idx - row*D_;
    int e = row >> 8, c = row & 255;
    g_z3[idx] += g_EW3a[e*D_ + n] + g_CW3b[c*D_ + n] + g_disW3[c*D_ + n]
               + g_n3[row]*W3W[(size_t)1536*D_ + n]
               + g_of[(e<<6) + (c>>2)]*W3W[(size_t)2355*D_ + n];
}

// ---------------- BatchNorm (biased var) + lrelu ----------------
__global__ void k_bn(float* __restrict__ z, int rows){
    int e = blockIdx.x;
    int d = blockIdx.y*256 + threadIdx.x;
    size_t base = (size_t)e*rows*D_ + d;
    float s = 0.f;
    for (int r = 0; r < rows; r++) s += z[base + (size_t)r*D_];
    float m = s / (float)rows;
    float v = 0.f;
    for (int r = 0; r < rows; r++){ float t = z[base + (size_t)r*D_] - m; v += t*t; }
    v /= (float)rows;
    float inv = 1.f/sqrtf(v + 1e-5f);
    for (int r = 0; r < rows; r++){
        float t = (z[base + (size_t)r*D_] - m)*inv;
        z[base + (size_t)r*D_] = lrelu(t);
    }
}

// ---------------- 2-class head ----------------
__global__ void k_head(const float* __restrict__ Hx, const float* __restrict__ W,
                       const float* __restrict__ b2, float* __restrict__ out,
                       float* __restrict__ of, int rows){
    int warp = threadIdx.x >> 5, lane = threadIdx.x & 31;
    int row = blockIdx.x*8 + warp; if (row >= rows) return;
    const float* h = Hx + (size_t)row*D_;
    const float2* Wv = (const float2*)W;
    float a0 = 0.f, a1 = 0.f;
    for (int k = lane; k < D_; k += 32){
        float hv = h[k]; float2 w = Wv[k];
        a0 += hv*w.x; a1 += hv*w.y;
    }
    #pragma unroll
    for (int s = 16; s; s >>= 1){
        a0 += __shfl_down_sync(0xffffffffu, a0, s);
        a1 += __shfl_down_sync(0xffffffffu, a1, s);
    }
    if (!lane){
        float l0 = a0 + b2[0], l1 = a1 + b2[1];
        float m = fmaxf(l0, l1);
        float lse = m + logf(expf(l0-m) + expf(l1-m));
        out[row*2]   = l0 - lse;
        out[row*2+1] = l1 - lse;
        if (of) of[row] = (l1 > l0) ? 1.f : 0.f;
    }
}

// ---------------- L indicator ----------------
__global__ void k_L(const int* __restrict__ lab, float* __restrict__ out){
    int e = blockIdx.x, c = threadIdx.x;
    int a = lab[e*3], b = lab[e*3+1], d = lab[e*3+2];
    out[e*NC_ + c] = (a == c || b == c || d == c) ? 1.f : 0.f;
}

// ---------------- orchestration ----------------
extern "C" void kernel_launch(void* const* d_in, const int* in_sizes, int n_in,
                              void* d_out, int out_size){
    const float* word = (const float*)d_in[0];
    const float* pos  = (const float*)d_in[1];
    const float* dis  = (const float*)d_in[2];
    const float* WihF = (const float*)d_in[3];
    const float* WhhF = (const float*)d_in[4];
    const float* bihF = (const float*)d_in[5];
    const float* bhhF = (const float*)d_in[6];
    const float* WihB = (const float*)d_in[7];
    const float* WhhB = (const float*)d_in[8];
    const float* bihB = (const float*)d_in[9];
    const float* bhhB = (const float*)d_in[10];
    const float* s1W  = (const float*)d_in[11];
    const float* s1b  = (const float*)d_in[12];
    const float* s2W  = (const float*)d_in[13];
    const float* repW = (const float*)d_in[14];
    const float* repb = (const float*)d_in[15];
    const float* W2W  = (const float*)d_in[16];
    const float* W2b  = (const float*)d_in[17];
    const float* WoW  = (const float*)d_in[18];
    const float* Wob  = (const float*)d_in[19];
    const float* W3W  = (const float*)d_in[20];
    const float* W3b  = (const float*)d_in[21];
    const float* clsW = (const float*)d_in[22];
    const float* clsb = (const float*)d_in[23];
    const int* slen   = (const int*)d_in[24];
    const int* emo    = (const int*)d_in[25];
    const int* cau    = (const int*)d_in[26];
    const int* lab    = (const int*)d_in[27];
    float* out = (float*)d_out;

    cudaFuncSetAttribute(bgemm<false,true >, cudaFuncAttributeMaxDynamicSharedMemorySize, BGS_);
    cudaFuncSetAttribute(bgemm<false,false>, cudaFuncAttributeMaxDynamicSharedMemorySize, BGS_);

    void *p_xall,*p_Hs,*p_t1,*p_U,*p_R,*p_E,*p_Cu,*p_cE;
    void *p_z2,*p_z3,*p_EW2a,*p_EW3a,*p_CW3b,*p_disW3,*p_bm,*p_zero,*p_of;
    void *p_WcT,*p_W2yT,*p_W2eyT,*p_W3cT;
    void *p_A1,*p_A2,*p_A3,*p_B1,*p_B2,*p_B3;
    cudaGetSymbolAddress(&p_xall, g_xall);
    cudaGetSymbolAddress(&p_Hs,   g_Hs);
    cudaGetSymbolAddress(&p_t1,   g_t1);
    cudaGetSymbolAddress(&p_U,    g_U);
    cudaGetSymbolAddress(&p_R,    g_R);
    cudaGetSymbolAddress(&p_E,    g_E);
    cudaGetSymbolAddress(&p_Cu,   g_Cu);
    cudaGetSymbolAddress(&p_cE,   g_cE);
    cudaGetSymbolAddress(&p_z2,   g_z2);
    cudaGetSymbolAddress(&p_z3,   g_z3);
    cudaGetSymbolAddress(&p_EW2a, g_EW2a);
    cudaGetSymbolAddress(&p_EW3a, g_EW3a);
    cudaGetSymbolAddress(&p_CW3b, g_CW3b);
    cudaGetSymbolAddress(&p_disW3,g_disW3);
    cudaGetSymbolAddress(&p_bm,   g_bm);
    cudaGetSymbolAddress(&p_zero, g_zero);
    cudaGetSymbolAddress(&p_of,   g_of);
    cudaGetSymbolAddress(&p_WcT,  g_WcT);
    cudaGetSymbolAddress(&p_W2yT, g_W2yT);
    cudaGetSymbolAddress(&p_W2eyT,g_W2eyT);
    cudaGetSymbolAddress(&p_W3cT, g_W3cT);
    cudaGetSymbolAddress(&p_A1, g_A1);
    cudaGetSymbolAddress(&p_A2, g_A2);
    cudaGetSymbolAddress(&p_A3, g_A3);
    cudaGetSymbolAddress(&p_B1, g_B1);
    cudaGetSymbolAddress(&p_B2, g_B2);
    cudaGetSymbolAddress(&p_B3, g_B3);

    __nv_bfloat16 *A1 = (__nv_bfloat16*)p_A1, *A2 = (__nv_bfloat16*)p_A2,
                  *A3 = (__nv_bfloat16*)p_A3, *B1 = (__nv_bfloat16*)p_B1,
                  *B2 = (__nv_bfloat16*)p_B2, *B3 = (__nv_bfloat16*)p_B3;

    auto splitA = [&](const float* src, int n){
        k_split<<<(n + 255)/256, 256>>>(src, A1, A2, A3, n);
    };
    auto splitB = [&](const float* src, int n){
        k_split<<<(n + 255)/256, 256>>>(src, B1, B2, B3, n);
    };

    dim3 tb(32, 8);
    dim3 tg(D_/32, D_/32);

    // prep
    k_prep<<<B_, T_>>>(slen);
    k_biasM<<<(G2_ + 255)/256, 256>>>(bihF, bhhF, bihB, bhhB);
    k_zero<<<(2*2*B_*H_ + 255)/256, 256>>>();
    k_transT<<<tg, tb>>>(W2W + (size_t)768*D_,  (float*)p_W2yT);
    k_transT<<<tg, tb>>>(W2W + (size_t)1537*D_, (float*)p_W2eyT);
    k_transT<<<tg, tb>>>(W3W + (size_t)1537*D_, (float*)p_W3cT);
    k_transWM<<<dim3(D_/32, G_/32), tb>>>(WihF, 0);
    k_transWM<<<dim3(D_/32, G_/32), tb>>>(WihB, G_);

    // UPSTREAM (fp32): merged input projection, N=3072
    sgemmF<false,false><<<dim3(G2_/128, BT_/128), 256>>>(word, (const float*)p_WcT,
        (const float*)p_bm, (float*)p_xall, BT_, G2_, D_);

    // recurrence (k-split x2 for occupancy; writes g_Hs directly)
    for (int t = 0; t < T_; t++)
        k_lstm3<<<dim3(B_/32, H_/32, 2), 256>>>(WhhF, WhhB, t);

    // attention pooling — fp32
    sgemmF<true,false><<<dim3(D_/128, BT_/128), 256>>>((const float*)p_Hs, s1W, s1b,
        (float*)p_t1, BT_, D_, D_);
    k_e<<<BT_/8, 256>>>(s2W);
    k_u<<<B_, 256>>>(slen);

    // shared representation — fp32
    sgemmF<true,false><<<dim3(D_/128, B_/128), 256>>>((const float*)p_U, repW, repb,
        (float*)p_R, B_, D_, D_);
    k_gatherR<<<(NC_*D_ + 255)/256, 256>>>(emo, cau);

    // phase 2
    k_chunk<<<NE_*NK_, 256>>>();
    sgemm64<false,false><<<dim3(D_/64, (NE_*NK_)/64), 256>>>(pos, W2W + (size_t)2305*D_,
        W2b, (float*)p_z2, NE_*NK_, D_, POS_, D_);
    splitA((const float*)p_cE, NE_*NK_*D_); splitB((const float*)p_W2yT, D_*D_);
    bgemm<false,true><<<dim3(D_/128, (NE_*NK_)/128), 256, BGS_>>>(A1,A2,A3, B1,B2,B3,
        (const float*)p_zero, (float*)p_z2, NE_*NK_, D_, D_);
    k_EYsplit<<<NE_*NK_, 256>>>(A1, A2, A3);
    splitB((const float*)p_W2eyT, D_*D_);
    bgemm<false,true><<<dim3(D_/128, (NE_*NK_)/128), 256, BGS_>>>(A1,A2,A3, B1,B2,B3,
        (const float*)p_zero, (float*)p_z2, NE_*NK_, D_, D_);
    sgemm64<false,false><<<dim3(D_/64, (NE_+63)/64), 256>>>((const float*)p_E, W2W,
        (const float*)p_zero, (float*)p_EW2a, NE_, D_, D_, D_);
    k_add2<<<(NE_*NK_*D_ + 255)/256, 256>>>(W2W);
    k_bn<<<dim3(NE_, 3), 256>>>((float*)p_z2, NK_);
    k_head<<<(NE_*NK_)/8, 256>>>((const float*)p_z2, WoW, Wob, out, (float*)p_of, NE_*NK_);

    // phase 3
    k_ECsplit<<<NE_*NC_, 256>>>(A1, A2, A3);
    splitB((const float*)p_W3cT, D_*D_);
    bgemm<false,false><<<dim3(D_/128, (NE_*NC_)/128), 256, BGS_>>>(A1,A2,A3, B1,B2,B3,
        W3b, (float*)p_z3, NE_*NC_, D_, D_);
    sgemm64<false,false><<<dim3(D_/64, (NE_+63)/64), 256>>>((const float*)p_E, W3W,
        (const float*)p_zero, (float*)p_EW3a, NE_, D_, D_, D_);
    sgemm64<false,false><<<dim3(D_/64, (NC_+63)/64), 256>>>((const float*)p_Cu,
        W3W + (size_t)768*D_, (const float*)p_zero, (float*)p_CW3b, NC_, D_, D_, D_);
    sgemm64<false,false><<<dim3(D_/64, (NC_+63)/64), 256>>>(dis, W3W + (size_t)2305*D_,
        (const float*)p_zero, (float*)p_disW3, NC_, D_, POS_, D_);
    k_add3<<<(NE_*NC_*D_ + 255)/256, 256>>>(W3W);
    k_bn<<<dim3(NE_, 3), 256>>>((float*)p_z3, NC_);
    k_head<<<(NE_*NC_)/8, 256>>>((const float*)p_z3, clsW, clsb,
        out + NE_*NK_*2, nullptr, NE_*NC_);

    // L indicator
    k_L<<<NE_, NC_>>>(lab, out + NE_*NK_*2 + NE_*NC_*2);
}

// round 16
// speedup vs baseline: 2.1275x; 1.1290x over previous
#include <cuda_runtime.h>
#include <cuda_bf16.h>
#include <math.h>
#include <stdint.h>
#include <stddef.h>

// ---------------- problem dims ----------------
#define B_   256
#define T_   96
#define D_   768
#define H_   384
#define G_   1536          // 4*H
#define G2_  3072          // both directions merged
#define BT_  (B_*T_)       // 24576
#define NE_  128
#define NC_  256
#define NK_  64
#define POS_ 50
#define AMAX_ ((size_t)NE_*NC_*D_)
#define BMAX_ ((size_t)D_*D_)

// ---------------- scratch ----------------
__device__ float g_xall[(size_t)BT_*G2_];
__device__ float g_hbuf[2][2][B_*H_];
__device__ float g_cbuf[2][B_*H_];
__device__ float g_Hs[BT_*D_];
__device__ float g_t1[BT_*D_];
__device__ float g_e[BT_];
__device__ float g_U[B_*D_];
__device__ float g_R[NC_*D_];
__device__ float g_E[NE_*D_];
__device__ float g_Cu[NC_*D_];
__device__ float g_cE[NE_*NK_*D_];
__device__ float g_n2[NE_*NK_];
__device__ float g_n3[NE_*NC_];
__device__ float g_z2[NE_*NK_*D_];
__device__ float g_z3[NE_*NC_*D_];
__device__ float g_EW2a[NE_*D_];
__device__ float g_EW3a[NE_*D_];
__device__ float g_CW3b[NC_*D_];
__device__ float g_disW3[NC_*D_];
__device__ float g_of[NE_*NK_];
__device__ float g_bm[G2_];
__device__ float g_zero[G_];
__device__ int   g_rev[BT_];
__device__ float g_WcT[(size_t)D_*G2_];
__device__ float g_W2yT [D_*D_];
__device__ float g_W2eyT[D_*D_];
__device__ float g_W3cT [D_*D_];
__device__ __nv_bfloat16 g_A1[AMAX_];
__device__ __nv_bfloat16 g_A2[AMAX_];
__device__ __nv_bfloat16 g_A3[AMAX_];
__device__ __nv_bfloat16 g_B1[BMAX_];
__device__ __nv_bfloat16 g_B2[BMAX_];
__device__ __nv_bfloat16 g_B3[BMAX_];

__device__ __forceinline__ float lrelu(float x){ return x >= 0.f ? x : 0.01f*x; }
__device__ __forceinline__ float sigm(float x){ return 1.f/(1.f+expf(-x)); }

// ---- packed fp32x2 helpers (PTX 8.6, sm_100 family) ----
__device__ __forceinline__ void fma2(uint64_t& d, uint64_t a, uint64_t b){
    asm("fma.rn.f32x2 %0, %1, %2, %0;" : "+l"(d) : "l"(a), "l"(b));
}
__device__ __forceinline__ uint64_t dup2(float x){
    uint64_t r;
    asm("mov.b64 %0, {%1, %1};" : "=l"(r) : "r"(__float_as_uint(x)));
    return r;
}
__device__ __forceinline__ void unpk2(uint64_t v, float& lo, float& hi){
    uint32_t l, h;
    asm("mov.b64 {%0, %1}, %2;" : "=r"(l), "=r"(h) : "l"(v));
    lo = __uint_as_float(l); hi = __uint_as_float(h);
}

__device__ __forceinline__ void split3(float a, __nv_bfloat16& x1,
                                       __nv_bfloat16& x2, __nv_bfloat16& x3){
    x1 = __float2bfloat16(a);
    float r = a - __bfloat162float(x1);
    x2 = __float2bfloat16(r);
    float r2 = r - __bfloat162float(x2);
    x3 = __float2bfloat16(r2);
}

#define MMAB(C, A0,A1,A2,A3, B0,B1) \
    asm volatile("mma.sync.aligned.m16n8k16.row.col.f32.bf16.bf16.f32 " \
        "{%0,%1,%2,%3}, {%4,%5,%6,%7}, {%8,%9}, {%0,%1,%2,%3};" \
        : "+f"((C)[0]),"+f"((C)[1]),"+f"((C)[2]),"+f"((C)[3]) \
        : "r"(A0),"r"(A1),"r"(A2),"r"(A3),"r"(B0),"r"(B1))

// ---------------- fp32 SGEMM with FFMA2 inner loop ----------------
template<bool RELU, bool ACC>
__global__ __launch_bounds__(256, 2)
void sgemmF(const float* __restrict__ A, const float* __restrict__ Bm,
            const float* __restrict__ bias, float* __restrict__ Cm,
            int M, int N, int K){
    __shared__ float As[2][16][136];
    __shared__ __align__(16) float Bs[2][16][128];
    const int tid = threadIdx.x;
    const int bm = blockIdx.y << 7, bn = blockIdx.x << 7;
    const int tx = tid & 15, ty = tid >> 4;

    const int am0 = tid >> 2, ak0 = (tid & 3) << 2;
    const int am1 = am0 + 64;
    const int bk0 = tid >> 5, bn0 = (tid & 31) << 2;
    const int bk1 = bk0 + 8;

    float4 ra0, ra1, rb0, rb1;
    uint64_t acc2[8][4];
    #pragma unroll
    for (int i = 0; i < 8; i++)
        #pragma unroll
        for (int jp = 0; jp < 4; jp++) acc2[i][jp] = 0ull;

    auto loadRegs = [&](int k0){
        ra0 = *(const float4*)(A  + (size_t)(bm+am0)*K + k0 + ak0);
        ra1 = *(const float4*)(A  + (size_t)(bm+am1)*K + k0 + ak0);
        rb0 = *(const float4*)(Bm + (size_t)(k0+bk0)*N + bn + bn0);
        rb1 = *(const float4*)(Bm + (size_t)(k0+bk1)*N + bn + bn0);
    };
    auto storeSmem = [&](int buf){
        As[buf][ak0+0][am0] = ra0.x; As[buf][ak0+1][am0] = ra0.y;
        As[buf][ak0+2][am0] = ra0.z; As[buf][ak0+3][am0] = ra0.w;
        As[buf][ak0+0][am1] = ra1.x; As[buf][ak0+1][am1] = ra1.y;
        As[buf][ak0+2][am1] = ra1.z; As[buf][ak0+3][am1] = ra1.w;
        *(float4*)&Bs[buf][bk0][bn0] = rb0;
        *(float4*)&Bs[buf][bk1][bn0] = rb1;
    };

    loadRegs(0); storeSmem(0); __syncthreads();
    const int ntk = K >> 4;
    for (int kt = 0; kt < ntk; kt++){
        if (kt + 1 < ntk) loadRegs((kt+1) << 4);
        const int buf = kt & 1;
        #pragma unroll
        for (int kk = 0; kk < 16; kk++){
            float4 a0 = *(const float4*)&As[buf][kk][ty<<2];
            float4 a1 = *(const float4*)&As[buf][kk][(ty<<2)+64];
            ulonglong2 bq0 = *(const ulonglong2*)&Bs[buf][kk][tx<<2];
            ulonglong2 bq1 = *(const ulonglong2*)&Bs[buf][kk][(tx<<2)+64];
            uint64_t bp[4] = {bq0.x, bq0.y, bq1.x, bq1.y};
            float av[8] = {a0.x,a0.y,a0.z,a0.w,a1.x,a1.y,a1.z,a1.w};
            #pragma unroll
            for (int i = 0; i < 8; i++){
                uint64_t ad = dup2(av[i]);
                #pragma unroll
                for (int jp = 0; jp < 4; jp++) fma2(acc2[i][jp], ad, bp[jp]);
            }
        }
        if (kt + 1 < ntk) storeSmem(buf ^ 1);
        __syncthreads();
    }
    #pragma unroll
    for (int i = 0; i < 8; i++){
        int m = bm + (ty<<2) + (i&3) + ((i>>2)<<6);
        size_t base = (size_t)m*N;
        #pragma unroll
        for (int jg = 0; jg < 2; jg++){
            int n0 = bn + (tx<<2) + (jg<<6);
            float4 v;
            if (ACC) v = *(const float4*)&Cm[base + n0];
            else     v = *(const float4*)&bias[n0];
            float e0, e1, e2, e3;
            unpk2(acc2[i][jg*2+0], e0, e1);
            unpk2(acc2[i][jg*2+1], e2, e3);
            v.x += e0; v.y += e1; v.z += e2; v.w += e3;
            if (RELU){ v.x = lrelu(v.x); v.y = lrelu(v.y); v.z = lrelu(v.z); v.w = lrelu(v.w); }
            *(float4*)&Cm[base + n0] = v;
        }
    }
}

// ---------------- fp32 -> 3x bf16 split ----------------
__global__ void k_split(const float* __restrict__ src,
                        __nv_bfloat16* __restrict__ p1,
                        __nv_bfloat16* __restrict__ p2,
                        __nv_bfloat16* __restrict__ p3, int n){
    int i = blockIdx.x*256 + threadIdx.x;
    if (i >= n) return;
    __nv_bfloat16 h1, h2, h3;
    split3(src[i], h1, h2, h3);
    p1[i] = h1; p2[i] = h2; p3[i] = h3;
}

// ============ bf16x6 GEMM (big downstream GEMMs) ==========
#define BGP_  10240
#define BGS_  67584

template<bool RELU, bool ACC>
__global__ void __launch_bounds__(256)
bgemm(const __nv_bfloat16* __restrict__ A1, const __nv_bfloat16* __restrict__ A2,
      const __nv_bfloat16* __restrict__ A3, const __nv_bfloat16* __restrict__ Bt1,
      const __nv_bfloat16* __restrict__ Bt2, const __nv_bfloat16* __restrict__ Bt3,
      const float* __restrict__ bias, float* __restrict__ Cm,
      int M, int N, int K){
    extern __shared__ char sm[];
    const int tid = threadIdx.x, warp = tid >> 5, lane = tid & 31;
    const int gid = lane >> 2, tig = lane & 3;
    const int bm = blockIdx.y << 7, bn = blockIdx.x << 7;
    const int wm = (warp & 1) << 6, wn = (warp >> 1) << 5;

    const __nv_bfloat16* Ap[3] = {A1, A2, A3};
    const __nv_bfloat16* Bp[3] = {Bt1, Bt2, Bt3};

    float acc[4][4][4];
    #pragma unroll
    for (int i = 0; i < 4; i++)
        #pragma unroll
        for (int j = 0; j < 4; j++)
            #pragma unroll
            for (int q = 0; q < 4; q++) acc[i][j][q] = 0.f;

    for (int k0 = 0; k0 < K; k0 += 32){
        __syncthreads();
        for (int idx = tid; idx < 128*16; idx += 256){
            int r = idx >> 4, kq = idx & 15;
            size_t ga = (((size_t)(bm + r)*K + k0) >> 1) + kq;
            size_t gb = (((size_t)(bn + r)*K + k0) >> 1) + kq;
            uint32_t so = (uint32_t)(r*80 + kq*4);
            #pragma unroll
            for (int p = 0; p < 3; p++){
                *(uint32_t*)(sm + p*BGP_ + so)           = ((const uint32_t*)Ap[p])[ga];
                *(uint32_t*)(sm + 3*BGP_ + p*BGP_ + so)  = ((const uint32_t*)Bp[p])[gb];
            }
        }
        __syncthreads();
        #pragma unroll
        for (int s = 0; s < 2; s++){
            uint32_t bfr[3][4][2];
            #pragma unroll
            for (int p = 0; p < 3; p++)
                #pragma unroll
                for (int nt = 0; nt < 4; nt++){
                    int n = wn + (nt << 3) + gid;
                    const char* bb = sm + 3*BGP_ + p*BGP_ + n*80 + s*32 + tig*4;
                    bfr[p][nt][0] = *(const uint32_t*)bb;
                    bfr[p][nt][1] = *(const uint32_t*)(bb + 16);
                }
            #pragma unroll
            for (int pa = 0; pa < 3; pa++){
                #pragma unroll
                for (int mt = 0; mt < 4; mt++){
                    int r = wm + (mt << 4) + gid;
                    const char* ab = sm + pa*BGP_ + r*80 + s*32 + tig*4;
                    uint32_t a0 = *(const uint32_t*)ab;
                    uint32_t a1 = *(const uint32_t*)(ab + 640);
                    uint32_t a2 = *(const uint32_t*)(ab + 16);
                    uint32_t a3 = *(const uint32_t*)(ab + 656);
                    if (pa == 0){
                        #pragma unroll
                        for (int nt = 0; nt < 4; nt++){
                            MMAB(acc[mt][nt], a0,a1,a2,a3, bfr[0][nt][0], bfr[0][nt][1]);
                            MMAB(acc[mt][nt], a0,a1,a2,a3, bfr[1][nt][0], bfr[1][nt][1]);
                            MMAB(acc[mt][nt], a0,a1,a2,a3, bfr[2][nt][0], bfr[2][nt][1]);
                        }
                    } else if (pa == 1){
                        #pragma unroll
                        for (int nt = 0; nt < 4; nt++){
                            MMAB(acc[mt][nt], a0,a1,a2,a3, bfr[0][nt][0], bfr[0][nt][1]);
                            MMAB(acc[mt][nt], a0,a1,a2,a3, bfr[1][nt][0], bfr[1][nt][1]);
                        }
                    } else {
                        #pragma unroll
                        for (int nt = 0; nt < 4; nt++)
                            MMAB(acc[mt][nt], a0,a1,a2,a3, bfr[0][nt][0], bfr[0][nt][1]);
                    }
                }
            }
        }
    }
    __syncthreads();
    float* fs = (float*)sm;
    #pragma unroll
    for (int mt = 0; mt < 4; mt++){
        int r0 = wm + (mt << 4) + gid;
        #pragma unroll
        for (int nt = 0; nt < 4; nt++){
            int c = wn + (nt << 3) + (tig << 1);
            fs[r0*132 + c]       = acc[mt][nt][0];
            fs[r0*132 + c + 1]   = acc[mt][nt][1];
            fs[(r0+8)*132 + c]   = acc[mt][nt][2];
            fs[(r0+8)*132 + c+1] = acc[mt][nt][3];
        }
    }
    __syncthreads();
    for (int i = tid; i < 128*128; i += 256){
        int r = i >> 7, c = i & 127;
        float v = fs[r*132 + c];
        float* dst = Cm + (size_t)(bm + r)*N + bn + c;
        float base = ACC ? *dst : bias[bn + c];
        v += base;
        if (RELU) v = lrelu(v);
        *dst = v;
    }
}

// ---------------- prep ----------------
__global__ void k_prep(const int* __restrict__ slen){
    int b = blockIdx.x, t = threadIdx.x;
    int len = slen[b];
    g_rev[b*T_ + t] = (t < len) ? (len - 1 - t) : t;
}

__global__ void k_biasM(const float* bihf, const float* bhhf,
                        const float* bihb, const float* bhhb){
    int i = blockIdx.x*256 + threadIdx.x;
    if (i < G_)       g_bm[i]      = bihf[i] + bhhf[i];
    else if (i < G2_) g_bm[i]      = bihb[i-G_] + bhhb[i-G_];
}

__global__ void k_zero(){
    int i = blockIdx.x*256 + threadIdx.x;
    if (i < 2*2*B_*H_) (&g_hbuf[0][0][0])[i] = 0.f;
    if (i < 2*B_*H_)   (&g_cbuf[0][0])[i]    = 0.f;
}

// 768x768 block transpose
__global__ void k_transT(const float* __restrict__ src, float* __restrict__ dst){
    __shared__ float t[32][33];
    int r0 = blockIdx.y*32, c0 = blockIdx.x*32;
    int tx = threadIdx.x, ty = threadIdx.y;
    #pragma unroll
    for (int q = 0; q < 32; q += 8)
        t[ty+q][tx] = src[(size_t)(r0+ty+q)*D_ + c0+tx];
    __syncthreads();
    #pragma unroll
    for (int q = 0; q < 32; q += 8)
        dst[(size_t)(c0+ty+q)*D_ + r0+tx] = t[tx][ty+q];
}

// Wih [G,D] -> merged [D, G2] at column offset
__global__ void k_transWM(const float* __restrict__ src, int colOff){
    __shared__ float t[32][33];
    int k0 = blockIdx.x*32, n0 = blockIdx.y*32;
    int tx = threadIdx.x, ty = threadIdx.y;
    #pragma unroll
    for (int q = 0; q < 32; q += 8)
        t[ty+q][tx] = src[(size_t)(n0+ty+q)*D_ + k0+tx];
    __syncthreads();
    #pragma unroll
    for (int q = 0; q < 32; q += 8)
        g_WcT[(size_t)(k0+ty+q)*G2_ + colOff + n0+tx] = t[tx][ty+q];
}

// ---------------- small-K SGEMM (guards), 64x64 ----------------
template<bool TB, bool RELU>
__global__ void sgemm64(const float* __restrict__ A, const float* __restrict__ Bm,
                        const float* __restrict__ bias, float* __restrict__ Cm,
                        int M, int N, int K, int ldb){
    __shared__ float As[16][65];
    __shared__ float Bs[16][65];
    int bm = blockIdx.y << 6, bn = blockIdx.x << 6;
    int tid = threadIdx.x;
    int tx = tid & 15, ty = tid >> 4;
    float acc[4][4];
    #pragma unroll
    for (int i = 0; i < 4; i++)
        #pragma unroll
        for (int j = 0; j < 4; j++) acc[i][j] = 0.f;
    int arow = tid >> 2, ak0 = (tid & 3) << 2;
    for (int k0 = 0; k0 < K; k0 += 16){
        #pragma unroll
        for (int q = 0; q < 4; q++){
            int kk = ak0 + q, gm = bm + arow, gk = k0 + kk;
            As[kk][arow] = (gm < M && gk < K) ? A[(size_t)gm*K + gk] : 0.f;
        }
        {
            int kr = tid >> 4, nc0 = (tid & 15) << 2;
            #pragma unroll
            for (int q = 0; q < 4; q++){
                int n = nc0 + q, gk = k0 + kr, gn = bn + n;
                Bs[kr][n] = (gk < K && gn < N) ? Bm[(size_t)gk*ldb + gn] : 0.f;
            }
        }
        __syncthreads();
        #pragma unroll
        for (int kk = 0; kk < 16; kk++){
            float a[4], b[4];
            #pragma unroll
            for (int i = 0; i < 4; i++) a[i] = As[kk][ty + (i<<4)];
            #pragma unroll
            for (int j = 0; j < 4; j++) b[j] = Bs[kk][tx + (j<<4)];
            #pragma unroll
            for (int i = 0; i < 4; i++)
                #pragma unroll
                for (int j = 0; j < 4; j++) acc[i][j] += a[i]*b[j];
        }
        __syncthreads();
    }
    #pragma unroll
    for (int i = 0; i < 4; i++){
        int gm = bm + ty + (i<<4); if (gm >= M) continue;
        #pragma unroll
        for (int j = 0; j < 4; j++){
            int gn = bn + tx + (j<<4); if (gn >= N) continue;
            float v = acc[i][j] + bias[gn];
            if (RELU) v = lrelu(v);
            Cm[(size_t)gm*N + gn] = v;
        }
    }
}

// ---------------- fused LSTM step, k-split x2, FFMA2 inner -------------------
__global__ void __launch_bounds__(256)
k_lstm3(const float* __restrict__ WhhF, const float* __restrict__ WhhB, int t){
    int dir = blockIdx.z;
    const float* Whh = dir ? WhhB : WhhF;
    const float* hp  = g_hbuf[dir][t & 1];
    float* hn        = g_hbuf[dir][(t & 1) ^ 1];
    float* cc        = g_cbuf[dir];

    int bBase = blockIdx.x << 5, jBase = blockIdx.y << 5;
    int tid = threadIdx.x;
    int tz = tid >> 7, tl = tid & 127;
    int tx = tl & 15, ty = tl >> 4;

    __shared__ float shh[2][32][17];
    __shared__ __align__(16) float shw[2][4][16][34];   // even pad: 8B-aligned pairs
    __shared__ float red[128][33];

    uint64_t acc2[4][4];   // [bb][gate], packed pair over jj
    #pragma unroll
    for (int a = 0; a < 4; a++)
        #pragma unroll
        for (int g = 0; g < 4; g++) acc2[a][g] = 0ull;

    const int kcBase = tz * (H_/2);
    for (int c = 0; c < (H_/2)/16; c++){
        int kc = kcBase + c*16;
        #pragma unroll
        for (int q = 0; q < 4; q++){
            int e = tl + 128*q;
            int bl = e >> 4, kk = e & 15;
            shh[tz][bl][kk] = hp[(bBase + bl)*H_ + kc + kk];
        }
        #pragma unroll
        for (int q = 0; q < 16; q++){
            int e = tl + 128*q;
            int g = e >> 9, rem = e & 511;
            int jl = rem >> 4, kk = rem & 15;
            shw[tz][g][kk][jl] = Whh[(size_t)(g*H_ + jBase + jl)*H_ + kc + kk];
        }
        __syncthreads();
        #pragma unroll
        for (int kk = 0; kk < 16; kk++){
            float hv[4];
            #pragma unroll
            for (int bb = 0; bb < 4; bb++) hv[bb] = shh[tz][(ty<<2)+bb][kk];
            uint64_t w2[4];
            #pragma unroll
            for (int g = 0; g < 4; g++)
                w2[g] = *(const uint64_t*)&shw[tz][g][kk][tx<<1];
            #pragma unroll
            for (int bb = 0; bb < 4; bb++){
                uint64_t hd = dup2(hv[bb]);
                #pragma unroll
                for (int g = 0; g < 4; g++) fma2(acc2[bb][g], hd, w2[g]);
            }
        }
        __syncthreads();
    }

    float acc[4][4][2];
    #pragma unroll
    for (int bb = 0; bb < 4; bb++)
        #pragma unroll
        for (int g = 0; g < 4; g++)
            unpk2(acc2[bb][g], acc[bb][g][0], acc[bb][g][1]);

    if (tz == 1){
        #pragma unroll
        for (int bb = 0; bb < 4; bb++)
            #pragma unroll
            for (int g = 0; g < 4; g++){
                red[tl][bb*8 + g*2 + 0] = acc[bb][g][0];
                red[tl][bb*8 + g*2 + 1] = acc[bb][g][1];
            }
    }
    __syncthreads();
    if (tz == 0){
        #pragma unroll
        for (int bb = 0; bb < 4; bb++)
            #pragma unroll
            for (int g = 0; g < 4; g++){
                acc[bb][g][0] += red[tl][bb*8 + g*2 + 0];
                acc[bb][g][1] += red[tl][bb*8 + g*2 + 1];
            }
        #pragma unroll
        for (int bb = 0; bb < 4; bb++){
            int b = bBase + (ty<<2) + bb;
            int rid = g_rev[b*T_ + t];
            const float* xrow = g_xall + (size_t)(b*T_ + (dir ? rid : t))*G2_ + (dir ? G_ : 0);
            float* hsrow = g_Hs + (size_t)(b*T_ + (dir ? rid : t))*D_ + (dir ? H_ : 0);
            #pragma unroll
            for (int jj = 0; jj < 2; jj++){
                int j = jBase + (tx<<1) + jj;
                float gi = acc[bb][0][jj] + xrow[j];
                float gf = acc[bb][1][jj] + xrow[H_ + j];
                float gg = acc[bb][2][jj] + xrow[2*H_ + j];
                float go = acc[bb][3][jj] + xrow[3*H_ + j];
                float cold = cc[b*H_ + j];
                float cn = sigm(gf)*cold + sigm(gi)*tanhf(gg);
                float hv = sigm(go)*tanhf(cn);
                cc[b*H_ + j] = cn;
                hn[b*H_ + j] = hv;
                hsrow[j] = hv;
            }
        }
    }
}

// ---------------- e = t1 @ s2 ----------------
__global__ void k_e(const float* __restrict__ s2){
    int warp = threadIdx.x >> 5, lane = threadIdx.x & 31;
    int row = blockIdx.x*8 + warp; if (row >= BT_) return;
    const float* h = g_t1 + (size_t)row*D_;
    float a = 0.f;
    for (int k = lane; k < D_; k += 32) a += h[k]*s2[k];
    #pragma unroll
    for (int s = 16; s; s >>= 1) a += __shfl_down_sync(0xffffffffu, a, s);
    if (!lane) g_e[row] = a;
}

// ---------------- masked pooling ----------------
__global__ void k_u(const int* __restrict__ slen){
    __shared__ float al[T_];
    __shared__ float red[256];
    int b = blockIdx.x, tid = threadIdx.x;
    int len = slen[b];
    float v = 0.f;
    if (tid < T_){ v = (tid < len) ? g_e[b*T_ + tid] : 0.f; al[tid] = v; }
    red[tid] = v; __syncthreads();
    for (int s = 128; s; s >>= 1){ if (tid < s) red[tid] += red[tid+s]; __syncthreads(); }
    float denom = red[0] + 1e-9f;
    __syncthreads();
    if (tid < T_) al[tid] = al[tid] / denom;
    __syncthreads();
    for (int d = tid; d < D_; d += 256){
        float acc = 0.f;
        for (int t = 0; t < T_; t++) acc += al[t]*g_Hs[(size_t)(b*T_ + t)*D_ + d];
        g_U[b*D_ + d] = acc;
    }
}

// ---------------- gather E / Cu rows ----------------
__global__ void k_gatherR(const int* __restrict__ emo, const int* __restrict__ cau){
    int i = blockIdx.x*256 + threadIdx.x;
    if (i < NE_*D_){ int r = i / D_, d = i - r*D_; g_E[i]  = g_R[(size_t)emo[r]*D_ + d]; }
    if (i < NC_*D_){ int r = i / D_, d = i - r*D_; g_Cu[i] = g_R[(size_t)cau[r]*D_ + d]; }
}

// ---------------- per-chunk cross attention ----------------
__global__ void k_chunk(){
    __shared__ float Esh[D_];
    __shared__ float red[256];
    __shared__ float scs[4];
    int blk = blockIdx.x, tid = threadIdx.x;
    int e = blk >> 6, k = blk & 63;
    const float* Er = g_E + (size_t)e*D_;
    for (int d = tid; d < D_; d += 256) Esh[d] = Er[d];
    __syncthreads();
    float dots[4];
    for (int c = 0; c < 4; c++){
        const float* Cr = g_Cu + (size_t)(k*4 + c)*D_;
        float a = 0.f;
        for (int d = tid; d < D_; d += 256) a += Esh[d]*Cr[d];
        red[tid] = a; __syncthreads();
        for (int s = 128; s; s >>= 1){ if (tid < s) red[tid] += red[tid+s]; __syncthreads(); }
        dots[c] = red[0]; __syncthreads();
    }
    if (tid == 0){
        float m = fmaxf(fmaxf(dots[0],dots[1]), fmaxf(dots[2],dots[3]));
        float ex[4], s = 0.f;
        #pragma unroll
        for (int c = 0; c < 4; c++){ ex[c] = expf(dots[c]-m); s += ex[c]; }
        #pragma unroll
        for (int c = 0; c < 4; c++) scs[c] = ex[c]/s;
    }
    __syncthreads();
    const float* C0 = g_Cu + (size_t)(k*4+0)*D_;
    const float* C1 = g_Cu + (size_t)(k*4+1)*D_;
    const float* C2 = g_Cu + (size_t)(k*4+2)*D_;
    const float* C3 = g_Cu + (size_t)(k*4+3)*D_;
    float s0 = scs[0], s1 = scs[1], s2 = scs[2], s3 = scs[3];
    for (int d = tid; d < D_; d += 256)
        g_cE[(size_t)blk*D_ + d] = s0*C0[d] + s1*C1[d] + s2*C2[d] + s3*C3[d];
}

// ---------------- EY = E⊙Y: split planes + nrm2 ----------------
__global__ void k_EYsplit(__nv_bfloat16* __restrict__ p1,
                          __nv_bfloat16* __restrict__ p2,
                          __nv_bfloat16* __restrict__ p3){
    __shared__ float red[256];
    int row = blockIdx.x, tid = threadIdx.x;
    int e = row >> 6;
    const float* Er = g_E + (size_t)e*D_;
    const float* Y  = g_cE + (size_t)row*D_;
    float a = 0.f;
    for (int d = tid; d < D_; d += 256){
        float ev = Er[d], yv = Y[d];
        float df = ev - yv; a += df*df;
        __nv_bfloat16 h1, h2, h3;
        split3(ev*yv, h1, h2, h3);
        size_t idx = (size_t)row*D_ + d;
        p1[idx] = h1; p2[idx] = h2; p3[idx] = h3;
    }
    red[tid] = a; __syncthreads();
    for (int s = 128; s; s >>= 1){ if (tid < s) red[tid] += red[tid+s]; __syncthreads(); }
    if (tid == 0) g_n2[row] = sqrtf(red[0]);
}

// ---------------- EC = E⊙Cu: split planes + nrm3 ----------------
__global__ void k_ECsplit(__nv_bfloat16* __restrict__ p1,
                          __nv_bfloat16* __restrict__ p2,
                          __nv_bfloat16* __restrict__ p3){
    __shared__ float red[256];
    int row = blockIdx.x, tid = threadIdx.x;
    int e = row >> 8, c = row & 255;
    const float* Er = g_E + (size_t)e*D_;
    const float* Cr = g_Cu + (size_t)c*D_;
    float a = 0.f;
    for (int d = tid; d < D_; d += 256){
        float ev = Er[d], cv = Cr[d];
        float df = ev - cv; a += df*df;
        __nv_bfloat16 h1, h2, h3;
        split3(ev*cv, h1, h2, h3);
        size_t idx = (size_t)row*D_ + d;
        p1[idx] = h1; p2[idx] = h2; p3[idx] = h3;
    }
    red[tid] = a; __syncthreads();
    for (int s = 128; s; s >>= 1){ if (tid < s) red[tid] += red[tid+s]; __syncthreads(); }
    if (tid == 0) g_n3[row] = sqrtf(red[0]);
}

// ---------------- epilogue adds ----------------
__global__ void k_add2(const float* __restrict__ W2W){
    int idx = blockIdx.x*256 + threadIdx.x;
    if (idx >= NE_*NK_*D_) return;
    int row = idx / D_, n = idx - row*D_;
    int e = row >> 6;
    g_z2[idx] += g_EW2a[e*D_ + n] + g_n2[row]*W2W[(size_t)1536*D_ + n];
}

__global__ void k_add3(const float* __restrict__ W3W){
    int idx = blockIdx.x*256 + threadIdx.x;
    if (idx >= NE_*NC_*D_) return;
    int row = idx / D_, n = idx - row*D_;
    int e = row >> 8, c = row & 255;
    g_z3[idx] += g_EW3a[e*D_ + n] + g_CW3b[c*D_ + n] + g_disW3[c*D_ + n]
               + g_n3[row]*W3W[(size_t)1536*D_ + n]
               + g_of[(e<<6) + (c>>2)]*W3W[(size_t)2355*D_ + n];
}

// ---------------- BatchNorm (biased var) + lrelu ----------------
__global__ void k_bn(float* __restrict__ z, int rows){
    int e = blockIdx.x;
    int d = blockIdx.y*256 + threadIdx.x;
    size_t base = (size_t)e*rows*D_ + d;
    float s = 0.f;
    for (int r = 0; r < rows; r++) s += z[base + (size_t)r*D_];
    float m = s / (float)rows;
    float v = 0.f;
    for (int r = 0; r < rows; r++){ float t = z[base + (size_t)r*D_] - m; v += t*t; }
    v /= (float)rows;
    float inv = 1.f/sqrtf(v + 1e-5f);
    for (int r = 0; r < rows; r++){
        float t = (z[base + (size_t)r*D_] - m)*inv;
        z[base + (size_t)r*D_] = lrelu(t);
    }
}

// ---------------- 2-class head ----------------
__global__ void k_head(const float* __restrict__ Hx, const float* __restrict__ W,
                       const float* __restrict__ b2, float* __restrict__ out,
                       float* __restrict__ of, int rows){
    int warp = threadIdx.x >> 5, lane = threadIdx.x & 31;
    int row = blockIdx.x*8 + warp; if (row >= rows) return;
    const float* h = Hx + (size_t)row*D_;
    const float2* Wv = (const float2*)W;
    float a0 = 0.f, a1 = 0.f;
    for (int k = lane; k < D_; k += 32){
        float hv = h[k]; float2 w = Wv[k];
        a0 += hv*w.x; a1 += hv*w.y;
    }
    #pragma unroll
    for (int s = 16; s; s >>= 1){
        a0 += __shfl_down_sync(0xffffffffu, a0, s);
        a1 += __shfl_down_sync(0xffffffffu, a1, s);
    }
    if (!lane){
        float l0 = a0 + b2[0], l1 = a1 + b2[1];
        float m = fmaxf(l0, l1);
        float lse = m + logf(expf(l0-m) + expf(l1-m));
        out[row*2]   = l0 - lse;
        out[row*2+1] = l1 - lse;
        if (of) of[row] = (l1 > l0) ? 1.f : 0.f;
    }
}

// ---------------- L indicator ----------------
__global__ void k_L(const int* __restrict__ lab, float* __restrict__ out){
    int e = blockIdx.x, c = threadIdx.x;
    int a = lab[e*3], b = lab[e*3+1], d = lab[e*3+2];
    out[e*NC_ + c] = (a == c || b == c || d == c) ? 1.f : 0.f;
}

// ---------------- orchestration ----------------
extern "C" void kernel_launch(void* const* d_in, const int* in_sizes, int n_in,
                              void* d_out, int out_size){
    const float* word = (const float*)d_in[0];
    const float* pos  = (const float*)d_in[1];
    const float* dis  = (const float*)d_in[2];
    const float* WihF = (const float*)d_in[3];
    const float* WhhF = (const float*)d_in[4];
    const float* bihF = (const float*)d_in[5];
    const float* bhhF = (const float*)d_in[6];
    const float* WihB = (const float*)d_in[7];
    const float* WhhB = (const float*)d_in[8];
    const float* bihB = (const float*)d_in[9];
    const float* bhhB = (const float*)d_in[10];
    const float* s1W  = (const float*)d_in[11];
    const float* s1b  = (const float*)d_in[12];
    const float* s2W  = (const float*)d_in[13];
    const float* repW = (const float*)d_in[14];
    const float* repb = (const float*)d_in[15];
    const float* W2W  = (const float*)d_in[16];
    const float* W2b  = (const float*)d_in[17];
    const float* WoW  = (const float*)d_in[18];
    const float* Wob  = (const float*)d_in[19];
    const float* W3W  = (const float*)d_in[20];
    const float* W3b  = (const float*)d_in[21];
    const float* clsW = (const float*)d_in[22];
    const float* clsb = (const float*)d_in[23];
    const int* slen   = (const int*)d_in[24];
    const int* emo    = (const int*)d_in[25];
    const int* cau    = (const int*)d_in[26];
    const int* lab    = (const int*)d_in[27];
    float* out = (float*)d_out;

    cudaFuncSetAttribute(bgemm<false,true >, cudaFuncAttributeMaxDynamicSharedMemorySize, BGS_);
    cudaFuncSetAttribute(bgemm<false,false>, cudaFuncAttributeMaxDynamicSharedMemorySize, BGS_);

    void *p_xall,*p_Hs,*p_t1,*p_U,*p_R,*p_E,*p_Cu,*p_cE;
    void *p_z2,*p_z3,*p_EW2a,*p_EW3a,*p_CW3b,*p_disW3,*p_bm,*p_zero,*p_of;
    void *p_WcT,*p_W2yT,*p_W2eyT,*p_W3cT;
    void *p_A1,*p_A2,*p_A3,*p_B1,*p_B2,*p_B3;
    cudaGetSymbolAddress(&p_xall, g_xall);
    cudaGetSymbolAddress(&p_Hs,   g_Hs);
    cudaGetSymbolAddress(&p_t1,   g_t1);
    cudaGetSymbolAddress(&p_U,    g_U);
    cudaGetSymbolAddress(&p_R,    g_R);
    cudaGetSymbolAddress(&p_E,    g_E);
    cudaGetSymbolAddress(&p_Cu,   g_Cu);
    cudaGetSymbolAddress(&p_cE,   g_cE);
    cudaGetSymbolAddress(&p_z2,   g_z2);
    cudaGetSymbolAddress(&p_z3,   g_z3);
    cudaGetSymbolAddress(&p_EW2a, g_EW2a);
    cudaGetSymbolAddress(&p_EW3a, g_EW3a);
    cudaGetSymbolAddress(&p_CW3b, g_CW3b);
    cudaGetSymbolAddress(&p_disW3,g_disW3);
    cudaGetSymbolAddress(&p_bm,   g_bm);
    cudaGetSymbolAddress(&p_zero, g_zero);
    cudaGetSymbolAddress(&p_of,   g_of);
    cudaGetSymbolAddress(&p_WcT,  g_WcT);
    cudaGetSymbolAddress(&p_W2yT, g_W2yT);
    cudaGetSymbolAddress(&p_W2eyT,g_W2eyT);
    cudaGetSymbolAddress(&p_W3cT, g_W3cT);
    cudaGetSymbolAddress(&p_A1, g_A1);
    cudaGetSymbolAddress(&p_A2, g_A2);
    cudaGetSymbolAddress(&p_A3, g_A3);
    cudaGetSymbolAddress(&p_B1, g_B1);
    cudaGetSymbolAddress(&p_B2, g_B2);
    cudaGetSymbolAddress(&p_B3, g_B3);

    __nv_bfloat16 *A1 = (__nv_bfloat16*)p_A1, *A2 = (__nv_bfloat16*)p_A2,
                  *A3 = (__nv_bfloat16*)p_A3, *B1 = (__nv_bfloat16*)p_B1,
                  *B2 = (__nv_bfloat16*)p_B2, *B3 = (__nv_bfloat16*)p_B3;

    auto splitA = [&](const float* src, int n){
        k_split<<<(n + 255)/256, 256>>>(src, A1, A2, A3, n);
    };
    auto splitB = [&](const float* src, int n){
        k_split<<<(n + 255)/256, 256>>>(src, B1, B2, B3, n);
    };

    dim3 tb(32, 8);
    dim3 tg(D_/32, D_/32);

    // prep
    k_prep<<<B_, T_>>>(slen);
    k_biasM<<<(G2_ + 255)/256, 256>>>(bihF, bhhF, bihB, bhhB);
    k_zero<<<(2*2*B_*H_ + 255)/256, 256>>>();
    k_transT<<<tg, tb>>>(W2W + (size_t)768*D_,  (float*)p_W2yT);
    k_transT<<<tg, tb>>>(W2W + (size_t)1537*D_, (float*)p_W2eyT);
    k_transT<<<tg, tb>>>(W3W + (size_t)1537*D_, (float*)p_W3cT);
    k_transWM<<<dim3(D_/32, G_/32), tb>>>(WihF, 0);
    k_transWM<<<dim3(D_/32, G_/32), tb>>>(WihB, G_);

    // UPSTREAM (fp32+FFMA2): merged input projection, N=3072
    sgemmF<false,false><<<dim3(G2_/128, BT_/128), 256>>>(word, (const float*)p_WcT,
        (const float*)p_bm, (float*)p_xall, BT_, G2_, D_);

    // recurrence (k-split x2, FFMA2)
    for (int t = 0; t < T_; t++)
        k_lstm3<<<dim3(B_/32, H_/32, 2), 256>>>(WhhF, WhhB, t);

    // attention pooling — fp32+FFMA2
    sgemmF<true,false><<<dim3(D_/128, BT_/128), 256>>>((const float*)p_Hs, s1W, s1b,
        (float*)p_t1, BT_, D_, D_);
    k_e<<<BT_/8, 256>>>(s2W);
    k_u<<<B_, 256>>>(slen);

    // shared representation — fp32+FFMA2
    sgemmF<true,false><<<dim3(D_/128, B_/128), 256>>>((const float*)p_U, repW, repb,
        (float*)p_R, B_, D_, D_);
    k_gatherR<<<(NC_*D_ + 255)/256, 256>>>(emo, cau);

    // phase 2
    k_chunk<<<NE_*NK_, 256>>>();
    sgemm64<false,false><<<dim3(D_/64, (NE_*NK_)/64), 256>>>(pos, W2W + (size_t)2305*D_,
        W2b, (float*)p_z2, NE_*NK_, D_, POS_, D_);
    splitA((const float*)p_cE, NE_*NK_*D_); splitB((const float*)p_W2yT, D_*D_);
    bgemm<false,true><<<dim3(D_/128, (NE_*NK_)/128), 256, BGS_>>>(A1,A2,A3, B1,B2,B3,
        (const float*)p_zero, (float*)p_z2, NE_*NK_, D_, D_);
    k_EYsplit<<<NE_*NK_, 256>>>(A1, A2, A3);
    splitB((const float*)p_W2eyT, D_*D_);
    bgemm<false,true><<<dim3(D_/128, (NE_*NK_)/128), 256, BGS_>>>(A1,A2,A3, B1,B2,B3,
        (const float*)p_zero, (float*)p_z2, NE_*NK_, D_, D_);
    sgemm64<false,false><<<dim3(D_/64, (NE_+63)/64), 256>>>((const float*)p_E, W2W,
        (const float*)p_zero, (float*)p_EW2a, NE_, D_, D_, D_);
    k_add2<<<(NE_*NK_*D_ + 255)/256, 256>>>(W2W);
    k_bn<<<dim3(NE_, 3), 256>>>((float*)p_z2, NK_);
    k_head<<<(NE_*NK_)/8, 256>>>((const float*)p_z2, WoW, Wob, out, (float*)p_of, NE_*NK_);

    // phase 3
    k_ECsplit<<<NE_*NC_, 256>>>(A1, A2, A3);
    splitB((const float*)p_W3cT, D_*D_);
    bgemm<false,false><<<dim3(D_/128, (NE_*NC_)/128), 256, BGS_>>>(A1,A2,A3, B1,B2,B3,
        W3b, (float*)p_z3, NE_*NC_, D_, D_);
    sgemm64<false,false><<<dim3(D_/64, (NE_+63)/64), 256>>>((const float*)p_E, W3W,
        (const float*)p_zero, (float*)p_EW3a, NE_, D_, D_, D_);
    sgemm64<false,false><<<dim3(D_/64, (NC_+63)/64), 256>>>((const float*)p_Cu,
        W3W + (size_t)768*D_, (const float*)p_zero, (float*)p_CW3b, NC_, D_, D_, D_);
    sgemm64<false,false><<<dim3(D_/64, (NC_+63)/64), 256>>>(dis, W3W + (size_t)2305*D_,
        (const float*)p_zero, (float*)p_disW3, NC_, D_, POS_, D_);
    k_add3<<<(NE_*NC_*D_ + 255)/256, 256>>>(W3W);
    k_bn<<<dim3(NE_, 3), 256>>>((float*)p_z3, NC_);
    k_head<<<(NE_*NC_)/8, 256>>>((const float*)p_z3, clsW, clsb,
        out + NE_*NK_*2, nullptr, NE_*NC_);

    // L indicator
    k_L<<<NE_, NC_>>>(lab, out + NE_*NK_*2 + NE_*NC_*2);
}